// round 1
// baseline (speedup 1.0000x reference)
#include <cuda_runtime.h>
#include <cuda_bf16.h>
#include <math.h>

// Problem constants
#define LYR 4
#define DMODEL 1024
#define NHEAD 16
#define HDIM 64
#define FDIM 4096
#define VOCAB 32000
#define BATCH 2
#define SEQ 2048
#define NTOK (BATCH*SEQ)   // 4096

// ---------------- scratch (static device memory; no allocs allowed) --------
__device__ float g_h[NTOK * DMODEL];
__device__ float g_q[NTOK * DMODEL];
__device__ float g_k[NTOK * DMODEL];
__device__ float g_v[NTOK * DMODEL];
__device__ float g_ctx[NTOK * DMODEL];
__device__ float g_tmp[NTOK * DMODEL];     // attn_out / ffn2 out
__device__ float g_ffn[NTOK * FDIM];       // ffn intermediate

// ---------------- embed: h = 2*embed[id] + pe[s] ---------------------------
__global__ void embed_kernel(const int* __restrict__ ids,
                             const float* __restrict__ emb,
                             const float* __restrict__ pe,
                             float* __restrict__ h) {
    int n = blockIdx.x;              // token index 0..4095
    int s = n & (SEQ - 1);
    int id = ids[n];
    int c = threadIdx.x * 4;         // 256 threads * 4 = 1024
    const float4 e = *(const float4*)(emb + (size_t)id * DMODEL + c);
    const float4 p = *(const float4*)(pe + (size_t)s * DMODEL + c);
    float4 o;
    o.x = 2.f * e.x + p.x; o.y = 2.f * e.y + p.y;
    o.z = 2.f * e.z + p.z; o.w = 2.f * e.w + p.w;
    *(float4*)(h + (size_t)n * DMODEL + c) = o;
}

// ---------------- SGEMM: C[M,N] = A[M,K] @ W[K,N] (+bias)(+gelu) -----------
// 128x128 block tile, BK=8, 256 threads, 8x8 per-thread microtile.
// EPI: 0 = none, 1 = +bias, 2 = +bias then exact gelu
template<int EPI>
__global__ void __launch_bounds__(256, 2)
sgemm_kernel(const float* __restrict__ A, const float* __restrict__ W,
             const float* __restrict__ bias, float* __restrict__ C,
             int M, int N, int K) {
    __shared__ float As[8][128];
    __shared__ float Bs[8][128];

    const int tid = threadIdx.x;
    const int bx = blockIdx.x;   // N tile
    const int by = blockIdx.y;   // M tile

    const int aRow = tid >> 1;           // 0..127
    const int aCol = (tid & 1) * 4;      // 0 or 4
    const int bRow = tid >> 5;           // 0..7
    const int bCol = (tid & 31) * 4;     // 0..124

    const int tCol = (tid & 15) * 8;     // 0..120
    const int tRow = (tid >> 4) * 8;     // 0..120

    const float* Aptr = A + (size_t)(by * 128) * K;
    const float* Wptr = W + (size_t)bx * 128;

    float acc[8][8];
#pragma unroll
    for (int i = 0; i < 8; i++)
#pragma unroll
        for (int j = 0; j < 8; j++) acc[i][j] = 0.f;

    for (int k0 = 0; k0 < K; k0 += 8) {
        float4 a = *(const float4*)(Aptr + (size_t)aRow * K + k0 + aCol);
        As[aCol + 0][aRow] = a.x;
        As[aCol + 1][aRow] = a.y;
        As[aCol + 2][aRow] = a.z;
        As[aCol + 3][aRow] = a.w;
        float4 b = *(const float4*)(Wptr + (size_t)(k0 + bRow) * N + bCol);
        *(float4*)&Bs[bRow][bCol] = b;
        __syncthreads();
#pragma unroll
        for (int kk = 0; kk < 8; kk++) {
            float ar[8], br[8];
#pragma unroll
            for (int i = 0; i < 8; i++) ar[i] = As[kk][tRow + i];
#pragma unroll
            for (int j = 0; j < 8; j++) br[j] = Bs[kk][tCol + j];
#pragma unroll
            for (int i = 0; i < 8; i++)
#pragma unroll
                for (int j = 0; j < 8; j++)
                    acc[i][j] += ar[i] * br[j];
        }
        __syncthreads();
    }

    const int crow = by * 128 + tRow;
    const int ccol = bx * 128 + tCol;
    float bv[8];
    if (EPI >= 1) {
#pragma unroll
        for (int j = 0; j < 8; j++) bv[j] = bias[ccol + j];
    }
#pragma unroll
    for (int i = 0; i < 8; i++) {
        float* Crow = C + (size_t)(crow + i) * N + ccol;
#pragma unroll
        for (int j4 = 0; j4 < 8; j4 += 4) {
            float4 o;
            float v0 = acc[i][j4 + 0], v1 = acc[i][j4 + 1];
            float v2 = acc[i][j4 + 2], v3 = acc[i][j4 + 3];
            if (EPI >= 1) { v0 += bv[j4]; v1 += bv[j4 + 1]; v2 += bv[j4 + 2]; v3 += bv[j4 + 3]; }
            if (EPI == 2) {
                v0 = 0.5f * v0 * (1.f + erff(v0 * 0.70710678118654752f));
                v1 = 0.5f * v1 * (1.f + erff(v1 * 0.70710678118654752f));
                v2 = 0.5f * v2 * (1.f + erff(v2 * 0.70710678118654752f));
                v3 = 0.5f * v3 * (1.f + erff(v3 * 0.70710678118654752f));
            }
            o.x = v0; o.y = v1; o.z = v2; o.w = v3;
            *(float4*)(Crow + j4) = o;
        }
    }
}

// ---------------- Flash attention: one block = (q-tile 128, head, batch) ---
// 128 threads; each thread owns one q row (q in 64 regs, acc in 64 regs).
// K/V tiles (64x64) staged in shared; scores row per thread in shared.
#define ATTN_SMEM ((128*65 + 2*64*64) * 4)

__global__ void __launch_bounds__(128)
attn_kernel(const float* __restrict__ Q, const float* __restrict__ K,
            const float* __restrict__ Vv, float* __restrict__ O) {
    extern __shared__ float sm[];
    float* Ss = sm;                 // 128 * 65 (also Q staging)
    float* Ks = Ss + 128 * 65;      // 64 * 64
    float* Vs = Ks + 64 * 64;       // 64 * 64

    const int tid = threadIdx.x;
    const int q0 = blockIdx.x * 128;
    const int h  = blockIdx.y;
    const int b  = blockIdx.z;
    const int rowbase = b * SEQ;
    const int colbase = h * HDIM;
    const float scale = 0.125f;     // 1/sqrt(64)

    // stage Q tile into shared (coalesced), pre-scaled
    for (int i = tid; i < 128 * 16; i += 128) {
        int r = i >> 4, c4 = (i & 15) * 4;
        float4 qv = *(const float4*)(Q + (size_t)(rowbase + q0 + r) * DMODEL + colbase + c4);
        float* dst = Ss + r * 65 + c4;
        dst[0] = qv.x * scale; dst[1] = qv.y * scale;
        dst[2] = qv.z * scale; dst[3] = qv.w * scale;
    }
    __syncthreads();
    float qr[64];
#pragma unroll
    for (int d = 0; d < 64; d++) qr[d] = Ss[tid * 65 + d];
    __syncthreads();

    float m = -1e30f, l = 0.f;
    float acc[64];
#pragma unroll
    for (int d = 0; d < 64; d++) acc[d] = 0.f;

    for (int kt = 0; kt < SEQ; kt += 64) {
        for (int i = tid; i < 64 * 16; i += 128) {
            int r = i >> 4, c4 = (i & 15) * 4;
            *(float4*)(Ks + r * 64 + c4) =
                *(const float4*)(K + (size_t)(rowbase + kt + r) * DMODEL + colbase + c4);
            *(float4*)(Vs + r * 64 + c4) =
                *(const float4*)(Vv + (size_t)(rowbase + kt + r) * DMODEL + colbase + c4);
        }
        __syncthreads();

        float* Sr = Ss + tid * 65;
        float mt = -1e30f;
#pragma unroll 4
        for (int j = 0; j < 64; j++) {
            const float4* K4 = (const float4*)(Ks + j * 64);
            float s = 0.f;
#pragma unroll
            for (int d4 = 0; d4 < 16; d4++) {
                float4 kv = K4[d4];
                s += qr[4*d4+0]*kv.x + qr[4*d4+1]*kv.y + qr[4*d4+2]*kv.z + qr[4*d4+3]*kv.w;
            }
            Sr[j] = s;
            mt = fmaxf(mt, s);
        }
        float mnew = fmaxf(m, mt);
        float corr = __expf(m - mnew);
        l *= corr;
#pragma unroll
        for (int d = 0; d < 64; d++) acc[d] *= corr;
#pragma unroll 2
        for (int j = 0; j < 64; j++) {
            float p = __expf(Sr[j] - mnew);
            l += p;
            const float4* V4 = (const float4*)(Vs + j * 64);
#pragma unroll
            for (int d4 = 0; d4 < 16; d4++) {
                float4 vv = V4[d4];
                acc[4*d4+0] += p * vv.x; acc[4*d4+1] += p * vv.y;
                acc[4*d4+2] += p * vv.z; acc[4*d4+3] += p * vv.w;
            }
        }
        m = mnew;
        __syncthreads();
    }

    float inv = 1.f / l;
    float* Op = O + (size_t)(rowbase + q0 + tid) * DMODEL + colbase;
#pragma unroll
    for (int d4 = 0; d4 < 16; d4++) {
        float4 o;
        o.x = acc[4*d4+0] * inv; o.y = acc[4*d4+1] * inv;
        o.z = acc[4*d4+2] * inv; o.w = acc[4*d4+3] * inv;
        *(float4*)(Op + 4 * d4) = o;
    }
}

// ---------------- residual add + LayerNorm (block per row of 1024) ---------
template<int HAS_RES>
__global__ void __launch_bounds__(256)
add_ln_kernel(const float* __restrict__ x, const float* __restrict__ res,
              const float* __restrict__ g, const float* __restrict__ b,
              float* __restrict__ out) {
    int row = blockIdx.x, tid = threadIdx.x;
    __shared__ float sh[16];
    __shared__ float stats[2];

    float4 v = *(const float4*)(x + (size_t)row * DMODEL + tid * 4);
    if (HAS_RES) {
        float4 r = *(const float4*)(res + (size_t)row * DMODEL + tid * 4);
        v.x += r.x; v.y += r.y; v.z += r.z; v.w += r.w;
    }
    float s  = v.x + v.y + v.z + v.w;
    float s2 = v.x*v.x + v.y*v.y + v.z*v.z + v.w*v.w;
#pragma unroll
    for (int o = 16; o > 0; o >>= 1) {
        s  += __shfl_down_sync(0xFFFFFFFFu, s,  o);
        s2 += __shfl_down_sync(0xFFFFFFFFu, s2, o);
    }
    int wid = tid >> 5, lane = tid & 31;
    if (lane == 0) { sh[wid] = s; sh[wid + 8] = s2; }
    __syncthreads();
    if (tid == 0) {
        float ts = 0.f, ts2 = 0.f;
#pragma unroll
        for (int i = 0; i < 8; i++) { ts += sh[i]; ts2 += sh[i + 8]; }
        float mean = ts * (1.f / DMODEL);
        float var  = ts2 * (1.f / DMODEL) - mean * mean;
        stats[0] = mean;
        stats[1] = rsqrtf(var + 1e-5f);
    }
    __syncthreads();
    float mean = stats[0], rstd = stats[1];
    float4 gv = *(const float4*)(g + tid * 4);
    float4 bv = *(const float4*)(b + tid * 4);
    float4 o;
    o.x = (v.x - mean) * rstd * gv.x + bv.x;
    o.y = (v.y - mean) * rstd * gv.y + bv.y;
    o.z = (v.z - mean) * rstd * gv.z + bv.z;
    o.w = (v.w - mean) * rstd * gv.w + bv.w;
    *(float4*)(out + (size_t)row * DMODEL + tid * 4) = o;
}

// ---------------- host orchestration ---------------------------------------
extern "C" void kernel_launch(void* const* d_in, const int* in_sizes, int n_in,
                              void* d_out, int out_size) {
    const int*   ids     = (const int*)  d_in[0];
    const float* emb     = (const float*)d_in[1];
    const float* pe      = (const float*)d_in[2];
    const float* wq      = (const float*)d_in[3];
    const float* bq      = (const float*)d_in[4];
    const float* wk      = (const float*)d_in[5];
    const float* bk      = (const float*)d_in[6];
    const float* wv      = (const float*)d_in[7];
    const float* bv      = (const float*)d_in[8];
    const float* wo      = (const float*)d_in[9];
    const float* bo      = (const float*)d_in[10];
    const float* ln1_g   = (const float*)d_in[11];
    const float* ln1_b   = (const float*)d_in[12];
    const float* w1      = (const float*)d_in[13];
    const float* b1      = (const float*)d_in[14];
    const float* w2      = (const float*)d_in[15];
    const float* b2      = (const float*)d_in[16];
    const float* ln2_g   = (const float*)d_in[17];
    const float* ln2_b   = (const float*)d_in[18];
    const float* lnf_g   = (const float*)d_in[19];
    const float* lnf_b   = (const float*)d_in[20];
    const float* lm_head = (const float*)d_in[21];
    float* out = (float*)d_out;

    float *h, *q, *k, *v, *ctx, *tmp, *ffn;
    cudaGetSymbolAddress((void**)&h,   g_h);
    cudaGetSymbolAddress((void**)&q,   g_q);
    cudaGetSymbolAddress((void**)&k,   g_k);
    cudaGetSymbolAddress((void**)&v,   g_v);
    cudaGetSymbolAddress((void**)&ctx, g_ctx);
    cudaGetSymbolAddress((void**)&tmp, g_tmp);
    cudaGetSymbolAddress((void**)&ffn, g_ffn);

    cudaFuncSetAttribute(attn_kernel, cudaFuncAttributeMaxDynamicSharedMemorySize, ATTN_SMEM);

    // embed: h = 2*tok + pe
    embed_kernel<<<NTOK, 256>>>(ids, emb, pe, h);

    dim3 gD(DMODEL / 128, NTOK / 128);   // (8, 32)
    dim3 gF(FDIM / 128,  NTOK / 128);    // (32, 32)
    dim3 gV(VOCAB / 128, NTOK / 128);    // (250, 32)
    dim3 gAttn(SEQ / 128, NHEAD, BATCH); // (16, 16, 2)

    for (int i = 0; i < LYR; i++) {
        const size_t oDD = (size_t)i * DMODEL * DMODEL;
        const size_t oD  = (size_t)i * DMODEL;
        const size_t oDF = (size_t)i * DMODEL * FDIM;
        const size_t oF  = (size_t)i * FDIM;

        sgemm_kernel<1><<<gD, 256>>>(h, wq + oDD, bq + oD, q, NTOK, DMODEL, DMODEL);
        sgemm_kernel<1><<<gD, 256>>>(h, wk + oDD, bk + oD, k, NTOK, DMODEL, DMODEL);
        sgemm_kernel<1><<<gD, 256>>>(h, wv + oDD, bv + oD, v, NTOK, DMODEL, DMODEL);

        attn_kernel<<<gAttn, 128, ATTN_SMEM>>>(q, k, v, ctx);

        sgemm_kernel<1><<<gD, 256>>>(ctx, wo + oDD, bo + oD, tmp, NTOK, DMODEL, DMODEL);
        add_ln_kernel<1><<<NTOK, 256>>>(tmp, h, ln1_g + oD, ln1_b + oD, h);

        sgemm_kernel<2><<<gF, 256>>>(h, w1 + oDF, b1 + oF, ffn, NTOK, FDIM, DMODEL);
        sgemm_kernel<1><<<gD, 256>>>(ffn, w2 + oDF, b2 + oD, tmp, NTOK, DMODEL, FDIM);
        add_ln_kernel<1><<<NTOK, 256>>>(tmp, h, ln2_g + oD, ln2_b + oD, h);
    }

    // final LN (no residual)
    add_ln_kernel<0><<<NTOK, 256>>>(h, nullptr, lnf_g, lnf_b, h);

    // LM head: logits = h @ lm_head  [4096, 32000]
    sgemm_kernel<0><<<gV, 256>>>(h, lm_head, nullptr, out, NTOK, VOCAB, DMODEL);
}

// round 2
// speedup vs baseline: 1.0912x; 1.0912x over previous
#include <cuda_runtime.h>
#include <cuda_bf16.h>
#include <math.h>

// Problem constants
#define LYR 4
#define DMODEL 1024
#define NHEAD 16
#define HDIM 64
#define FDIM 4096
#define VOCAB 32000
#define BATCH 2
#define SEQ 2048
#define NTOK (BATCH*SEQ)   // 4096

// ---------------- scratch (static device memory; no allocs allowed) --------
__device__ float g_h[NTOK * DMODEL];
__device__ float g_q[NTOK * DMODEL];
__device__ float g_k[NTOK * DMODEL];
__device__ float g_v[NTOK * DMODEL];
__device__ float g_ctx[NTOK * DMODEL];
__device__ float g_tmp[NTOK * DMODEL];
__device__ float g_ffn[NTOK * FDIM];

// ---------------- embed: h = 2*embed[id] + pe[s] ---------------------------
__global__ void embed_kernel(const int* __restrict__ ids,
                             const float* __restrict__ emb,
                             const float* __restrict__ pe,
                             float* __restrict__ h) {
    int n = blockIdx.x;
    int s = n & (SEQ - 1);
    int id = ids[n];
    int c = threadIdx.x * 4;
    const float4 e = *(const float4*)(emb + (size_t)id * DMODEL + c);
    const float4 p = *(const float4*)(pe + (size_t)s * DMODEL + c);
    float4 o;
    o.x = 2.f * e.x + p.x; o.y = 2.f * e.y + p.y;
    o.z = 2.f * e.z + p.z; o.w = 2.f * e.w + p.w;
    *(float4*)(h + (size_t)n * DMODEL + c) = o;
}

// ---------------- TF32 tensor-core GEMM ------------------------------------
// C[M,N] = A[M,K] @ B[K,N] (+bias)(+gelu), fp32 in/out, tf32 mma accumulate fp32.
// Block tile 128x128, BK=16, 256 threads = 8 warps (2M x 4N), warp tile 64x32.
// Shared memory holds pre-swizzled mma fragments (scatter on store,
// conflict-free vector loads on read). Double buffered over K stages.

__device__ __forceinline__ unsigned f2tf32(float x) {
    unsigned u;
    asm("cvt.rna.tf32.f32 %0, %1;" : "=r"(u) : "f"(x));
    return u;
}

template<int EPI>  // 0=none, 1=+bias, 2=+bias+gelu
__global__ void __launch_bounds__(256)
gemm_tf32_kernel(const float* __restrict__ A, const float* __restrict__ B,
                 const float* __restrict__ bias, float* __restrict__ C,
                 int M, int N, int K) {
    // fragment-layout shared: A: [8 mtiles][2 ksteps][32 lanes][4 regs]
    //                         B: [16 ntiles][2 ksteps][32 lanes][2 regs]
    __shared__ unsigned As[2][2048];
    __shared__ unsigned Bs[2][2048];

    const int tid  = threadIdx.x;
    const int lane = tid & 31;
    const int warp = tid >> 5;
    const int warpM = warp >> 2;      // 0..1
    const int warpN = warp & 3;       // 0..3
    const int bx = blockIdx.x, by = blockIdx.y;

    // ---- per-thread global load + scatter descriptors (2 A float4, 2 B float4)
    // A: idx = j*256+tid ; m = idx>>2 ; kq = (idx&3)*4
    int aM[2], aBase[2];
    const float* aPtr[2];
    const float* bPtr[2];
    int bBase[2];
#pragma unroll
    for (int j = 0; j < 2; j++) {
        int idx = j * 256 + tid;
        int m = idx >> 2;
        int kq = (idx & 3) << 2;
        int r = m & 15, mtile = m >> 4;
        int kstep = kq >> 3, tb = kq & 7;
        int regbase = ((r >> 3) & 1) | ((tb >> 2) << 1);
        aBase[j] = (mtile * 2 + kstep) * 128 + ((r & 7) << 4) + regbase;
        aM[j] = m;
        aPtr[j] = A + (size_t)(by * 128 + m) * K + kq;

        int idxb = j * 256 + tid;
        int krow = idxb >> 5;
        int n4 = (idxb & 31) << 2;
        int t = krow & 7, kstepb = krow >> 3;
        int reg = (t >> 2) & 1;
        int tl = t & 3;
        int ntile = n4 >> 3;
        int cb = n4 & 7;
        bBase[j] = (ntile * 2 + kstepb) * 64 + cb * 8 + tl * 2 + reg;
        bPtr[j] = B + (size_t)krow * N + bx * 128 + n4;
    }
    (void)aM;

    float acc[4][4][4];
#pragma unroll
    for (int mt = 0; mt < 4; mt++)
#pragma unroll
        for (int nt = 0; nt < 4; nt++)
#pragma unroll
            for (int r = 0; r < 4; r++) acc[mt][nt][r] = 0.f;

    const int NS = K >> 4;
    float4 av[2], bv[2];

    // prologue: load + scatter stage 0
#pragma unroll
    for (int j = 0; j < 2; j++) { av[j] = *(const float4*)aPtr[j]; bv[j] = *(const float4*)bPtr[j]; }
#pragma unroll
    for (int j = 0; j < 2; j++) {
        unsigned* a = &As[0][aBase[j]];
        a[0]  = f2tf32(av[j].x); a[4]  = f2tf32(av[j].y);
        a[8]  = f2tf32(av[j].z); a[12] = f2tf32(av[j].w);
        unsigned* b = &Bs[0][bBase[j]];
        b[0]  = f2tf32(bv[j].x); b[8]  = f2tf32(bv[j].y);
        b[16] = f2tf32(bv[j].z); b[24] = f2tf32(bv[j].w);
    }
    __syncthreads();

    for (int s = 0; s < NS; s++) {
        int cur = s & 1;
        if (s + 1 < NS) {
#pragma unroll
            for (int j = 0; j < 2; j++) {
                aPtr[j] += 16;
                bPtr[j] += (size_t)16 * N;
                av[j] = *(const float4*)aPtr[j];
                bv[j] = *(const float4*)bPtr[j];
            }
        }
        // compute on cur
#pragma unroll
        for (int kstep = 0; kstep < 2; kstep++) {
            uint4 afr[4];
            uint2 bfr[4];
#pragma unroll
            for (int mt = 0; mt < 4; mt++)
                afr[mt] = *(const uint4*)&As[cur][((warpM * 4 + mt) * 2 + kstep) * 128 + lane * 4];
#pragma unroll
            for (int nt = 0; nt < 4; nt++)
                bfr[nt] = *(const uint2*)&Bs[cur][((warpN * 4 + nt) * 2 + kstep) * 64 + lane * 2];
#pragma unroll
            for (int mt = 0; mt < 4; mt++)
#pragma unroll
                for (int nt = 0; nt < 4; nt++) {
                    asm volatile(
                        "mma.sync.aligned.m16n8k8.row.col.f32.tf32.tf32.f32 "
                        "{%0,%1,%2,%3}, {%4,%5,%6,%7}, {%8,%9}, {%0,%1,%2,%3};"
                        : "+f"(acc[mt][nt][0]), "+f"(acc[mt][nt][1]),
                          "+f"(acc[mt][nt][2]), "+f"(acc[mt][nt][3])
                        : "r"(afr[mt].x), "r"(afr[mt].y), "r"(afr[mt].z), "r"(afr[mt].w),
                          "r"(bfr[nt].x), "r"(bfr[nt].y));
                }
        }
        if (s + 1 < NS) {
            int nxt = cur ^ 1;
#pragma unroll
            for (int j = 0; j < 2; j++) {
                unsigned* a = &As[nxt][aBase[j]];
                a[0]  = f2tf32(av[j].x); a[4]  = f2tf32(av[j].y);
                a[8]  = f2tf32(av[j].z); a[12] = f2tf32(av[j].w);
                unsigned* b = &Bs[nxt][bBase[j]];
                b[0]  = f2tf32(bv[j].x); b[8]  = f2tf32(bv[j].y);
                b[16] = f2tf32(bv[j].z); b[24] = f2tf32(bv[j].w);
            }
        }
        __syncthreads();
    }

    // epilogue
    const int g = lane >> 2, tc = lane & 3;
#pragma unroll
    for (int mt = 0; mt < 4; mt++) {
        int row0 = by * 128 + warpM * 64 + mt * 16 + g;
#pragma unroll
        for (int nt = 0; nt < 4; nt++) {
            int col = bx * 128 + warpN * 32 + nt * 8 + tc * 2;
            float b0 = 0.f, b1 = 0.f;
            if (EPI >= 1) { float2 bb = *(const float2*)(bias + col); b0 = bb.x; b1 = bb.y; }
            float v0 = acc[mt][nt][0] + b0, v1 = acc[mt][nt][1] + b1;
            float v2 = acc[mt][nt][2] + b0, v3 = acc[mt][nt][3] + b1;
            if (EPI == 2) {
                v0 = 0.5f * v0 * (1.f + erff(v0 * 0.70710678118654752f));
                v1 = 0.5f * v1 * (1.f + erff(v1 * 0.70710678118654752f));
                v2 = 0.5f * v2 * (1.f + erff(v2 * 0.70710678118654752f));
                v3 = 0.5f * v3 * (1.f + erff(v3 * 0.70710678118654752f));
            }
            *(float2*)(C + (size_t)row0 * N + col)       = make_float2(v0, v1);
            *(float2*)(C + (size_t)(row0 + 8) * N + col) = make_float2(v2, v3);
        }
    }
}

// ---------------- Flash attention (fp32), KT=32, scores in registers -------
__global__ void __launch_bounds__(128, 2)
attn_kernel(const float* __restrict__ Q, const float* __restrict__ K,
            const float* __restrict__ Vv, float* __restrict__ O) {
    __shared__ float Ks[32 * 64];
    __shared__ float Vs[32 * 64];

    const int tid = threadIdx.x;
    const int q0 = blockIdx.x * 128;
    const int h  = blockIdx.y;
    const int b  = blockIdx.z;
    const int rowbase = b * SEQ;
    const int colbase = h * HDIM;
    const float scale = 0.125f;

    // each thread owns one q row, loaded directly (full 256B row consumed)
    float qr[64];
    const float* qp = Q + (size_t)(rowbase + q0 + tid) * DMODEL + colbase;
#pragma unroll
    for (int d4 = 0; d4 < 16; d4++) {
        float4 qv = *(const float4*)(qp + 4 * d4);
        qr[4*d4+0] = qv.x * scale; qr[4*d4+1] = qv.y * scale;
        qr[4*d4+2] = qv.z * scale; qr[4*d4+3] = qv.w * scale;
    }

    float m = -1e30f, l = 0.f;
    float acc[64];
#pragma unroll
    for (int d = 0; d < 64; d++) acc[d] = 0.f;

    for (int kt = 0; kt < SEQ; kt += 32) {
#pragma unroll
        for (int i = 0; i < 4; i++) {
            int ii = tid + i * 128;
            int r = ii >> 4, c4 = (ii & 15) * 4;
            *(float4*)(Ks + r * 64 + c4) =
                *(const float4*)(K + (size_t)(rowbase + kt + r) * DMODEL + colbase + c4);
            *(float4*)(Vs + r * 64 + c4) =
                *(const float4*)(Vv + (size_t)(rowbase + kt + r) * DMODEL + colbase + c4);
        }
        __syncthreads();

        float s[32];
        float mt = -1e30f;
#pragma unroll 4
        for (int j = 0; j < 32; j++) {
            const float4* K4 = (const float4*)(Ks + j * 64);
            float sv = 0.f;
#pragma unroll
            for (int d4 = 0; d4 < 16; d4++) {
                float4 kv = K4[d4];
                sv += qr[4*d4+0]*kv.x + qr[4*d4+1]*kv.y + qr[4*d4+2]*kv.z + qr[4*d4+3]*kv.w;
            }
            s[j] = sv;
            mt = fmaxf(mt, sv);
        }
        float mnew = fmaxf(m, mt);
        float corr = __expf(m - mnew);
        l *= corr;
#pragma unroll
        for (int d = 0; d < 64; d++) acc[d] *= corr;
#pragma unroll 2
        for (int j = 0; j < 32; j++) {
            float p = __expf(s[j] - mnew);
            l += p;
            const float4* V4 = (const float4*)(Vs + j * 64);
#pragma unroll
            for (int d4 = 0; d4 < 16; d4++) {
                float4 vv = V4[d4];
                acc[4*d4+0] += p * vv.x; acc[4*d4+1] += p * vv.y;
                acc[4*d4+2] += p * vv.z; acc[4*d4+3] += p * vv.w;
            }
        }
        m = mnew;
        __syncthreads();
    }

    float inv = 1.f / l;
    float* Op = O + (size_t)(rowbase + q0 + tid) * DMODEL + colbase;
#pragma unroll
    for (int d4 = 0; d4 < 16; d4++) {
        float4 o;
        o.x = acc[4*d4+0] * inv; o.y = acc[4*d4+1] * inv;
        o.z = acc[4*d4+2] * inv; o.w = acc[4*d4+3] * inv;
        *(float4*)(Op + 4 * d4) = o;
    }
}

// ---------------- residual add + LayerNorm ---------------------------------
template<int HAS_RES>
__global__ void __launch_bounds__(256)
add_ln_kernel(const float* __restrict__ x, const float* __restrict__ res,
              const float* __restrict__ g, const float* __restrict__ b,
              float* __restrict__ out) {
    int row = blockIdx.x, tid = threadIdx.x;
    __shared__ float sh[16];
    __shared__ float stats[2];

    float4 v = *(const float4*)(x + (size_t)row * DMODEL + tid * 4);
    if (HAS_RES) {
        float4 r = *(const float4*)(res + (size_t)row * DMODEL + tid * 4);
        v.x += r.x; v.y += r.y; v.z += r.z; v.w += r.w;
    }
    float s  = v.x + v.y + v.z + v.w;
    float s2 = v.x*v.x + v.y*v.y + v.z*v.z + v.w*v.w;
#pragma unroll
    for (int o = 16; o > 0; o >>= 1) {
        s  += __shfl_down_sync(0xFFFFFFFFu, s,  o);
        s2 += __shfl_down_sync(0xFFFFFFFFu, s2, o);
    }
    int wid = tid >> 5, lane = tid & 31;
    if (lane == 0) { sh[wid] = s; sh[wid + 8] = s2; }
    __syncthreads();
    if (tid == 0) {
        float ts = 0.f, ts2 = 0.f;
#pragma unroll
        for (int i = 0; i < 8; i++) { ts += sh[i]; ts2 += sh[i + 8]; }
        float mean = ts * (1.f / DMODEL);
        float var  = ts2 * (1.f / DMODEL) - mean * mean;
        stats[0] = mean;
        stats[1] = rsqrtf(var + 1e-5f);
    }
    __syncthreads();
    float mean = stats[0], rstd = stats[1];
    float4 gv = *(const float4*)(g + tid * 4);
    float4 bv = *(const float4*)(b + tid * 4);
    float4 o;
    o.x = (v.x - mean) * rstd * gv.x + bv.x;
    o.y = (v.y - mean) * rstd * gv.y + bv.y;
    o.z = (v.z - mean) * rstd * gv.z + bv.z;
    o.w = (v.w - mean) * rstd * gv.w + bv.w;
    *(float4*)(out + (size_t)row * DMODEL + tid * 4) = o;
}

// ---------------- host orchestration ---------------------------------------
extern "C" void kernel_launch(void* const* d_in, const int* in_sizes, int n_in,
                              void* d_out, int out_size) {
    const int*   ids     = (const int*)  d_in[0];
    const float* emb     = (const float*)d_in[1];
    const float* pe      = (const float*)d_in[2];
    const float* wq      = (const float*)d_in[3];
    const float* bq      = (const float*)d_in[4];
    const float* wk      = (const float*)d_in[5];
    const float* bk      = (const float*)d_in[6];
    const float* wv      = (const float*)d_in[7];
    const float* bv      = (const float*)d_in[8];
    const float* wo      = (const float*)d_in[9];
    const float* bo      = (const float*)d_in[10];
    const float* ln1_g   = (const float*)d_in[11];
    const float* ln1_b   = (const float*)d_in[12];
    const float* w1      = (const float*)d_in[13];
    const float* b1      = (const float*)d_in[14];
    const float* w2      = (const float*)d_in[15];
    const float* b2      = (const float*)d_in[16];
    const float* ln2_g   = (const float*)d_in[17];
    const float* ln2_b   = (const float*)d_in[18];
    const float* lnf_g   = (const float*)d_in[19];
    const float* lnf_b   = (const float*)d_in[20];
    const float* lm_head = (const float*)d_in[21];
    float* out = (float*)d_out;

    float *h, *q, *k, *v, *ctx, *tmp, *ffn;
    cudaGetSymbolAddress((void**)&h,   g_h);
    cudaGetSymbolAddress((void**)&q,   g_q);
    cudaGetSymbolAddress((void**)&k,   g_k);
    cudaGetSymbolAddress((void**)&v,   g_v);
    cudaGetSymbolAddress((void**)&ctx, g_ctx);
    cudaGetSymbolAddress((void**)&tmp, g_tmp);
    cudaGetSymbolAddress((void**)&ffn, g_ffn);

    embed_kernel<<<NTOK, 256>>>(ids, emb, pe, h);

    dim3 gD(DMODEL / 128, NTOK / 128);   // (8, 32)
    dim3 gF(FDIM / 128,  NTOK / 128);    // (32, 32)
    dim3 gV(VOCAB / 128, NTOK / 128);    // (250, 32)
    dim3 gAttn(SEQ / 128, NHEAD, BATCH); // (16, 16, 2)

    for (int i = 0; i < LYR; i++) {
        const size_t oDD = (size_t)i * DMODEL * DMODEL;
        const size_t oD  = (size_t)i * DMODEL;
        const size_t oDF = (size_t)i * DMODEL * FDIM;
        const size_t oF  = (size_t)i * FDIM;

        gemm_tf32_kernel<1><<<gD, 256>>>(h, wq + oDD, bq + oD, q, NTOK, DMODEL, DMODEL);
        gemm_tf32_kernel<1><<<gD, 256>>>(h, wk + oDD, bk + oD, k, NTOK, DMODEL, DMODEL);
        gemm_tf32_kernel<1><<<gD, 256>>>(h, wv + oDD, bv + oD, v, NTOK, DMODEL, DMODEL);

        attn_kernel<<<gAttn, 128>>>(q, k, v, ctx);

        gemm_tf32_kernel<1><<<gD, 256>>>(ctx, wo + oDD, bo + oD, tmp, NTOK, DMODEL, DMODEL);
        add_ln_kernel<1><<<NTOK, 256>>>(tmp, h, ln1_g + oD, ln1_b + oD, h);

        gemm_tf32_kernel<2><<<gF, 256>>>(h, w1 + oDF, b1 + oF, ffn, NTOK, FDIM, DMODEL);
        gemm_tf32_kernel<1><<<gD, 256>>>(ffn, w2 + oDF, b2 + oD, tmp, NTOK, DMODEL, FDIM);
        add_ln_kernel<1><<<NTOK, 256>>>(tmp, h, ln2_g + oD, ln2_b + oD, h);
    }

    add_ln_kernel<0><<<NTOK, 256>>>(h, nullptr, lnf_g, lnf_b, h);

    gemm_tf32_kernel<0><<<gV, 256>>>(h, lm_head, nullptr, out, NTOK, VOCAB, DMODEL);
}

// round 6
// speedup vs baseline: 2.1719x; 1.9903x over previous
#include <cuda_runtime.h>
#include <cuda_bf16.h>
#include <math.h>
#include <stdint.h>

#define LYR 4
#define DMODEL 1024
#define NHEAD 16
#define HDIM 64
#define FDIM 4096
#define VOCAB 32000
#define BATCH 2
#define SEQ 2048
#define NTOK (BATCH*SEQ)   // 4096

// ---------------- scratch -----------------------------------------------
__device__ float g_h[NTOK * DMODEL];
__device__ float g_q[NTOK * DMODEL];
__device__ float g_k[NTOK * DMODEL];
__device__ float g_v[NTOK * DMODEL];
__device__ float g_ctx[NTOK * DMODEL];
__device__ float g_tmp[NTOK * DMODEL];
__device__ float g_ffn[NTOK * FDIM];

__device__ __forceinline__ unsigned f2tf(float x) {
    unsigned u; asm("cvt.rna.tf32.f32 %0, %1;" : "=r"(u) : "f"(x)); return u;
}

// ---------------- embed ---------------------------------------------------
__global__ void embed_kernel(const int* __restrict__ ids, const float* __restrict__ emb,
                             const float* __restrict__ pe, float* __restrict__ h) {
    int n = blockIdx.x;
    int s = n & (SEQ - 1);
    int id = ids[n];
    int c = threadIdx.x * 4;
    const float4 e = *(const float4*)(emb + (size_t)id * DMODEL + c);
    const float4 p = *(const float4*)(pe + (size_t)s * DMODEL + c);
    float4 o;
    o.x = 2.f * e.x + p.x; o.y = 2.f * e.y + p.y;
    o.z = 2.f * e.z + p.z; o.w = 2.f * e.w + p.w;
    *(float4*)(h + (size_t)n * DMODEL + c) = o;
}

// ---------------- TF32 mma.sync GEMM, conflict-free staging ----------------
// C[M,N] = A[M,K] @ W[K,N] (+bias)(+gelu). BM=BN=128, BK=16, 256 thr = 8 warps
// (2Mx4N), warp tile 64x32, double-buffered smem.
//
// A smem layout (words): blk(mtile,kstep)=( (mtile*2+kstep)*128 );
//   word = blk + reg2*32 + (g ^ (q<<1))*4 + tc,  reg2 = klow*2+hi, q = kstep*2+klow.
//   Producer: one STS.128 per A float4 (conflict-free). Consumer: LDS.32 at
//   blk + i*32 + (ln ^ (q_i<<3)) -- 32 distinct banks per instruction.
// B smem layout: blk(ntile,kstep)=((ntile*2+kstep)*64);
//   word = blk + reg*32 + n8*4 + tck.  Producer STS.128, consumer reads blk+ln.

template<int EPI>  // 0 none, 1 +bias, 2 +bias+gelu
__global__ void __launch_bounds__(256)
gemm_tf32_v2(const float* __restrict__ A, const float* __restrict__ W,
             const float* __restrict__ bias, float* __restrict__ C,
             int M, int N, int K) {
    __shared__ unsigned As[2][2048];
    __shared__ unsigned Bs[2][2048];

    const int tid  = threadIdx.x;
    const int ln   = tid & 31;
    const int wid  = tid >> 5;
    const int warpM = wid >> 2;    // 0..1
    const int warpN = wid & 3;     // 0..3
    const int bm = blockIdx.x, bn = blockIdx.y;

    // ---- producer descriptors (2 A-uint4 + 2 B-uint4 per thread per stage)
    uint32_t aOffW[2], bOffW[2];
    const float* aG[2];
    const float* bG[2];
#pragma unroll
    for (int j = 0; j < 2; j++) {
        int idx = j * 256 + tid;            // 0..511
        int m = idx >> 2, q = idx & 3;      // q = k-quad within stage
        int mtile = m >> 4, r = m & 15, g = r & 7, hi = r >> 3;
        int kstep = q >> 1, klow = q & 1;
        aOffW[j] = (uint32_t)((mtile * 2 + kstep) * 128 + (klow * 2 + hi) * 32
                              + ((g ^ (q << 1)) << 2));
        aG[j] = A + (size_t)(bm * 128 + m) * K + q * 4;

        int n = idx & 127, k4 = idx >> 7;   // k4 = k-quad index 0..3
        bOffW[j] = (uint32_t)(((n >> 3) * 2 + (k4 >> 1)) * 64 + (k4 & 1) * 32
                              + ((n & 7) << 2));
        bG[j] = W + (size_t)(k4 * 4) * N + (size_t)bn * 128 + n;
    }

    float acc[4][4][4];
#pragma unroll
    for (int mt = 0; mt < 4; mt++)
#pragma unroll
        for (int nt = 0; nt < 4; nt++)
#pragma unroll
            for (int r = 0; r < 4; r++) acc[mt][nt][r] = 0.f;

    const int NS = K >> 4;
    float4 av[2];
    float bvr[2][4];

    // prologue: stage 0 ldg+store, stage 1 ldg
#pragma unroll
    for (int j = 0; j < 2; j++) {
        av[j] = *(const float4*)(aG[j]);
#pragma unroll
        for (int e = 0; e < 4; e++) bvr[j][e] = bG[j][(size_t)e * N];
    }
#pragma unroll
    for (int j = 0; j < 2; j++) {
        *(uint4*)&As[0][aOffW[j]] =
            make_uint4(f2tf(av[j].x), f2tf(av[j].y), f2tf(av[j].z), f2tf(av[j].w));
        *(uint4*)&Bs[0][bOffW[j]] =
            make_uint4(f2tf(bvr[j][0]), f2tf(bvr[j][1]), f2tf(bvr[j][2]), f2tf(bvr[j][3]));
    }
    if (NS > 1) {
#pragma unroll
        for (int j = 0; j < 2; j++) {
            av[j] = *(const float4*)(aG[j] + 16);
#pragma unroll
            for (int e = 0; e < 4; e++) bvr[j][e] = bG[j][(size_t)(16 + e) * N];
        }
    }
    __syncthreads();

    for (int s = 0; s < NS; s++) {
        const unsigned* Ab = As[s & 1];
        const unsigned* Bb = Bs[s & 1];
#pragma unroll
        for (int kstep = 0; kstep < 2; kstep++) {
            const int x0 = kstep << 4;       // (kstep*2+0)<<3
            const int x1 = x0 | 8;           // (kstep*2+1)<<3
            uint4 af[4];
            uint2 bf[4];
#pragma unroll
            for (int mt = 0; mt < 4; mt++) {
                int base = ((warpM * 4 + mt) * 2 + kstep) * 128;
                af[mt].x = Ab[base +       (ln ^ x0)];
                af[mt].y = Ab[base + 32  + (ln ^ x0)];
                af[mt].z = Ab[base + 64  + (ln ^ x1)];
                af[mt].w = Ab[base + 96  + (ln ^ x1)];
            }
#pragma unroll
            for (int nt = 0; nt < 4; nt++) {
                int bb = ((warpN * 4 + nt) * 2 + kstep) * 64;
                bf[nt].x = Bb[bb + ln];
                bf[nt].y = Bb[bb + 32 + ln];
            }
#pragma unroll
            for (int mt = 0; mt < 4; mt++)
#pragma unroll
                for (int nt = 0; nt < 4; nt++) {
                    asm volatile(
                        "mma.sync.aligned.m16n8k8.row.col.f32.tf32.tf32.f32 "
                        "{%0,%1,%2,%3}, {%4,%5,%6,%7}, {%8,%9}, {%0,%1,%2,%3};"
                        : "+f"(acc[mt][nt][0]), "+f"(acc[mt][nt][1]),
                          "+f"(acc[mt][nt][2]), "+f"(acc[mt][nt][3])
                        : "r"(af[mt].x), "r"(af[mt].y), "r"(af[mt].z), "r"(af[mt].w),
                          "r"(bf[nt].x), "r"(bf[nt].y));
                }
        }
        if (s + 1 < NS) {
            unsigned* An = As[(s + 1) & 1];
            unsigned* Bn = Bs[(s + 1) & 1];
#pragma unroll
            for (int j = 0; j < 2; j++) {
                *(uint4*)&An[aOffW[j]] =
                    make_uint4(f2tf(av[j].x), f2tf(av[j].y), f2tf(av[j].z), f2tf(av[j].w));
                *(uint4*)&Bn[bOffW[j]] =
                    make_uint4(f2tf(bvr[j][0]), f2tf(bvr[j][1]), f2tf(bvr[j][2]), f2tf(bvr[j][3]));
            }
            if (s + 2 < NS) {
                const int k0 = (s + 2) * 16;
#pragma unroll
                for (int j = 0; j < 2; j++) {
                    av[j] = *(const float4*)(aG[j] + k0);
#pragma unroll
                    for (int e = 0; e < 4; e++) bvr[j][e] = bG[j][(size_t)(k0 + e) * N];
                }
            }
            __syncthreads();
        }
    }

    // epilogue (layout verified in R2)
    const int g = ln >> 2, tc = ln & 3;
#pragma unroll
    for (int mt = 0; mt < 4; mt++) {
        int row0 = bm * 128 + warpM * 64 + mt * 16 + g;
#pragma unroll
        for (int nt = 0; nt < 4; nt++) {
            int col = bn * 128 + warpN * 32 + nt * 8 + tc * 2;
            float b0 = 0.f, b1 = 0.f;
            if (EPI >= 1) { float2 bb = *(const float2*)(bias + col); b0 = bb.x; b1 = bb.y; }
            float v0 = acc[mt][nt][0] + b0, v1 = acc[mt][nt][1] + b1;
            float v2 = acc[mt][nt][2] + b0, v3 = acc[mt][nt][3] + b1;
            if (EPI == 2) {
                v0 = 0.5f * v0 * (1.f + erff(v0 * 0.70710678118654752f));
                v1 = 0.5f * v1 * (1.f + erff(v1 * 0.70710678118654752f));
                v2 = 0.5f * v2 * (1.f + erff(v2 * 0.70710678118654752f));
                v3 = 0.5f * v3 * (1.f + erff(v3 * 0.70710678118654752f));
            }
            *(float2*)(C + (size_t)row0 * N + col)       = make_float2(v0, v1);
            *(float2*)(C + (size_t)(row0 + 8) * N + col) = make_float2(v2, v3);
        }
    }
}

// ---------------- Flash attention (fp32, KT=32) ----------------------------
__global__ void __launch_bounds__(128, 2)
attn_kernel(const float* __restrict__ Q, const float* __restrict__ K,
            const float* __restrict__ Vv, float* __restrict__ O) {
    __shared__ float Ks[32 * 64];
    __shared__ float Vs[32 * 64];

    const int tid = threadIdx.x;
    const int q0 = blockIdx.x * 128;
    const int h  = blockIdx.y;
    const int b  = blockIdx.z;
    const int rowbase = b * SEQ;
    const int colbase = h * HDIM;
    const float scale = 0.125f;

    float qr[64];
    const float* qp = Q + (size_t)(rowbase + q0 + tid) * DMODEL + colbase;
#pragma unroll
    for (int d4 = 0; d4 < 16; d4++) {
        float4 qv = *(const float4*)(qp + 4 * d4);
        qr[4*d4+0] = qv.x * scale; qr[4*d4+1] = qv.y * scale;
        qr[4*d4+2] = qv.z * scale; qr[4*d4+3] = qv.w * scale;
    }

    float m = -1e30f, l = 0.f;
    float acc[64];
#pragma unroll
    for (int d = 0; d < 64; d++) acc[d] = 0.f;

    for (int kt = 0; kt < SEQ; kt += 32) {
#pragma unroll
        for (int i = 0; i < 4; i++) {
            int ii = tid + i * 128;
            int r = ii >> 4, c4 = (ii & 15) * 4;
            *(float4*)(Ks + r * 64 + c4) =
                *(const float4*)(K + (size_t)(rowbase + kt + r) * DMODEL + colbase + c4);
            *(float4*)(Vs + r * 64 + c4) =
                *(const float4*)(Vv + (size_t)(rowbase + kt + r) * DMODEL + colbase + c4);
        }
        __syncthreads();

        float s[32];
        float mt = -1e30f;
#pragma unroll 4
        for (int j = 0; j < 32; j++) {
            const float4* K4 = (const float4*)(Ks + j * 64);
            float sv = 0.f;
#pragma unroll
            for (int d4 = 0; d4 < 16; d4++) {
                float4 kv = K4[d4];
                sv += qr[4*d4+0]*kv.x + qr[4*d4+1]*kv.y + qr[4*d4+2]*kv.z + qr[4*d4+3]*kv.w;
            }
            s[j] = sv;
            mt = fmaxf(mt, sv);
        }
        float mnew = fmaxf(m, mt);
        float corr = __expf(m - mnew);
        l *= corr;
#pragma unroll
        for (int d = 0; d < 64; d++) acc[d] *= corr;
#pragma unroll 2
        for (int j = 0; j < 32; j++) {
            float p = __expf(s[j] - mnew);
            l += p;
            const float4* V4 = (const float4*)(Vs + j * 64);
#pragma unroll
            for (int d4 = 0; d4 < 16; d4++) {
                float4 vv = V4[d4];
                acc[4*d4+0] += p * vv.x; acc[4*d4+1] += p * vv.y;
                acc[4*d4+2] += p * vv.z; acc[4*d4+3] += p * vv.w;
            }
        }
        m = mnew;
        __syncthreads();
    }

    float inv = 1.f / l;
    float* Op = O + (size_t)(rowbase + q0 + tid) * DMODEL + colbase;
#pragma unroll
    for (int d4 = 0; d4 < 16; d4++) {
        float4 o;
        o.x = acc[4*d4+0] * inv; o.y = acc[4*d4+1] * inv;
        o.z = acc[4*d4+2] * inv; o.w = acc[4*d4+3] * inv;
        *(float4*)(Op + 4 * d4) = o;
    }
}

// ---------------- residual add + LayerNorm ---------------------------------
template<int HAS_RES>
__global__ void __launch_bounds__(256)
add_ln_kernel(const float* __restrict__ x, const float* __restrict__ res,
              const float* __restrict__ g, const float* __restrict__ b,
              float* __restrict__ out) {
    int row = blockIdx.x, tid = threadIdx.x;
    __shared__ float sh[16];
    __shared__ float stats[2];

    float4 v = *(const float4*)(x + (size_t)row * DMODEL + tid * 4);
    if (HAS_RES) {
        float4 r = *(const float4*)(res + (size_t)row * DMODEL + tid * 4);
        v.x += r.x; v.y += r.y; v.z += r.z; v.w += r.w;
    }
    float s  = v.x + v.y + v.z + v.w;
    float s2 = v.x*v.x + v.y*v.y + v.z*v.z + v.w*v.w;
#pragma unroll
    for (int o = 16; o > 0; o >>= 1) {
        s  += __shfl_down_sync(0xFFFFFFFFu, s,  o);
        s2 += __shfl_down_sync(0xFFFFFFFFu, s2, o);
    }
    int wid = tid >> 5, lane = tid & 31;
    if (lane == 0) { sh[wid] = s; sh[wid + 8] = s2; }
    __syncthreads();
    if (tid == 0) {
        float ts = 0.f, ts2 = 0.f;
#pragma unroll
        for (int i = 0; i < 8; i++) { ts += sh[i]; ts2 += sh[i + 8]; }
        float mean = ts * (1.f / DMODEL);
        float var  = ts2 * (1.f / DMODEL) - mean * mean;
        stats[0] = mean;
        stats[1] = rsqrtf(var + 1e-5f);
    }
    __syncthreads();
    float mean = stats[0], rstd = stats[1];
    float4 gv = *(const float4*)(g + tid * 4);
    float4 bv = *(const float4*)(b + tid * 4);
    float4 o;
    o.x = (v.x - mean) * rstd * gv.x + bv.x;
    o.y = (v.y - mean) * rstd * gv.y + bv.y;
    o.z = (v.z - mean) * rstd * gv.z + bv.z;
    o.w = (v.w - mean) * rstd * gv.w + bv.w;
    *(float4*)(out + (size_t)row * DMODEL + tid * 4) = o;
}

// ---------------- host orchestration ---------------------------------------
extern "C" void kernel_launch(void* const* d_in, const int* in_sizes, int n_in,
                              void* d_out, int out_size) {
    const int*   ids     = (const int*)  d_in[0];
    const float* emb     = (const float*)d_in[1];
    const float* pe      = (const float*)d_in[2];
    const float* wq      = (const float*)d_in[3];
    const float* bq      = (const float*)d_in[4];
    const float* wk      = (const float*)d_in[5];
    const float* bk      = (const float*)d_in[6];
    const float* wv      = (const float*)d_in[7];
    const float* bvv     = (const float*)d_in[8];
    const float* wo      = (const float*)d_in[9];
    const float* bo      = (const float*)d_in[10];
    const float* ln1_g   = (const float*)d_in[11];
    const float* ln1_b   = (const float*)d_in[12];
    const float* w1      = (const float*)d_in[13];
    const float* b1      = (const float*)d_in[14];
    const float* w2      = (const float*)d_in[15];
    const float* b2      = (const float*)d_in[16];
    const float* ln2_g   = (const float*)d_in[17];
    const float* ln2_b   = (const float*)d_in[18];
    const float* lnf_g   = (const float*)d_in[19];
    const float* lnf_b   = (const float*)d_in[20];
    const float* lm_head = (const float*)d_in[21];
    float* out = (float*)d_out;

    float *h, *q, *k, *v, *ctx, *tmp, *ffn;
    cudaGetSymbolAddress((void**)&h,   g_h);
    cudaGetSymbolAddress((void**)&q,   g_q);
    cudaGetSymbolAddress((void**)&k,   g_k);
    cudaGetSymbolAddress((void**)&v,   g_v);
    cudaGetSymbolAddress((void**)&ctx, g_ctx);
    cudaGetSymbolAddress((void**)&tmp, g_tmp);
    cudaGetSymbolAddress((void**)&ffn, g_ffn);

    embed_kernel<<<NTOK, 256>>>(ids, emb, pe, h);

    dim3 gD(NTOK / 128, DMODEL / 128);   // (32, 8)
    dim3 gF(NTOK / 128, FDIM / 128);     // (32, 32)
    dim3 gV(NTOK / 128, VOCAB / 128);    // (32, 250)
    dim3 gAttn(SEQ / 128, NHEAD, BATCH); // (16, 16, 2)

    for (int i = 0; i < LYR; i++) {
        const size_t oDD = (size_t)i * DMODEL * DMODEL;
        const size_t oD  = (size_t)i * DMODEL;
        const size_t oDF = (size_t)i * DMODEL * FDIM;
        const size_t oF  = (size_t)i * FDIM;

        gemm_tf32_v2<1><<<gD, 256>>>(h, wq + oDD, bq + oD, q, NTOK, DMODEL, DMODEL);
        gemm_tf32_v2<1><<<gD, 256>>>(h, wk + oDD, bk + oD, k, NTOK, DMODEL, DMODEL);
        gemm_tf32_v2<1><<<gD, 256>>>(h, wv + oDD, bvv + oD, v, NTOK, DMODEL, DMODEL);

        attn_kernel<<<gAttn, 128>>>(q, k, v, ctx);

        gemm_tf32_v2<1><<<gD, 256>>>(ctx, wo + oDD, bo + oD, tmp, NTOK, DMODEL, DMODEL);
        add_ln_kernel<1><<<NTOK, 256>>>(tmp, h, ln1_g + oD, ln1_b + oD, h);

        gemm_tf32_v2<2><<<gF, 256>>>(h, w1 + oDF, b1 + oF, ffn, NTOK, FDIM, DMODEL);
        gemm_tf32_v2<1><<<gD, 256>>>(ffn, w2 + oDF, b2 + oD, tmp, NTOK, DMODEL, FDIM);
        add_ln_kernel<1><<<NTOK, 256>>>(tmp, h, ln2_g + oD, ln2_b + oD, h);
    }

    add_ln_kernel<0><<<NTOK, 256>>>(h, nullptr, lnf_g, lnf_b, h);

    gemm_tf32_v2<0><<<gV, 256>>>(h, lm_head, nullptr, out, NTOK, VOCAB, DMODEL);
}

// round 7
// speedup vs baseline: 3.5752x; 1.6461x over previous
#include <cuda_runtime.h>
#include <cuda_bf16.h>
#include <math.h>
#include <stdint.h>

#define LYR 4
#define DMODEL 1024
#define NHEAD 16
#define HDIM 64
#define FDIM 4096
#define VOCAB 32000
#define BATCH 2
#define SEQ 2048
#define NTOK (BATCH*SEQ)   // 4096

// ---------------- scratch -----------------------------------------------
__device__ float g_h[NTOK * DMODEL];
__device__ float g_q[NTOK * DMODEL];
__device__ float g_k[NTOK * DMODEL];
__device__ float g_v[NTOK * DMODEL];
__device__ float g_ctx[NTOK * DMODEL];
__device__ float g_tmp[NTOK * DMODEL];
__device__ float g_ffn[NTOK * FDIM];

__device__ __forceinline__ unsigned f2tf(float x) {
    unsigned u; asm("cvt.rna.tf32.f32 %0, %1;" : "=r"(u) : "f"(x)); return u;
}

#define MMA4(d, a, b0, b1) \
    asm volatile("mma.sync.aligned.m16n8k8.row.col.f32.tf32.tf32.f32 " \
        "{%0,%1,%2,%3}, {%4,%5,%6,%7}, {%8,%9}, {%0,%1,%2,%3};" \
        : "+f"((d)[0]), "+f"((d)[1]), "+f"((d)[2]), "+f"((d)[3]) \
        : "r"((a)[0]), "r"((a)[1]), "r"((a)[2]), "r"((a)[3]), "r"(b0), "r"(b1))

// ---------------- embed ---------------------------------------------------
__global__ void embed_kernel(const int* __restrict__ ids, const float* __restrict__ emb,
                             const float* __restrict__ pe, float* __restrict__ h) {
    int n = blockIdx.x;
    int s = n & (SEQ - 1);
    int id = ids[n];
    int c = threadIdx.x * 4;
    const float4 e = *(const float4*)(emb + (size_t)id * DMODEL + c);
    const float4 p = *(const float4*)(pe + (size_t)s * DMODEL + c);
    float4 o;
    o.x = 2.f * e.x + p.x; o.y = 2.f * e.y + p.y;
    o.z = 2.f * e.z + p.z; o.w = 2.f * e.w + p.w;
    *(float4*)(h + (size_t)n * DMODEL + c) = o;
}

// ---------------- TF32 mma.sync GEMM (unchanged from R6) -------------------
template<int EPI>  // 0 none, 1 +bias, 2 +bias+gelu
__global__ void __launch_bounds__(256)
gemm_tf32_v2(const float* __restrict__ A, const float* __restrict__ W,
             const float* __restrict__ bias, float* __restrict__ C,
             int M, int N, int K) {
    __shared__ unsigned As[2][2048];
    __shared__ unsigned Bs[2][2048];

    const int tid  = threadIdx.x;
    const int ln   = tid & 31;
    const int wid  = tid >> 5;
    const int warpM = wid >> 2;
    const int warpN = wid & 3;
    const int bm = blockIdx.x, bn = blockIdx.y;

    uint32_t aOffW[2], bOffW[2];
    const float* aG[2];
    const float* bG[2];
#pragma unroll
    for (int j = 0; j < 2; j++) {
        int idx = j * 256 + tid;
        int m = idx >> 2, q = idx & 3;
        int mtile = m >> 4, r = m & 15, g = r & 7, hi = r >> 3;
        int kstep = q >> 1, klow = q & 1;
        aOffW[j] = (uint32_t)((mtile * 2 + kstep) * 128 + (klow * 2 + hi) * 32
                              + ((g ^ (q << 1)) << 2));
        aG[j] = A + (size_t)(bm * 128 + m) * K + q * 4;

        int n = idx & 127, k4 = idx >> 7;
        bOffW[j] = (uint32_t)(((n >> 3) * 2 + (k4 >> 1)) * 64 + (k4 & 1) * 32
                              + ((n & 7) << 2));
        bG[j] = W + (size_t)(k4 * 4) * N + (size_t)bn * 128 + n;
    }

    float acc[4][4][4];
#pragma unroll
    for (int mt = 0; mt < 4; mt++)
#pragma unroll
        for (int nt = 0; nt < 4; nt++)
#pragma unroll
            for (int r = 0; r < 4; r++) acc[mt][nt][r] = 0.f;

    const int NS = K >> 4;
    float4 av[2];
    float bvr[2][4];

#pragma unroll
    for (int j = 0; j < 2; j++) {
        av[j] = *(const float4*)(aG[j]);
#pragma unroll
        for (int e = 0; e < 4; e++) bvr[j][e] = bG[j][(size_t)e * N];
    }
#pragma unroll
    for (int j = 0; j < 2; j++) {
        *(uint4*)&As[0][aOffW[j]] =
            make_uint4(f2tf(av[j].x), f2tf(av[j].y), f2tf(av[j].z), f2tf(av[j].w));
        *(uint4*)&Bs[0][bOffW[j]] =
            make_uint4(f2tf(bvr[j][0]), f2tf(bvr[j][1]), f2tf(bvr[j][2]), f2tf(bvr[j][3]));
    }
    if (NS > 1) {
#pragma unroll
        for (int j = 0; j < 2; j++) {
            av[j] = *(const float4*)(aG[j] + 16);
#pragma unroll
            for (int e = 0; e < 4; e++) bvr[j][e] = bG[j][(size_t)(16 + e) * N];
        }
    }
    __syncthreads();

    for (int s = 0; s < NS; s++) {
        const unsigned* Ab = As[s & 1];
        const unsigned* Bb = Bs[s & 1];
#pragma unroll
        for (int kstep = 0; kstep < 2; kstep++) {
            const int x0 = kstep << 4;
            const int x1 = x0 | 8;
            uint4 af[4];
            uint2 bf[4];
#pragma unroll
            for (int mt = 0; mt < 4; mt++) {
                int base = ((warpM * 4 + mt) * 2 + kstep) * 128;
                af[mt].x = Ab[base +       (ln ^ x0)];
                af[mt].y = Ab[base + 32  + (ln ^ x0)];
                af[mt].z = Ab[base + 64  + (ln ^ x1)];
                af[mt].w = Ab[base + 96  + (ln ^ x1)];
            }
#pragma unroll
            for (int nt = 0; nt < 4; nt++) {
                int bb = ((warpN * 4 + nt) * 2 + kstep) * 64;
                bf[nt].x = Bb[bb + ln];
                bf[nt].y = Bb[bb + 32 + ln];
            }
#pragma unroll
            for (int mt = 0; mt < 4; mt++)
#pragma unroll
                for (int nt = 0; nt < 4; nt++) {
                    asm volatile(
                        "mma.sync.aligned.m16n8k8.row.col.f32.tf32.tf32.f32 "
                        "{%0,%1,%2,%3}, {%4,%5,%6,%7}, {%8,%9}, {%0,%1,%2,%3};"
                        : "+f"(acc[mt][nt][0]), "+f"(acc[mt][nt][1]),
                          "+f"(acc[mt][nt][2]), "+f"(acc[mt][nt][3])
                        : "r"(af[mt].x), "r"(af[mt].y), "r"(af[mt].z), "r"(af[mt].w),
                          "r"(bf[nt].x), "r"(bf[nt].y));
                }
        }
        if (s + 1 < NS) {
            unsigned* An = As[(s + 1) & 1];
            unsigned* Bn = Bs[(s + 1) & 1];
#pragma unroll
            for (int j = 0; j < 2; j++) {
                *(uint4*)&An[aOffW[j]] =
                    make_uint4(f2tf(av[j].x), f2tf(av[j].y), f2tf(av[j].z), f2tf(av[j].w));
                *(uint4*)&Bn[bOffW[j]] =
                    make_uint4(f2tf(bvr[j][0]), f2tf(bvr[j][1]), f2tf(bvr[j][2]), f2tf(bvr[j][3]));
            }
            if (s + 2 < NS) {
                const int k0 = (s + 2) * 16;
#pragma unroll
                for (int j = 0; j < 2; j++) {
                    av[j] = *(const float4*)(aG[j] + k0);
#pragma unroll
                    for (int e = 0; e < 4; e++) bvr[j][e] = bG[j][(size_t)(k0 + e) * N];
                }
            }
            __syncthreads();
        }
    }

    const int g = ln >> 2, tc = ln & 3;
#pragma unroll
    for (int mt = 0; mt < 4; mt++) {
        int row0 = bm * 128 + warpM * 64 + mt * 16 + g;
#pragma unroll
        for (int nt = 0; nt < 4; nt++) {
            int col = bn * 128 + warpN * 32 + nt * 8 + tc * 2;
            float b0 = 0.f, b1 = 0.f;
            if (EPI >= 1) { float2 bb = *(const float2*)(bias + col); b0 = bb.x; b1 = bb.y; }
            float v0 = acc[mt][nt][0] + b0, v1 = acc[mt][nt][1] + b1;
            float v2 = acc[mt][nt][2] + b0, v3 = acc[mt][nt][3] + b1;
            if (EPI == 2) {
                v0 = 0.5f * v0 * (1.f + erff(v0 * 0.70710678118654752f));
                v1 = 0.5f * v1 * (1.f + erff(v1 * 0.70710678118654752f));
                v2 = 0.5f * v2 * (1.f + erff(v2 * 0.70710678118654752f));
                v3 = 0.5f * v3 * (1.f + erff(v3 * 0.70710678118654752f));
            }
            *(float2*)(C + (size_t)row0 * N + col)       = make_float2(v0, v1);
            *(float2*)(C + (size_t)(row0 + 8) * N + col) = make_float2(v2, v3);
        }
    }
}

// ---------------- Tensor-core flash attention ------------------------------
// CTA: 128 q rows, 4 warps x 32 rows (2 m16 tiles). K-tile 64.
// S = (Q*scale) @ K^T via mma tf32; online softmax on C-frags (quad shuffles);
// P -> per-warp smem (A-frag reload); ctx += P @ V via mma tf32.
// Smem strides chosen for conflict-free fragment access:
//   K [j][d] stride 68 (B-frag banks 4g+tc), V [j][d] stride 72 (banks 8tc+g),
//   P [r][j] stride 68 (A-frag banks 4g+tc).
#define KS_STR 68
#define VS_STR 72
#define PS_STR 68
#define ATT_SMEM ((64*KS_STR + 64*VS_STR + 4*32*PS_STR) * 4)   // 70656 B

__global__ void __launch_bounds__(128)
attn_tc_kernel(const float* __restrict__ Q, const float* __restrict__ K,
               const float* __restrict__ Vv, float* __restrict__ O) {
    extern __shared__ unsigned att_sm[];
    unsigned* Ks = att_sm;
    unsigned* Vs = Ks + 64 * KS_STR;
    unsigned* Ps = Vs + 64 * VS_STR;

    const int tid = threadIdx.x;
    const int w = tid >> 5, ln = tid & 31;
    const int g = ln >> 2, tc = ln & 3;
    const int q0 = blockIdx.x * 128;
    const int h = blockIdx.y, b = blockIdx.z;
    const int rowb = b * SEQ;
    const int colb = h * HDIM;
    unsigned* Pw = Ps + w * (32 * PS_STR);

    // Q fragments (pre-scaled, tf32) held in registers
    unsigned qa[2][8][4];
#pragma unroll
    for (int mt = 0; mt < 2; mt++) {
        const float* qb = Q + (size_t)(rowb + q0 + w * 32 + mt * 16) * DMODEL + colb;
#pragma unroll
        for (int ks = 0; ks < 8; ks++) {
            qa[mt][ks][0] = f2tf(qb[(size_t)g       * DMODEL + ks * 8 + tc]     * 0.125f);
            qa[mt][ks][1] = f2tf(qb[(size_t)(g + 8) * DMODEL + ks * 8 + tc]     * 0.125f);
            qa[mt][ks][2] = f2tf(qb[(size_t)g       * DMODEL + ks * 8 + tc + 4] * 0.125f);
            qa[mt][ks][3] = f2tf(qb[(size_t)(g + 8) * DMODEL + ks * 8 + tc + 4] * 0.125f);
        }
    }

    float oc[2][8][4];
#pragma unroll
    for (int mt = 0; mt < 2; mt++)
#pragma unroll
        for (int nt = 0; nt < 8; nt++)
#pragma unroll
            for (int r = 0; r < 4; r++) oc[mt][nt][r] = 0.f;
    float mrow[2][2] = {{-1e30f, -1e30f}, {-1e30f, -1e30f}};
    float lrow[2][2] = {{0.f, 0.f}, {0.f, 0.f}};

    for (int kt = 0; kt < SEQ / 64; kt++) {
        __syncthreads();
        // stage K,V tile (64x64), convert to tf32
#pragma unroll
        for (int i = 0; i < 8; i++) {
            int idx = tid + i * 128;
            int r = idx >> 4, c4 = (idx & 15) << 2;
            const float* kp = K  + (size_t)(rowb + kt * 64 + r) * DMODEL + colb + c4;
            const float* vp = Vv + (size_t)(rowb + kt * 64 + r) * DMODEL + colb + c4;
            float4 kv = *(const float4*)kp;
            float4 vv = *(const float4*)vp;
            *(uint4*)&Ks[r * KS_STR + c4] =
                make_uint4(f2tf(kv.x), f2tf(kv.y), f2tf(kv.z), f2tf(kv.w));
            *(uint4*)&Vs[r * VS_STR + c4] =
                make_uint4(f2tf(vv.x), f2tf(vv.y), f2tf(vv.z), f2tf(vv.w));
        }
        __syncthreads();

        // ---- S = Q @ K^T
        float s[2][8][4];
#pragma unroll
        for (int mt = 0; mt < 2; mt++)
#pragma unroll
            for (int nt = 0; nt < 8; nt++)
#pragma unroll
                for (int r = 0; r < 4; r++) s[mt][nt][r] = 0.f;
#pragma unroll
        for (int ks = 0; ks < 8; ks++) {
#pragma unroll
            for (int nt = 0; nt < 8; nt++) {
                unsigned b0 = Ks[(nt * 8 + g) * KS_STR + ks * 8 + tc];
                unsigned b1 = Ks[(nt * 8 + g) * KS_STR + ks * 8 + tc + 4];
                MMA4(s[0][nt], qa[0][ks], b0, b1);
                MMA4(s[1][nt], qa[1][ks], b0, b1);
            }
        }

        // ---- online softmax
        float rmax[2][2];
#pragma unroll
        for (int mt = 0; mt < 2; mt++) {
            rmax[mt][0] = -1e30f; rmax[mt][1] = -1e30f;
#pragma unroll
            for (int nt = 0; nt < 8; nt++) {
                rmax[mt][0] = fmaxf(rmax[mt][0], fmaxf(s[mt][nt][0], s[mt][nt][1]));
                rmax[mt][1] = fmaxf(rmax[mt][1], fmaxf(s[mt][nt][2], s[mt][nt][3]));
            }
        }
#pragma unroll
        for (int mt = 0; mt < 2; mt++)
#pragma unroll
            for (int hf = 0; hf < 2; hf++) {
                float v = rmax[mt][hf];
                v = fmaxf(v, __shfl_xor_sync(0xFFFFFFFFu, v, 1));
                v = fmaxf(v, __shfl_xor_sync(0xFFFFFFFFu, v, 2));
                rmax[mt][hf] = v;
            }
        float corr[2][2], rsum[2][2];
#pragma unroll
        for (int mt = 0; mt < 2; mt++)
#pragma unroll
            for (int hf = 0; hf < 2; hf++) {
                float mn = fmaxf(mrow[mt][hf], rmax[mt][hf]);
                corr[mt][hf] = __expf(mrow[mt][hf] - mn);
                mrow[mt][hf] = mn;
                rsum[mt][hf] = 0.f;
            }
        // p = exp(s - m), store P frags (tf32) to per-warp smem
#pragma unroll
        for (int mt = 0; mt < 2; mt++) {
#pragma unroll
            for (int nt = 0; nt < 8; nt++) {
                float p0 = __expf(s[mt][nt][0] - mrow[mt][0]);
                float p1 = __expf(s[mt][nt][1] - mrow[mt][0]);
                float p2 = __expf(s[mt][nt][2] - mrow[mt][1]);
                float p3 = __expf(s[mt][nt][3] - mrow[mt][1]);
                rsum[mt][0] += p0 + p1;
                rsum[mt][1] += p2 + p3;
                *(uint2*)&Pw[(mt * 16 + g)     * PS_STR + nt * 8 + 2 * tc] =
                    make_uint2(f2tf(p0), f2tf(p1));
                *(uint2*)&Pw[(mt * 16 + g + 8) * PS_STR + nt * 8 + 2 * tc] =
                    make_uint2(f2tf(p2), f2tf(p3));
            }
        }
        __syncwarp();
#pragma unroll
        for (int mt = 0; mt < 2; mt++)
#pragma unroll
            for (int hf = 0; hf < 2; hf++) {
                float v = rsum[mt][hf];
                v += __shfl_xor_sync(0xFFFFFFFFu, v, 1);
                v += __shfl_xor_sync(0xFFFFFFFFu, v, 2);
                lrow[mt][hf] = lrow[mt][hf] * corr[mt][hf] + v;
            }
        // rescale accumulators
#pragma unroll
        for (int mt = 0; mt < 2; mt++)
#pragma unroll
            for (int nt = 0; nt < 8; nt++) {
                oc[mt][nt][0] *= corr[mt][0];
                oc[mt][nt][1] *= corr[mt][0];
                oc[mt][nt][2] *= corr[mt][1];
                oc[mt][nt][3] *= corr[mt][1];
            }

        // ---- ctx += P @ V
#pragma unroll
        for (int ks = 0; ks < 8; ks++) {
            unsigned pa[2][4];
#pragma unroll
            for (int mt = 0; mt < 2; mt++) {
                pa[mt][0] = Pw[(mt * 16 + g)     * PS_STR + ks * 8 + tc];
                pa[mt][1] = Pw[(mt * 16 + g + 8) * PS_STR + ks * 8 + tc];
                pa[mt][2] = Pw[(mt * 16 + g)     * PS_STR + ks * 8 + tc + 4];
                pa[mt][3] = Pw[(mt * 16 + g + 8) * PS_STR + ks * 8 + tc + 4];
            }
#pragma unroll
            for (int nt = 0; nt < 8; nt++) {
                unsigned b0 = Vs[(ks * 8 + tc)     * VS_STR + nt * 8 + g];
                unsigned b1 = Vs[(ks * 8 + tc + 4) * VS_STR + nt * 8 + g];
                MMA4(oc[0][nt], pa[0], b0, b1);
                MMA4(oc[1][nt], pa[1], b0, b1);
            }
        }
    }

    // ---- write out
#pragma unroll
    for (int mt = 0; mt < 2; mt++) {
        float inv0 = 1.f / lrow[mt][0];
        float inv1 = 1.f / lrow[mt][1];
        int row = rowb + q0 + w * 32 + mt * 16 + g;
#pragma unroll
        for (int nt = 0; nt < 8; nt++) {
            int col = colb + nt * 8 + 2 * tc;
            *(float2*)(O + (size_t)row * DMODEL + col) =
                make_float2(oc[mt][nt][0] * inv0, oc[mt][nt][1] * inv0);
            *(float2*)(O + (size_t)(row + 8) * DMODEL + col) =
                make_float2(oc[mt][nt][2] * inv1, oc[mt][nt][3] * inv1);
        }
    }
}

// ---------------- residual add + LayerNorm ---------------------------------
template<int HAS_RES>
__global__ void __launch_bounds__(256)
add_ln_kernel(const float* __restrict__ x, const float* __restrict__ res,
              const float* __restrict__ g, const float* __restrict__ b,
              float* __restrict__ out) {
    int row = blockIdx.x, tid = threadIdx.x;
    __shared__ float sh[16];
    __shared__ float stats[2];

    float4 v = *(const float4*)(x + (size_t)row * DMODEL + tid * 4);
    if (HAS_RES) {
        float4 r = *(const float4*)(res + (size_t)row * DMODEL + tid * 4);
        v.x += r.x; v.y += r.y; v.z += r.z; v.w += r.w;
    }
    float s  = v.x + v.y + v.z + v.w;
    float s2 = v.x*v.x + v.y*v.y + v.z*v.z + v.w*v.w;
#pragma unroll
    for (int o = 16; o > 0; o >>= 1) {
        s  += __shfl_down_sync(0xFFFFFFFFu, s,  o);
        s2 += __shfl_down_sync(0xFFFFFFFFu, s2, o);
    }
    int wid = tid >> 5, lane = tid & 31;
    if (lane == 0) { sh[wid] = s; sh[wid + 8] = s2; }
    __syncthreads();
    if (tid == 0) {
        float ts = 0.f, ts2 = 0.f;
#pragma unroll
        for (int i = 0; i < 8; i++) { ts += sh[i]; ts2 += sh[i + 8]; }
        float mean = ts * (1.f / DMODEL);
        float var  = ts2 * (1.f / DMODEL) - mean * mean;
        stats[0] = mean;
        stats[1] = rsqrtf(var + 1e-5f);
    }
    __syncthreads();
    float mean = stats[0], rstd = stats[1];
    float4 gv = *(const float4*)(g + tid * 4);
    float4 bv = *(const float4*)(b + tid * 4);
    float4 o;
    o.x = (v.x - mean) * rstd * gv.x + bv.x;
    o.y = (v.y - mean) * rstd * gv.y + bv.y;
    o.z = (v.z - mean) * rstd * gv.z + bv.z;
    o.w = (v.w - mean) * rstd * gv.w + bv.w;
    *(float4*)(out + (size_t)row * DMODEL + tid * 4) = o;
}

// ---------------- host orchestration ---------------------------------------
extern "C" void kernel_launch(void* const* d_in, const int* in_sizes, int n_in,
                              void* d_out, int out_size) {
    const int*   ids     = (const int*)  d_in[0];
    const float* emb     = (const float*)d_in[1];
    const float* pe      = (const float*)d_in[2];
    const float* wq      = (const float*)d_in[3];
    const float* bq      = (const float*)d_in[4];
    const float* wk      = (const float*)d_in[5];
    const float* bk      = (const float*)d_in[6];
    const float* wv      = (const float*)d_in[7];
    const float* bvv     = (const float*)d_in[8];
    const float* wo      = (const float*)d_in[9];
    const float* bo      = (const float*)d_in[10];
    const float* ln1_g   = (const float*)d_in[11];
    const float* ln1_b   = (const float*)d_in[12];
    const float* w1      = (const float*)d_in[13];
    const float* b1      = (const float*)d_in[14];
    const float* w2      = (const float*)d_in[15];
    const float* b2      = (const float*)d_in[16];
    const float* ln2_g   = (const float*)d_in[17];
    const float* ln2_b   = (const float*)d_in[18];
    const float* lnf_g   = (const float*)d_in[19];
    const float* lnf_b   = (const float*)d_in[20];
    const float* lm_head = (const float*)d_in[21];
    float* out = (float*)d_out;

    float *h, *q, *k, *v, *ctx, *tmp, *ffn;
    cudaGetSymbolAddress((void**)&h,   g_h);
    cudaGetSymbolAddress((void**)&q,   g_q);
    cudaGetSymbolAddress((void**)&k,   g_k);
    cudaGetSymbolAddress((void**)&v,   g_v);
    cudaGetSymbolAddress((void**)&ctx, g_ctx);
    cudaGetSymbolAddress((void**)&tmp, g_tmp);
    cudaGetSymbolAddress((void**)&ffn, g_ffn);

    cudaFuncSetAttribute(attn_tc_kernel, cudaFuncAttributeMaxDynamicSharedMemorySize, ATT_SMEM);

    embed_kernel<<<NTOK, 256>>>(ids, emb, pe, h);

    dim3 gD(NTOK / 128, DMODEL / 128);   // (32, 8)
    dim3 gF(NTOK / 128, FDIM / 128);     // (32, 32)
    dim3 gV(NTOK / 128, VOCAB / 128);    // (32, 250)
    dim3 gAttn(SEQ / 128, NHEAD, BATCH); // (16, 16, 2)

    for (int i = 0; i < LYR; i++) {
        const size_t oDD = (size_t)i * DMODEL * DMODEL;
        const size_t oD  = (size_t)i * DMODEL;
        const size_t oDF = (size_t)i * DMODEL * FDIM;
        const size_t oF  = (size_t)i * FDIM;

        gemm_tf32_v2<1><<<gD, 256>>>(h, wq + oDD, bq + oD, q, NTOK, DMODEL, DMODEL);
        gemm_tf32_v2<1><<<gD, 256>>>(h, wk + oDD, bk + oD, k, NTOK, DMODEL, DMODEL);
        gemm_tf32_v2<1><<<gD, 256>>>(h, wv + oDD, bvv + oD, v, NTOK, DMODEL, DMODEL);

        attn_tc_kernel<<<gAttn, 128, ATT_SMEM>>>(q, k, v, ctx);

        gemm_tf32_v2<1><<<gD, 256>>>(ctx, wo + oDD, bo + oD, tmp, NTOK, DMODEL, DMODEL);
        add_ln_kernel<1><<<NTOK, 256>>>(tmp, h, ln1_g + oD, ln1_b + oD, h);

        gemm_tf32_v2<2><<<gF, 256>>>(h, w1 + oDF, b1 + oF, ffn, NTOK, FDIM, DMODEL);
        gemm_tf32_v2<1><<<gD, 256>>>(ffn, w2 + oDF, b2 + oD, tmp, NTOK, DMODEL, FDIM);
        add_ln_kernel<1><<<NTOK, 256>>>(tmp, h, ln2_g + oD, ln2_b + oD, h);
    }

    add_ln_kernel<0><<<NTOK, 256>>>(h, nullptr, lnf_g, lnf_b, h);

    gemm_tf32_v2<0><<<gV, 256>>>(h, lm_head, nullptr, out, NTOK, VOCAB, DMODEL);
}

// round 8
// speedup vs baseline: 3.6280x; 1.0148x over previous
#include <cuda_runtime.h>
#include <cuda_bf16.h>
#include <math.h>
#include <stdint.h>

#define LYR 4
#define DMODEL 1024
#define NHEAD 16
#define HDIM 64
#define FDIM 4096
#define VOCAB 32000
#define BATCH 2
#define SEQ 2048
#define NTOK (BATCH*SEQ)   // 4096

// ---------------- scratch -----------------------------------------------
__device__ float g_h[NTOK * DMODEL];
__device__ float g_q[NTOK * DMODEL];
__device__ float g_k[NTOK * DMODEL];
__device__ float g_v[NTOK * DMODEL];
__device__ float g_ctx[NTOK * DMODEL];
__device__ float g_tmp[NTOK * DMODEL];
__device__ float g_ffn[NTOK * FDIM];

__device__ __forceinline__ unsigned f2tf(float x) {
    unsigned u; asm("cvt.rna.tf32.f32 %0, %1;" : "=r"(u) : "f"(x)); return u;
}
__device__ __forceinline__ uint32_t smem_u32(const void* p) {
    uint32_t a;
    asm("{ .reg .u64 t; cvta.to.shared.u64 t, %1; cvt.u32.u64 %0, t; }" : "=r"(a) : "l"(p));
    return a;
}

#define CP_ASYNC16(dst, src) \
    asm volatile("cp.async.cg.shared.global [%0], [%1], 16;" :: "r"(dst), "l"(src))
#define CP_COMMIT() asm volatile("cp.async.commit_group;" ::: "memory")
#define CP_WAIT(n)  asm volatile("cp.async.wait_group %0;" :: "n"(n) : "memory")

#define MMA4(d, a, b0, b1) \
    asm volatile("mma.sync.aligned.m16n8k8.row.col.f32.tf32.tf32.f32 " \
        "{%0,%1,%2,%3}, {%4,%5,%6,%7}, {%8,%9}, {%0,%1,%2,%3};" \
        : "+f"((d)[0]), "+f"((d)[1]), "+f"((d)[2]), "+f"((d)[3]) \
        : "r"((a)[0]), "r"((a)[1]), "r"((a)[2]), "r"((a)[3]), "r"(b0), "r"(b1))

// ---------------- embed ---------------------------------------------------
__global__ void embed_kernel(const int* __restrict__ ids, const float* __restrict__ emb,
                             const float* __restrict__ pe, float* __restrict__ h) {
    int n = blockIdx.x;
    int s = n & (SEQ - 1);
    int id = ids[n];
    int c = threadIdx.x * 4;
    const float4 e = *(const float4*)(emb + (size_t)id * DMODEL + c);
    const float4 p = *(const float4*)(pe + (size_t)s * DMODEL + c);
    float4 o;
    o.x = 2.f * e.x + p.x; o.y = 2.f * e.y + p.y;
    o.z = 2.f * e.z + p.z; o.w = 2.f * e.w + p.w;
    *(float4*)(h + (size_t)n * DMODEL + c) = o;
}

// ---------------- TF32 GEMM, cp.async 4-stage pipeline ---------------------
// C[M,N] = A[M,K] @ W[K,N] (+bias)(+gelu). BM=BN=128, BK=16, 256 thr = 8 warps
// (2Mx4N), warp tile 64x32. Raw fp32 bits fed to mma.tf32 (HW truncation);
// epilogue compensates the systematic -2^-10 truncation bias via *(1+2^-10).
// A smem [m][k] stride 20 words (banks 20g+tc all-distinct);
// B smem [k][n] stride 132 words (banks 4tc+g all-distinct). Both cp.async 16B.
#define STAGES 4
#define A_STR 20
#define B_STR 132
#define A_WORDS (128 * A_STR)          // 2560
#define B_WORDS (16 * B_STR)           // 2112
#define STG_WORDS (A_WORDS + B_WORDS)  // 4672
#define GEMM_SMEM (STAGES * STG_WORDS * 4)  // 74752 B
#define TRUNC_COMP 1.0009765625f       // 1 + 2^-10

template<int EPI>  // 0 none, 1 +bias, 2 +bias+gelu
__global__ void __launch_bounds__(256)
gemm_tf32_v3(const float* __restrict__ A, const float* __restrict__ W,
             const float* __restrict__ bias, float* __restrict__ C,
             int M, int N, int K) {
    extern __shared__ unsigned gsm[];
    const uint32_t sb = smem_u32(gsm);

    const int tid  = threadIdx.x;
    const int ln   = tid & 31;
    const int wid  = tid >> 5;
    const int warpM = wid >> 2;
    const int warpN = wid & 3;
    const int bm = blockIdx.x, bn = blockIdx.y;
    const int g = ln >> 2, tc = ln & 3;

    // per-thread copy descriptors: 2 A chunks + 2 B chunks per stage
    // A chunk c: m=c>>2, q=c&3 -> As[m*A_STR + q*4], src A[(bm*128+m)*K + k0 + q*4]
    // B chunk c: k=c>>5, n4=(c&31)*4 -> Bs[k*B_STR + n4], src W[(k0+k)*N + bn*128 + n4]
    uint32_t aDst[2], bDst[2];
    const float* aSrc[2];
    const float* bSrc[2];
#pragma unroll
    for (int j = 0; j < 2; j++) {
        int c = j * 256 + tid;
        int m = c >> 2, q = c & 3;
        aDst[j] = (uint32_t)((m * A_STR + q * 4) * 4);
        aSrc[j] = A + (size_t)(bm * 128 + m) * K + q * 4;
        int k = c >> 5, n4 = (c & 31) << 2;
        bDst[j] = (uint32_t)((A_WORDS + k * B_STR + n4) * 4);
        bSrc[j] = W + (size_t)k * N + (size_t)bn * 128 + n4;
    }

    const int NS = K >> 4;

    // prologue: issue stages 0..STAGES-2
#pragma unroll
    for (int p = 0; p < STAGES - 1; p++) {
        uint32_t base = sb + (uint32_t)(p * STG_WORDS * 4);
        const int k0 = p * 16;
#pragma unroll
        for (int j = 0; j < 2; j++) {
            CP_ASYNC16(base + aDst[j], aSrc[j] + k0);
            CP_ASYNC16(base + bDst[j], bSrc[j] + (size_t)k0 * N);
        }
        CP_COMMIT();
    }

    float acc[4][4][4];
#pragma unroll
    for (int mt = 0; mt < 4; mt++)
#pragma unroll
        for (int nt = 0; nt < 4; nt++)
#pragma unroll
            for (int r = 0; r < 4; r++) acc[mt][nt][r] = 0.f;

    for (int s = 0; s < NS; s++) {
        CP_WAIT(STAGES - 2);
        __syncthreads();

        // issue stage s+STAGES-1 into buffer (s-1)%STAGES (free by this sync)
        {
            const int sn = s + STAGES - 1;
            if (sn < NS) {
                uint32_t base = sb + (uint32_t)((sn % STAGES) * STG_WORDS * 4);
                const int k0 = sn * 16;
#pragma unroll
                for (int j = 0; j < 2; j++) {
                    CP_ASYNC16(base + aDst[j], aSrc[j] + k0);
                    CP_ASYNC16(base + bDst[j], bSrc[j] + (size_t)k0 * N);
                }
            }
            CP_COMMIT();
        }

        const unsigned* Ab = gsm + (s % STAGES) * STG_WORDS;
        const unsigned* Bb = Ab + A_WORDS;
#pragma unroll
        for (int kstep = 0; kstep < 2; kstep++) {
            const int kc = kstep * 8;
            uint4 af[4];
            uint2 bf[4];
#pragma unroll
            for (int mt = 0; mt < 4; mt++) {
                int r0 = (warpM * 64 + mt * 16 + g) * A_STR;
                af[mt].x = Ab[r0 + kc + tc];
                af[mt].y = Ab[r0 + 8 * A_STR + kc + tc];
                af[mt].z = Ab[r0 + kc + tc + 4];
                af[mt].w = Ab[r0 + 8 * A_STR + kc + tc + 4];
            }
#pragma unroll
            for (int nt = 0; nt < 4; nt++) {
                int nb = warpN * 32 + nt * 8 + g;
                bf[nt].x = Bb[(kc + tc) * B_STR + nb];
                bf[nt].y = Bb[(kc + tc + 4) * B_STR + nb];
            }
#pragma unroll
            for (int mt = 0; mt < 4; mt++)
#pragma unroll
                for (int nt = 0; nt < 4; nt++) {
                    asm volatile(
                        "mma.sync.aligned.m16n8k8.row.col.f32.tf32.tf32.f32 "
                        "{%0,%1,%2,%3}, {%4,%5,%6,%7}, {%8,%9}, {%0,%1,%2,%3};"
                        : "+f"(acc[mt][nt][0]), "+f"(acc[mt][nt][1]),
                          "+f"(acc[mt][nt][2]), "+f"(acc[mt][nt][3])
                        : "r"(af[mt].x), "r"(af[mt].y), "r"(af[mt].z), "r"(af[mt].w),
                          "r"(bf[nt].x), "r"(bf[nt].y));
                }
        }
    }

    // epilogue: compensate truncation bias, add bias, optional gelu
#pragma unroll
    for (int mt = 0; mt < 4; mt++) {
        int row0 = bm * 128 + warpM * 64 + mt * 16 + g;
#pragma unroll
        for (int nt = 0; nt < 4; nt++) {
            int col = bn * 128 + warpN * 32 + nt * 8 + tc * 2;
            float b0 = 0.f, b1 = 0.f;
            if (EPI >= 1) { float2 bb = *(const float2*)(bias + col); b0 = bb.x; b1 = bb.y; }
            float v0 = acc[mt][nt][0] * TRUNC_COMP + b0;
            float v1 = acc[mt][nt][1] * TRUNC_COMP + b1;
            float v2 = acc[mt][nt][2] * TRUNC_COMP + b0;
            float v3 = acc[mt][nt][3] * TRUNC_COMP + b1;
            if (EPI == 2) {
                v0 = 0.5f * v0 * (1.f + erff(v0 * 0.70710678118654752f));
                v1 = 0.5f * v1 * (1.f + erff(v1 * 0.70710678118654752f));
                v2 = 0.5f * v2 * (1.f + erff(v2 * 0.70710678118654752f));
                v3 = 0.5f * v3 * (1.f + erff(v3 * 0.70710678118654752f));
            }
            *(float2*)(C + (size_t)row0 * N + col)       = make_float2(v0, v1);
            *(float2*)(C + (size_t)(row0 + 8) * N + col) = make_float2(v2, v3);
        }
    }
}

// ---------------- Tensor-core flash attention (unchanged from R7) ----------
#define KS_STR 68
#define VS_STR 72
#define PS_STR 68
#define ATT_SMEM ((64*KS_STR + 64*VS_STR + 4*32*PS_STR) * 4)

__global__ void __launch_bounds__(128)
attn_tc_kernel(const float* __restrict__ Q, const float* __restrict__ K,
               const float* __restrict__ Vv, float* __restrict__ O) {
    extern __shared__ unsigned att_sm[];
    unsigned* Ks = att_sm;
    unsigned* Vs = Ks + 64 * KS_STR;
    unsigned* Ps = Vs + 64 * VS_STR;

    const int tid = threadIdx.x;
    const int w = tid >> 5, ln = tid & 31;
    const int g = ln >> 2, tc = ln & 3;
    const int q0 = blockIdx.x * 128;
    const int h = blockIdx.y, b = blockIdx.z;
    const int rowb = b * SEQ;
    const int colb = h * HDIM;
    unsigned* Pw = Ps + w * (32 * PS_STR);

    unsigned qa[2][8][4];
#pragma unroll
    for (int mt = 0; mt < 2; mt++) {
        const float* qb = Q + (size_t)(rowb + q0 + w * 32 + mt * 16) * DMODEL + colb;
#pragma unroll
        for (int ks = 0; ks < 8; ks++) {
            qa[mt][ks][0] = f2tf(qb[(size_t)g       * DMODEL + ks * 8 + tc]     * 0.125f);
            qa[mt][ks][1] = f2tf(qb[(size_t)(g + 8) * DMODEL + ks * 8 + tc]     * 0.125f);
            qa[mt][ks][2] = f2tf(qb[(size_t)g       * DMODEL + ks * 8 + tc + 4] * 0.125f);
            qa[mt][ks][3] = f2tf(qb[(size_t)(g + 8) * DMODEL + ks * 8 + tc + 4] * 0.125f);
        }
    }

    float oc[2][8][4];
#pragma unroll
    for (int mt = 0; mt < 2; mt++)
#pragma unroll
        for (int nt = 0; nt < 8; nt++)
#pragma unroll
            for (int r = 0; r < 4; r++) oc[mt][nt][r] = 0.f;
    float mrow[2][2] = {{-1e30f, -1e30f}, {-1e30f, -1e30f}};
    float lrow[2][2] = {{0.f, 0.f}, {0.f, 0.f}};

    for (int kt = 0; kt < SEQ / 64; kt++) {
        __syncthreads();
#pragma unroll
        for (int i = 0; i < 8; i++) {
            int idx = tid + i * 128;
            int r = idx >> 4, c4 = (idx & 15) << 2;
            const float* kp = K  + (size_t)(rowb + kt * 64 + r) * DMODEL + colb + c4;
            const float* vp = Vv + (size_t)(rowb + kt * 64 + r) * DMODEL + colb + c4;
            float4 kv = *(const float4*)kp;
            float4 vv = *(const float4*)vp;
            *(uint4*)&Ks[r * KS_STR + c4] =
                make_uint4(f2tf(kv.x), f2tf(kv.y), f2tf(kv.z), f2tf(kv.w));
            *(uint4*)&Vs[r * VS_STR + c4] =
                make_uint4(f2tf(vv.x), f2tf(vv.y), f2tf(vv.z), f2tf(vv.w));
        }
        __syncthreads();

        float s[2][8][4];
#pragma unroll
        for (int mt = 0; mt < 2; mt++)
#pragma unroll
            for (int nt = 0; nt < 8; nt++)
#pragma unroll
                for (int r = 0; r < 4; r++) s[mt][nt][r] = 0.f;
#pragma unroll
        for (int ks = 0; ks < 8; ks++) {
#pragma unroll
            for (int nt = 0; nt < 8; nt++) {
                unsigned b0 = Ks[(nt * 8 + g) * KS_STR + ks * 8 + tc];
                unsigned b1 = Ks[(nt * 8 + g) * KS_STR + ks * 8 + tc + 4];
                MMA4(s[0][nt], qa[0][ks], b0, b1);
                MMA4(s[1][nt], qa[1][ks], b0, b1);
            }
        }

        float rmax[2][2];
#pragma unroll
        for (int mt = 0; mt < 2; mt++) {
            rmax[mt][0] = -1e30f; rmax[mt][1] = -1e30f;
#pragma unroll
            for (int nt = 0; nt < 8; nt++) {
                rmax[mt][0] = fmaxf(rmax[mt][0], fmaxf(s[mt][nt][0], s[mt][nt][1]));
                rmax[mt][1] = fmaxf(rmax[mt][1], fmaxf(s[mt][nt][2], s[mt][nt][3]));
            }
        }
#pragma unroll
        for (int mt = 0; mt < 2; mt++)
#pragma unroll
            for (int hf = 0; hf < 2; hf++) {
                float v = rmax[mt][hf];
                v = fmaxf(v, __shfl_xor_sync(0xFFFFFFFFu, v, 1));
                v = fmaxf(v, __shfl_xor_sync(0xFFFFFFFFu, v, 2));
                rmax[mt][hf] = v;
            }
        float corr[2][2], rsum[2][2];
#pragma unroll
        for (int mt = 0; mt < 2; mt++)
#pragma unroll
            for (int hf = 0; hf < 2; hf++) {
                float mn = fmaxf(mrow[mt][hf], rmax[mt][hf]);
                corr[mt][hf] = __expf(mrow[mt][hf] - mn);
                mrow[mt][hf] = mn;
                rsum[mt][hf] = 0.f;
            }
#pragma unroll
        for (int mt = 0; mt < 2; mt++) {
#pragma unroll
            for (int nt = 0; nt < 8; nt++) {
                float p0 = __expf(s[mt][nt][0] - mrow[mt][0]);
                float p1 = __expf(s[mt][nt][1] - mrow[mt][0]);
                float p2 = __expf(s[mt][nt][2] - mrow[mt][1]);
                float p3 = __expf(s[mt][nt][3] - mrow[mt][1]);
                rsum[mt][0] += p0 + p1;
                rsum[mt][1] += p2 + p3;
                *(uint2*)&Pw[(mt * 16 + g)     * PS_STR + nt * 8 + 2 * tc] =
                    make_uint2(f2tf(p0), f2tf(p1));
                *(uint2*)&Pw[(mt * 16 + g + 8) * PS_STR + nt * 8 + 2 * tc] =
                    make_uint2(f2tf(p2), f2tf(p3));
            }
        }
        __syncwarp();
#pragma unroll
        for (int mt = 0; mt < 2; mt++)
#pragma unroll
            for (int hf = 0; hf < 2; hf++) {
                float v = rsum[mt][hf];
                v += __shfl_xor_sync(0xFFFFFFFFu, v, 1);
                v += __shfl_xor_sync(0xFFFFFFFFu, v, 2);
                lrow[mt][hf] = lrow[mt][hf] * corr[mt][hf] + v;
            }
#pragma unroll
        for (int mt = 0; mt < 2; mt++)
#pragma unroll
            for (int nt = 0; nt < 8; nt++) {
                oc[mt][nt][0] *= corr[mt][0];
                oc[mt][nt][1] *= corr[mt][0];
                oc[mt][nt][2] *= corr[mt][1];
                oc[mt][nt][3] *= corr[mt][1];
            }

#pragma unroll
        for (int ks = 0; ks < 8; ks++) {
            unsigned pa[2][4];
#pragma unroll
            for (int mt = 0; mt < 2; mt++) {
                pa[mt][0] = Pw[(mt * 16 + g)     * PS_STR + ks * 8 + tc];
                pa[mt][1] = Pw[(mt * 16 + g + 8) * PS_STR + ks * 8 + tc];
                pa[mt][2] = Pw[(mt * 16 + g)     * PS_STR + ks * 8 + tc + 4];
                pa[mt][3] = Pw[(mt * 16 + g + 8) * PS_STR + ks * 8 + tc + 4];
            }
#pragma unroll
            for (int nt = 0; nt < 8; nt++) {
                unsigned b0 = Vs[(ks * 8 + tc)     * VS_STR + nt * 8 + g];
                unsigned b1 = Vs[(ks * 8 + tc + 4) * VS_STR + nt * 8 + g];
                MMA4(oc[0][nt], pa[0], b0, b1);
                MMA4(oc[1][nt], pa[1], b0, b1);
            }
        }
    }

#pragma unroll
    for (int mt = 0; mt < 2; mt++) {
        float inv0 = 1.f / lrow[mt][0];
        float inv1 = 1.f / lrow[mt][1];
        int row = rowb + q0 + w * 32 + mt * 16 + g;
#pragma unroll
        for (int nt = 0; nt < 8; nt++) {
            int col = colb + nt * 8 + 2 * tc;
            *(float2*)(O + (size_t)row * DMODEL + col) =
                make_float2(oc[mt][nt][0] * inv0, oc[mt][nt][1] * inv0);
            *(float2*)(O + (size_t)(row + 8) * DMODEL + col) =
                make_float2(oc[mt][nt][2] * inv1, oc[mt][nt][3] * inv1);
        }
    }
}

// ---------------- residual add + LayerNorm ---------------------------------
template<int HAS_RES>
__global__ void __launch_bounds__(256)
add_ln_kernel(const float* __restrict__ x, const float* __restrict__ res,
              const float* __restrict__ g, const float* __restrict__ b,
              float* __restrict__ out) {
    int row = blockIdx.x, tid = threadIdx.x;
    __shared__ float sh[16];
    __shared__ float stats[2];

    float4 v = *(const float4*)(x + (size_t)row * DMODEL + tid * 4);
    if (HAS_RES) {
        float4 r = *(const float4*)(res + (size_t)row * DMODEL + tid * 4);
        v.x += r.x; v.y += r.y; v.z += r.z; v.w += r.w;
    }
    float s  = v.x + v.y + v.z + v.w;
    float s2 = v.x*v.x + v.y*v.y + v.z*v.z + v.w*v.w;
#pragma unroll
    for (int o = 16; o > 0; o >>= 1) {
        s  += __shfl_down_sync(0xFFFFFFFFu, s,  o);
        s2 += __shfl_down_sync(0xFFFFFFFFu, s2, o);
    }
    int wid = tid >> 5, lane = tid & 31;
    if (lane == 0) { sh[wid] = s; sh[wid + 8] = s2; }
    __syncthreads();
    if (tid == 0) {
        float ts = 0.f, ts2 = 0.f;
#pragma unroll
        for (int i = 0; i < 8; i++) { ts += sh[i]; ts2 += sh[i + 8]; }
        float mean = ts * (1.f / DMODEL);
        float var  = ts2 * (1.f / DMODEL) - mean * mean;
        stats[0] = mean;
        stats[1] = rsqrtf(var + 1e-5f);
    }
    __syncthreads();
    float mean = stats[0], rstd = stats[1];
    float4 gv = *(const float4*)(g + tid * 4);
    float4 bv = *(const float4*)(b + tid * 4);
    float4 o;
    o.x = (v.x - mean) * rstd * gv.x + bv.x;
    o.y = (v.y - mean) * rstd * gv.y + bv.y;
    o.z = (v.z - mean) * rstd * gv.z + bv.z;
    o.w = (v.w - mean) * rstd * gv.w + bv.w;
    *(float4*)(out + (size_t)row * DMODEL + tid * 4) = o;
}

// ---------------- host orchestration ---------------------------------------
extern "C" void kernel_launch(void* const* d_in, const int* in_sizes, int n_in,
                              void* d_out, int out_size) {
    const int*   ids     = (const int*)  d_in[0];
    const float* emb     = (const float*)d_in[1];
    const float* pe      = (const float*)d_in[2];
    const float* wq      = (const float*)d_in[3];
    const float* bq      = (const float*)d_in[4];
    const float* wk      = (const float*)d_in[5];
    const float* bk      = (const float*)d_in[6];
    const float* wv      = (const float*)d_in[7];
    const float* bvv     = (const float*)d_in[8];
    const float* wo      = (const float*)d_in[9];
    const float* bo      = (const float*)d_in[10];
    const float* ln1_g   = (const float*)d_in[11];
    const float* ln1_b   = (const float*)d_in[12];
    const float* w1      = (const float*)d_in[13];
    const float* b1      = (const float*)d_in[14];
    const float* w2      = (const float*)d_in[15];
    const float* b2      = (const float*)d_in[16];
    const float* ln2_g   = (const float*)d_in[17];
    const float* ln2_b   = (const float*)d_in[18];
    const float* lnf_g   = (const float*)d_in[19];
    const float* lnf_b   = (const float*)d_in[20];
    const float* lm_head = (const float*)d_in[21];
    float* out = (float*)d_out;

    float *h, *q, *k, *v, *ctx, *tmp, *ffn;
    cudaGetSymbolAddress((void**)&h,   g_h);
    cudaGetSymbolAddress((void**)&q,   g_q);
    cudaGetSymbolAddress((void**)&k,   g_k);
    cudaGetSymbolAddress((void**)&v,   g_v);
    cudaGetSymbolAddress((void**)&ctx, g_ctx);
    cudaGetSymbolAddress((void**)&tmp, g_tmp);
    cudaGetSymbolAddress((void**)&ffn, g_ffn);

    cudaFuncSetAttribute(attn_tc_kernel, cudaFuncAttributeMaxDynamicSharedMemorySize, ATT_SMEM);
    cudaFuncSetAttribute(gemm_tf32_v3<0>, cudaFuncAttributeMaxDynamicSharedMemorySize, GEMM_SMEM);
    cudaFuncSetAttribute(gemm_tf32_v3<1>, cudaFuncAttributeMaxDynamicSharedMemorySize, GEMM_SMEM);
    cudaFuncSetAttribute(gemm_tf32_v3<2>, cudaFuncAttributeMaxDynamicSharedMemorySize, GEMM_SMEM);

    embed_kernel<<<NTOK, 256>>>(ids, emb, pe, h);

    dim3 gD(NTOK / 128, DMODEL / 128);   // (32, 8)
    dim3 gF(NTOK / 128, FDIM / 128);     // (32, 32)
    dim3 gV(NTOK / 128, VOCAB / 128);    // (32, 250)
    dim3 gAttn(SEQ / 128, NHEAD, BATCH); // (16, 16, 2)

    for (int i = 0; i < LYR; i++) {
        const size_t oDD = (size_t)i * DMODEL * DMODEL;
        const size_t oD  = (size_t)i * DMODEL;
        const size_t oDF = (size_t)i * DMODEL * FDIM;
        const size_t oF  = (size_t)i * FDIM;

        gemm_tf32_v3<1><<<gD, 256, GEMM_SMEM>>>(h, wq + oDD, bq + oD, q, NTOK, DMODEL, DMODEL);
        gemm_tf32_v3<1><<<gD, 256, GEMM_SMEM>>>(h, wk + oDD, bk + oD, k, NTOK, DMODEL, DMODEL);
        gemm_tf32_v3<1><<<gD, 256, GEMM_SMEM>>>(h, wv + oDD, bvv + oD, v, NTOK, DMODEL, DMODEL);

        attn_tc_kernel<<<gAttn, 128, ATT_SMEM>>>(q, k, v, ctx);

        gemm_tf32_v3<1><<<gD, 256, GEMM_SMEM>>>(ctx, wo + oDD, bo + oD, tmp, NTOK, DMODEL, DMODEL);
        add_ln_kernel<1><<<NTOK, 256>>>(tmp, h, ln1_g + oD, ln1_b + oD, h);

        gemm_tf32_v3<2><<<gF, 256, GEMM_SMEM>>>(h, w1 + oDF, b1 + oF, ffn, NTOK, FDIM, DMODEL);
        gemm_tf32_v3<1><<<gD, 256, GEMM_SMEM>>>(ffn, w2 + oDF, b2 + oD, tmp, NTOK, DMODEL, FDIM);
        add_ln_kernel<1><<<NTOK, 256>>>(tmp, h, ln2_g + oD, ln2_b + oD, h);
    }

    add_ln_kernel<0><<<NTOK, 256>>>(h, nullptr, lnf_g, lnf_b, h);

    gemm_tf32_v3<0><<<gV, 256, GEMM_SMEM>>>(h, lm_head, nullptr, out, NTOK, VOCAB, DMODEL);
}

// round 10
// speedup vs baseline: 3.8355x; 1.0572x over previous
#include <cuda_runtime.h>
#include <cuda_bf16.h>
#include <math.h>
#include <stdint.h>

#define LYR 4
#define DMODEL 1024
#define NHEAD 16
#define HDIM 64
#define FDIM 4096
#define VOCAB 32000
#define BATCH 2
#define SEQ 2048
#define NTOK (BATCH*SEQ)   // 4096
#define QKV_LD 3072

// ---------------- scratch -----------------------------------------------
__device__ float g_h[NTOK * DMODEL];
__device__ float g_qkv[NTOK * QKV_LD];
__device__ float g_ctx[NTOK * DMODEL];
__device__ float g_tmp[NTOK * DMODEL];
__device__ float g_ffn[NTOK * FDIM];
__device__ float g_wqkv[LYR * DMODEL * QKV_LD];
__device__ float g_bqkv[LYR * QKV_LD];

__device__ __forceinline__ unsigned f2tf(float x) {
    unsigned u; asm("cvt.rna.tf32.f32 %0, %1;" : "=r"(u) : "f"(x)); return u;
}
__device__ __forceinline__ uint32_t smem_u32(const void* p) {
    uint32_t a;
    asm("{ .reg .u64 t; cvta.to.shared.u64 t, %1; cvt.u32.u64 %0, t; }" : "=r"(a) : "l"(p));
    return a;
}

#define CP_ASYNC16(dst, src) \
    asm volatile("cp.async.cg.shared.global [%0], [%1], 16;" :: "r"(dst), "l"(src))
#define CP_COMMIT() asm volatile("cp.async.commit_group;" ::: "memory")
#define CP_WAIT(n)  asm volatile("cp.async.wait_group %0;" :: "n"(n) : "memory")

#define MMA4(d, a, b0, b1) \
    asm volatile("mma.sync.aligned.m16n8k8.row.col.f32.tf32.tf32.f32 " \
        "{%0,%1,%2,%3}, {%4,%5,%6,%7}, {%8,%9}, {%0,%1,%2,%3};" \
        : "+f"((d)[0]), "+f"((d)[1]), "+f"((d)[2]), "+f"((d)[3]) \
        : "r"((a)[0]), "r"((a)[1]), "r"((a)[2]), "r"((a)[3]), "r"(b0), "r"(b1))

// ---------------- embed ---------------------------------------------------
__global__ void embed_kernel(const int* __restrict__ ids, const float* __restrict__ emb,
                             const float* __restrict__ pe, float* __restrict__ h) {
    int n = blockIdx.x;
    int s = n & (SEQ - 1);
    int id = ids[n];
    int c = threadIdx.x * 4;
    const float4 e = *(const float4*)(emb + (size_t)id * DMODEL + c);
    const float4 p = *(const float4*)(pe + (size_t)s * DMODEL + c);
    float4 o;
    o.x = 2.f * e.x + p.x; o.y = 2.f * e.y + p.y;
    o.z = 2.f * e.z + p.z; o.w = 2.f * e.w + p.w;
    *(float4*)(h + (size_t)n * DMODEL + c) = o;
}

// ---------------- QKV weight/bias repack (exact copies) --------------------
__global__ void repack_wqkv_kernel(const float* __restrict__ wq, const float* __restrict__ wk,
                                   const float* __restrict__ wv, float* __restrict__ wqkv) {
    size_t idx = (size_t)blockIdx.x * 256 + threadIdx.x;   // float4 index
    int c4 = (int)(idx % 768);
    size_t lk = idx / 768;                                  // l*1024 + k
    int sec = c4 >> 8;
    int nn = (c4 & 255) << 2;
    const float* src = (sec == 0) ? wq : (sec == 1 ? wk : wv);
    float4 v = *(const float4*)(src + lk * DMODEL + nn);
    *(float4*)(wqkv + lk * QKV_LD + (size_t)c4 * 4) = v;
}
__global__ void repack_bqkv_kernel(const float* __restrict__ bq, const float* __restrict__ bk,
                                   const float* __restrict__ bv, float* __restrict__ bqkv) {
    int idx = blockIdx.x * 256 + threadIdx.x;               // 0..LYR*3072-1
    int l = idx / QKV_LD, n = idx % QKV_LD;
    float v = (n < 1024) ? bq[l * DMODEL + n]
            : (n < 2048) ? bk[l * DMODEL + n - 1024]
                         : bv[l * DMODEL + n - 2048];
    bqkv[idx] = v;
}

// ---------------- TF32 GEMM, cp.async 3-stage, BK=32 -----------------------
// C[M,N] = A[M,K] @ W[K,N] (+bias)(+gelu). BM=BN=128, BK=32, 256 thr = 8 warps
// (2Mx4N), warp tile 64x32. Raw fp32 -> mma.tf32 truncation; epilogue *(1+2^-10).
// A smem [m][k] stride 36 words -> consumer banks (4g+tc) all-distinct.
// B smem [k][n] stride 136 words -> consumer banks (8tc+g) all-distinct.
#define STAGES 3
#define A_STR 36
#define B_STR 136
#define A_WORDS (128 * A_STR)          // 4608
#define B_WORDS (32 * B_STR)           // 4352
#define STG_WORDS (A_WORDS + B_WORDS)  // 8960
#define GEMM_SMEM (STAGES * STG_WORDS * 4)  // 107520 B
#define TRUNC_COMP 1.0009765625f       // 1 + 2^-10

template<int EPI>  // 0 none, 1 +bias, 2 +bias+gelu
__global__ void __launch_bounds__(256)
gemm_tf32_v4(const float* __restrict__ A, const float* __restrict__ W,
             const float* __restrict__ bias, float* __restrict__ C,
             int M, int N, int K) {
    extern __shared__ unsigned gsm[];
    const uint32_t sb = smem_u32(gsm);

    const int tid  = threadIdx.x;
    const int ln   = tid & 31;
    const int wid  = tid >> 5;
    const int warpM = wid >> 2;
    const int warpN = wid & 3;
    const int bm = blockIdx.x, bn = blockIdx.y;
    const int g = ln >> 2, tc = ln & 3;

    // per-thread copy descriptors: 4 A chunks + 4 B chunks per stage (16B each)
    uint32_t aDst[4], bDst[4];
    const float* aSrc[4];
    const float* bSrc[4];
#pragma unroll
    for (int j = 0; j < 4; j++) {
        int c = j * 256 + tid;                 // 0..1023
        int m = c >> 3, q = c & 7;
        aDst[j] = (uint32_t)((m * A_STR + q * 4) * 4);
        aSrc[j] = A + (size_t)(bm * 128 + m) * K + q * 4;
        int k = c >> 5, n4 = (c & 31) << 2;
        bDst[j] = (uint32_t)((A_WORDS + k * B_STR + n4) * 4);
        bSrc[j] = W + (size_t)k * N + (size_t)bn * 128 + n4;
    }

    const int NS = K >> 5;

    // prologue: issue stages 0..STAGES-2
#pragma unroll
    for (int p = 0; p < STAGES - 1; p++) {
        uint32_t base = sb + (uint32_t)(p * STG_WORDS * 4);
        const int k0 = p * 32;
#pragma unroll
        for (int j = 0; j < 4; j++) {
            CP_ASYNC16(base + aDst[j], aSrc[j] + k0);
            CP_ASYNC16(base + bDst[j], bSrc[j] + (size_t)k0 * N);
        }
        CP_COMMIT();
    }

    float acc[4][4][4];
#pragma unroll
    for (int mt = 0; mt < 4; mt++)
#pragma unroll
        for (int nt = 0; nt < 4; nt++)
#pragma unroll
            for (int r = 0; r < 4; r++) acc[mt][nt][r] = 0.f;

    for (int s = 0; s < NS; s++) {
        CP_WAIT(STAGES - 2);
        __syncthreads();

        {   // issue stage s+STAGES-1 into the buffer freed at iter s-1
            const int sn = s + STAGES - 1;
            if (sn < NS) {
                uint32_t base = sb + (uint32_t)((sn % STAGES) * STG_WORDS * 4);
                const int k0 = sn * 32;
#pragma unroll
                for (int j = 0; j < 4; j++) {
                    CP_ASYNC16(base + aDst[j], aSrc[j] + k0);
                    CP_ASYNC16(base + bDst[j], bSrc[j] + (size_t)k0 * N);
                }
            }
            CP_COMMIT();
        }

        const unsigned* Ab = gsm + (s % STAGES) * STG_WORDS;
        const unsigned* Bb = Ab + A_WORDS;
#pragma unroll
        for (int kstep = 0; kstep < 4; kstep++) {
            const int kc = kstep * 8;
            uint4 af[4];
            uint2 bf[4];
#pragma unroll
            for (int mt = 0; mt < 4; mt++) {
                int r0 = (warpM * 64 + mt * 16 + g) * A_STR;
                af[mt].x = Ab[r0 + kc + tc];
                af[mt].y = Ab[r0 + 8 * A_STR + kc + tc];
                af[mt].z = Ab[r0 + kc + tc + 4];
                af[mt].w = Ab[r0 + 8 * A_STR + kc + tc + 4];
            }
#pragma unroll
            for (int nt = 0; nt < 4; nt++) {
                int nb = warpN * 32 + nt * 8 + g;
                bf[nt].x = Bb[(kc + tc) * B_STR + nb];
                bf[nt].y = Bb[(kc + tc + 4) * B_STR + nb];
            }
#pragma unroll
            for (int mt = 0; mt < 4; mt++)
#pragma unroll
                for (int nt = 0; nt < 4; nt++) {
                    asm volatile(
                        "mma.sync.aligned.m16n8k8.row.col.f32.tf32.tf32.f32 "
                        "{%0,%1,%2,%3}, {%4,%5,%6,%7}, {%8,%9}, {%0,%1,%2,%3};"
                        : "+f"(acc[mt][nt][0]), "+f"(acc[mt][nt][1]),
                          "+f"(acc[mt][nt][2]), "+f"(acc[mt][nt][3])
                        : "r"(af[mt].x), "r"(af[mt].y), "r"(af[mt].z), "r"(af[mt].w),
                          "r"(bf[nt].x), "r"(bf[nt].y));
                }
        }
    }

    // epilogue
#pragma unroll
    for (int mt = 0; mt < 4; mt++) {
        int row0 = bm * 128 + warpM * 64 + mt * 16 + g;
#pragma unroll
        for (int nt = 0; nt < 4; nt++) {
            int col = bn * 128 + warpN * 32 + nt * 8 + tc * 2;
            float b0 = 0.f, b1 = 0.f;
            if (EPI >= 1) { float2 bb = *(const float2*)(bias + col); b0 = bb.x; b1 = bb.y; }
            float v0 = acc[mt][nt][0] * TRUNC_COMP + b0;
            float v1 = acc[mt][nt][1] * TRUNC_COMP + b1;
            float v2 = acc[mt][nt][2] * TRUNC_COMP + b0;
            float v3 = acc[mt][nt][3] * TRUNC_COMP + b1;
            if (EPI == 2) {
                v0 = 0.5f * v0 * (1.f + erff(v0 * 0.70710678118654752f));
                v1 = 0.5f * v1 * (1.f + erff(v1 * 0.70710678118654752f));
                v2 = 0.5f * v2 * (1.f + erff(v2 * 0.70710678118654752f));
                v3 = 0.5f * v3 * (1.f + erff(v3 * 0.70710678118654752f));
            }
            *(float2*)(C + (size_t)row0 * N + col)       = make_float2(v0, v1);
            *(float2*)(C + (size_t)(row0 + 8) * N + col) = make_float2(v2, v3);
        }
    }
}

// ---------------- Tensor-core flash attention (ld param for fused QKV) -----
#define KS_STR 68
#define VS_STR 72
#define PS_STR 68
#define ATT_SMEM ((64*KS_STR + 64*VS_STR + 4*32*PS_STR) * 4)

__global__ void __launch_bounds__(128)
attn_tc_kernel(const float* __restrict__ Q, const float* __restrict__ K,
               const float* __restrict__ Vv, float* __restrict__ O, int ld) {
    extern __shared__ unsigned att_sm[];
    unsigned* Ks = att_sm;
    unsigned* Vs = Ks + 64 * KS_STR;
    unsigned* Ps = Vs + 64 * VS_STR;

    const int tid = threadIdx.x;
    const int w = tid >> 5, ln = tid & 31;
    const int g = ln >> 2, tc = ln & 3;
    const int q0 = blockIdx.x * 128;
    const int h = blockIdx.y, b = blockIdx.z;
    const int rowb = b * SEQ;
    const int colb = h * HDIM;
    unsigned* Pw = Ps + w * (32 * PS_STR);

    unsigned qa[2][8][4];
#pragma unroll
    for (int mt = 0; mt < 2; mt++) {
        const float* qb = Q + (size_t)(rowb + q0 + w * 32 + mt * 16) * ld + colb;
#pragma unroll
        for (int ks = 0; ks < 8; ks++) {
            qa[mt][ks][0] = f2tf(qb[(size_t)g       * ld + ks * 8 + tc]     * 0.125f);
            qa[mt][ks][1] = f2tf(qb[(size_t)(g + 8) * ld + ks * 8 + tc]     * 0.125f);
            qa[mt][ks][2] = f2tf(qb[(size_t)g       * ld + ks * 8 + tc + 4] * 0.125f);
            qa[mt][ks][3] = f2tf(qb[(size_t)(g + 8) * ld + ks * 8 + tc + 4] * 0.125f);
        }
    }

    float oc[2][8][4];
#pragma unroll
    for (int mt = 0; mt < 2; mt++)
#pragma unroll
        for (int nt = 0; nt < 8; nt++)
#pragma unroll
            for (int r = 0; r < 4; r++) oc[mt][nt][r] = 0.f;
    float mrow[2][2] = {{-1e30f, -1e30f}, {-1e30f, -1e30f}};
    float lrow[2][2] = {{0.f, 0.f}, {0.f, 0.f}};

    for (int kt = 0; kt < SEQ / 64; kt++) {
        __syncthreads();
#pragma unroll
        for (int i = 0; i < 8; i++) {
            int idx = tid + i * 128;
            int r = idx >> 4, c4 = (idx & 15) << 2;
            const float* kp = K  + (size_t)(rowb + kt * 64 + r) * ld + colb + c4;
            const float* vp = Vv + (size_t)(rowb + kt * 64 + r) * ld + colb + c4;
            float4 kv = *(const float4*)kp;
            float4 vv = *(const float4*)vp;
            *(uint4*)&Ks[r * KS_STR + c4] =
                make_uint4(f2tf(kv.x), f2tf(kv.y), f2tf(kv.z), f2tf(kv.w));
            *(uint4*)&Vs[r * VS_STR + c4] =
                make_uint4(f2tf(vv.x), f2tf(vv.y), f2tf(vv.z), f2tf(vv.w));
        }
        __syncthreads();

        float s[2][8][4];
#pragma unroll
        for (int mt = 0; mt < 2; mt++)
#pragma unroll
            for (int nt = 0; nt < 8; nt++)
#pragma unroll
                for (int r = 0; r < 4; r++) s[mt][nt][r] = 0.f;
#pragma unroll
        for (int ks = 0; ks < 8; ks++) {
#pragma unroll
            for (int nt = 0; nt < 8; nt++) {
                unsigned b0 = Ks[(nt * 8 + g) * KS_STR + ks * 8 + tc];
                unsigned b1 = Ks[(nt * 8 + g) * KS_STR + ks * 8 + tc + 4];
                MMA4(s[0][nt], qa[0][ks], b0, b1);
                MMA4(s[1][nt], qa[1][ks], b0, b1);
            }
        }

        float rmax[2][2];
#pragma unroll
        for (int mt = 0; mt < 2; mt++) {
            rmax[mt][0] = -1e30f; rmax[mt][1] = -1e30f;
#pragma unroll
            for (int nt = 0; nt < 8; nt++) {
                rmax[mt][0] = fmaxf(rmax[mt][0], fmaxf(s[mt][nt][0], s[mt][nt][1]));
                rmax[mt][1] = fmaxf(rmax[mt][1], fmaxf(s[mt][nt][2], s[mt][nt][3]));
            }
        }
#pragma unroll
        for (int mt = 0; mt < 2; mt++)
#pragma unroll
            for (int hf = 0; hf < 2; hf++) {
                float v = rmax[mt][hf];
                v = fmaxf(v, __shfl_xor_sync(0xFFFFFFFFu, v, 1));
                v = fmaxf(v, __shfl_xor_sync(0xFFFFFFFFu, v, 2));
                rmax[mt][hf] = v;
            }
        float corr[2][2], rsum[2][2];
#pragma unroll
        for (int mt = 0; mt < 2; mt++)
#pragma unroll
            for (int hf = 0; hf < 2; hf++) {
                float mn = fmaxf(mrow[mt][hf], rmax[mt][hf]);
                corr[mt][hf] = __expf(mrow[mt][hf] - mn);
                mrow[mt][hf] = mn;
                rsum[mt][hf] = 0.f;
            }
#pragma unroll
        for (int mt = 0; mt < 2; mt++) {
#pragma unroll
            for (int nt = 0; nt < 8; nt++) {
                float p0 = __expf(s[mt][nt][0] - mrow[mt][0]);
                float p1 = __expf(s[mt][nt][1] - mrow[mt][0]);
                float p2 = __expf(s[mt][nt][2] - mrow[mt][1]);
                float p3 = __expf(s[mt][nt][3] - mrow[mt][1]);
                rsum[mt][0] += p0 + p1;
                rsum[mt][1] += p2 + p3;
                *(uint2*)&Pw[(mt * 16 + g)     * PS_STR + nt * 8 + 2 * tc] =
                    make_uint2(f2tf(p0), f2tf(p1));
                *(uint2*)&Pw[(mt * 16 + g + 8) * PS_STR + nt * 8 + 2 * tc] =
                    make_uint2(f2tf(p2), f2tf(p3));
            }
        }
        __syncwarp();
#pragma unroll
        for (int mt = 0; mt < 2; mt++)
#pragma unroll
            for (int hf = 0; hf < 2; hf++) {
                float v = rsum[mt][hf];
                v += __shfl_xor_sync(0xFFFFFFFFu, v, 1);
                v += __shfl_xor_sync(0xFFFFFFFFu, v, 2);
                lrow[mt][hf] = lrow[mt][hf] * corr[mt][hf] + v;
            }
#pragma unroll
        for (int mt = 0; mt < 2; mt++)
#pragma unroll
            for (int nt = 0; nt < 8; nt++) {
                oc[mt][nt][0] *= corr[mt][0];
                oc[mt][nt][1] *= corr[mt][0];
                oc[mt][nt][2] *= corr[mt][1];
                oc[mt][nt][3] *= corr[mt][1];
            }

#pragma unroll
        for (int ks = 0; ks < 8; ks++) {
            unsigned pa[2][4];
#pragma unroll
            for (int mt = 0; mt < 2; mt++) {
                pa[mt][0] = Pw[(mt * 16 + g)     * PS_STR + ks * 8 + tc];
                pa[mt][1] = Pw[(mt * 16 + g + 8) * PS_STR + ks * 8 + tc];
                pa[mt][2] = Pw[(mt * 16 + g)     * PS_STR + ks * 8 + tc + 4];
                pa[mt][3] = Pw[(mt * 16 + g + 8) * PS_STR + ks * 8 + tc + 4];
            }
#pragma unroll
            for (int nt = 0; nt < 8; nt++) {
                unsigned b0 = Vs[(ks * 8 + tc)     * VS_STR + nt * 8 + g];
                unsigned b1 = Vs[(ks * 8 + tc + 4) * VS_STR + nt * 8 + g];
                MMA4(oc[0][nt], pa[0], b0, b1);
                MMA4(oc[1][nt], pa[1], b0, b1);
            }
        }
    }

#pragma unroll
    for (int mt = 0; mt < 2; mt++) {
        float inv0 = 1.f / lrow[mt][0];
        float inv1 = 1.f / lrow[mt][1];
        int row = rowb + q0 + w * 32 + mt * 16 + g;
#pragma unroll
        for (int nt = 0; nt < 8; nt++) {
            int col = colb + nt * 8 + 2 * tc;
            *(float2*)(O + (size_t)row * DMODEL + col) =
                make_float2(oc[mt][nt][0] * inv0, oc[mt][nt][1] * inv0);
            *(float2*)(O + (size_t)(row + 8) * DMODEL + col) =
                make_float2(oc[mt][nt][2] * inv1, oc[mt][nt][3] * inv1);
        }
    }
}

// ---------------- residual add + LayerNorm ---------------------------------
template<int HAS_RES>
__global__ void __launch_bounds__(256)
add_ln_kernel(const float* __restrict__ x, const float* __restrict__ res,
              const float* __restrict__ g, const float* __restrict__ b,
              float* __restrict__ out) {
    int row = blockIdx.x, tid = threadIdx.x;
    __shared__ float sh[16];
    __shared__ float stats[2];

    float4 v = *(const float4*)(x + (size_t)row * DMODEL + tid * 4);
    if (HAS_RES) {
        float4 r = *(const float4*)(res + (size_t)row * DMODEL + tid * 4);
        v.x += r.x; v.y += r.y; v.z += r.z; v.w += r.w;
    }
    float s  = v.x + v.y + v.z + v.w;
    float s2 = v.x*v.x + v.y*v.y + v.z*v.z + v.w*v.w;
#pragma unroll
    for (int o = 16; o > 0; o >>= 1) {
        s  += __shfl_down_sync(0xFFFFFFFFu, s,  o);
        s2 += __shfl_down_sync(0xFFFFFFFFu, s2, o);
    }
    int wid = tid >> 5, lane = tid & 31;
    if (lane == 0) { sh[wid] = s; sh[wid + 8] = s2; }
    __syncthreads();
    if (tid == 0) {
        float ts = 0.f, ts2 = 0.f;
#pragma unroll
        for (int i = 0; i < 8; i++) { ts += sh[i]; ts2 += sh[i + 8]; }
        float mean = ts * (1.f / DMODEL);
        float var  = ts2 * (1.f / DMODEL) - mean * mean;
        stats[0] = mean;
        stats[1] = rsqrtf(var + 1e-5f);
    }
    __syncthreads();
    float mean = stats[0], rstd = stats[1];
    float4 gv = *(const float4*)(g + tid * 4);
    float4 bv = *(const float4*)(b + tid * 4);
    float4 o;
    o.x = (v.x - mean) * rstd * gv.x + bv.x;
    o.y = (v.y - mean) * rstd * gv.y + bv.y;
    o.z = (v.z - mean) * rstd * gv.z + bv.z;
    o.w = (v.w - mean) * rstd * gv.w + bv.w;
    *(float4*)(out + (size_t)row * DMODEL + tid * 4) = o;
}

// ---------------- host orchestration ---------------------------------------
extern "C" void kernel_launch(void* const* d_in, const int* in_sizes, int n_in,
                              void* d_out, int out_size) {
    const int*   ids     = (const int*)  d_in[0];
    const float* emb     = (const float*)d_in[1];
    const float* pe      = (const float*)d_in[2];
    const float* wq      = (const float*)d_in[3];
    const float* bq      = (const float*)d_in[4];
    const float* wk      = (const float*)d_in[5];
    const float* bk      = (const float*)d_in[6];
    const float* wv      = (const float*)d_in[7];
    const float* bvv     = (const float*)d_in[8];
    const float* wo      = (const float*)d_in[9];
    const float* bo      = (const float*)d_in[10];
    const float* ln1_g   = (const float*)d_in[11];
    const float* ln1_b   = (const float*)d_in[12];
    const float* w1      = (const float*)d_in[13];
    const float* b1      = (const float*)d_in[14];
    const float* w2      = (const float*)d_in[15];
    const float* b2      = (const float*)d_in[16];
    const float* ln2_g   = (const float*)d_in[17];
    const float* ln2_b   = (const float*)d_in[18];
    const float* lnf_g   = (const float*)d_in[19];
    const float* lnf_b   = (const float*)d_in[20];
    const float* lm_head = (const float*)d_in[21];
    float* out = (float*)d_out;

    float *h, *qkv, *ctx, *tmp, *ffn, *wqkv, *bqkv;
    cudaGetSymbolAddress((void**)&h,    g_h);
    cudaGetSymbolAddress((void**)&qkv,  g_qkv);
    cudaGetSymbolAddress((void**)&ctx,  g_ctx);
    cudaGetSymbolAddress((void**)&tmp,  g_tmp);
    cudaGetSymbolAddress((void**)&ffn,  g_ffn);
    cudaGetSymbolAddress((void**)&wqkv, g_wqkv);
    cudaGetSymbolAddress((void**)&bqkv, g_bqkv);

    cudaFuncSetAttribute(attn_tc_kernel, cudaFuncAttributeMaxDynamicSharedMemorySize, ATT_SMEM);
    cudaFuncSetAttribute(gemm_tf32_v4<0>, cudaFuncAttributeMaxDynamicSharedMemorySize, GEMM_SMEM);
    cudaFuncSetAttribute(gemm_tf32_v4<1>, cudaFuncAttributeMaxDynamicSharedMemorySize, GEMM_SMEM);
    cudaFuncSetAttribute(gemm_tf32_v4<2>, cudaFuncAttributeMaxDynamicSharedMemorySize, GEMM_SMEM);

    embed_kernel<<<NTOK, 256>>>(ids, emb, pe, h);
    repack_wqkv_kernel<<<(LYR * DMODEL * QKV_LD / 4) / 256, 256>>>(wq, wk, wv, wqkv);
    repack_bqkv_kernel<<<(LYR * QKV_LD) / 256, 256>>>(bq, bk, bvv, bqkv);

    dim3 gQKV(NTOK / 128, QKV_LD / 128);  // (32, 24)
    dim3 gD(NTOK / 128, DMODEL / 128);    // (32, 8)
    dim3 gF(NTOK / 128, FDIM / 128);      // (32, 32)
    dim3 gV(NTOK / 128, VOCAB / 128);     // (32, 250)
    dim3 gAttn(SEQ / 128, NHEAD, BATCH);  // (16, 16, 2)

    for (int i = 0; i < LYR; i++) {
        const size_t oDD = (size_t)i * DMODEL * DMODEL;
        const size_t oD  = (size_t)i * DMODEL;
        const size_t oDF = (size_t)i * DMODEL * FDIM;
        const size_t oF  = (size_t)i * FDIM;

        gemm_tf32_v4<1><<<gQKV, 256, GEMM_SMEM>>>(h, wqkv + (size_t)i * DMODEL * QKV_LD,
                                                  bqkv + (size_t)i * QKV_LD, qkv,
                                                  NTOK, QKV_LD, DMODEL);

        attn_tc_kernel<<<gAttn, 128, ATT_SMEM>>>(qkv, qkv + 1024, qkv + 2048, ctx, QKV_LD);

        gemm_tf32_v4<1><<<gD, 256, GEMM_SMEM>>>(ctx, wo + oDD, bo + oD, tmp, NTOK, DMODEL, DMODEL);
        add_ln_kernel<1><<<NTOK, 256>>>(tmp, h, ln1_g + oD, ln1_b + oD, h);

        gemm_tf32_v4<2><<<gF, 256, GEMM_SMEM>>>(h, w1 + oDF, b1 + oF, ffn, NTOK, FDIM, DMODEL);
        gemm_tf32_v4<1><<<gD, 256, GEMM_SMEM>>>(ffn, w2 + oDF, b2 + oD, tmp, NTOK, DMODEL, FDIM);
        add_ln_kernel<1><<<NTOK, 256>>>(tmp, h, ln2_g + oD, ln2_b + oD, h);
    }

    add_ln_kernel<0><<<NTOK, 256>>>(h, nullptr, lnf_g, lnf_b, h);

    gemm_tf32_v4<0><<<gV, 256, GEMM_SMEM>>>(h, lm_head, nullptr, out, NTOK, VOCAB, DMODEL);
}

// round 12
// speedup vs baseline: 4.1497x; 1.0819x over previous
#include <cuda_runtime.h>
#include <cuda_bf16.h>
#include <math.h>
#include <stdint.h>

#define LYR 4
#define DMODEL 1024
#define NHEAD 16
#define HDIM 64
#define FDIM 4096
#define VOCAB 32000
#define BATCH 2
#define SEQ 2048
#define NTOK (BATCH*SEQ)   // 4096
#define QKV_LD 3072

// ---------------- scratch -----------------------------------------------
__device__ float g_h[NTOK * DMODEL];
__device__ float g_qkv[NTOK * QKV_LD];
__device__ float g_ctx[NTOK * DMODEL];
__device__ float g_tmp[NTOK * DMODEL];
__device__ float g_ffn[NTOK * FDIM];
__device__ float g_wqkv[LYR * DMODEL * QKV_LD];
__device__ float g_bqkv[LYR * QKV_LD];

__device__ __forceinline__ unsigned f2tf(float x) {
    unsigned u; asm("cvt.rna.tf32.f32 %0, %1;" : "=r"(u) : "f"(x)); return u;
}
__device__ __forceinline__ uint32_t smem_u32(const void* p) {
    uint32_t a;
    asm("{ .reg .u64 t; cvta.to.shared.u64 t, %1; cvt.u32.u64 %0, t; }" : "=r"(a) : "l"(p));
    return a;
}

#define CP_ASYNC16(dst, src) \
    asm volatile("cp.async.cg.shared.global [%0], [%1], 16;" :: "r"(dst), "l"(src))
#define CP_COMMIT() asm volatile("cp.async.commit_group;" ::: "memory")
#define CP_WAIT(n)  asm volatile("cp.async.wait_group %0;" :: "n"(n) : "memory")

#define MMA4(d, a, b0, b1) \
    asm volatile("mma.sync.aligned.m16n8k8.row.col.f32.tf32.tf32.f32 " \
        "{%0,%1,%2,%3}, {%4,%5,%6,%7}, {%8,%9}, {%0,%1,%2,%3};" \
        : "+f"((d)[0]), "+f"((d)[1]), "+f"((d)[2]), "+f"((d)[3]) \
        : "r"((a)[0]), "r"((a)[1]), "r"((a)[2]), "r"((a)[3]), "r"(b0), "r"(b1))

// ---------------- embed ---------------------------------------------------
__global__ void embed_kernel(const int* __restrict__ ids, const float* __restrict__ emb,
                             const float* __restrict__ pe, float* __restrict__ h) {
    int n = blockIdx.x;
    int s = n & (SEQ - 1);
    int id = ids[n];
    int c = threadIdx.x * 4;
    const float4 e = *(const float4*)(emb + (size_t)id * DMODEL + c);
    const float4 p = *(const float4*)(pe + (size_t)s * DMODEL + c);
    float4 o;
    o.x = 2.f * e.x + p.x; o.y = 2.f * e.y + p.y;
    o.z = 2.f * e.z + p.z; o.w = 2.f * e.w + p.w;
    *(float4*)(h + (size_t)n * DMODEL + c) = o;
}

// ---------------- QKV weight/bias repack (exact copies) --------------------
__global__ void repack_wqkv_kernel(const float* __restrict__ wq, const float* __restrict__ wk,
                                   const float* __restrict__ wv, float* __restrict__ wqkv) {
    size_t idx = (size_t)blockIdx.x * 256 + threadIdx.x;
    int c4 = (int)(idx % 768);
    size_t lk = idx / 768;
    int sec = c4 >> 8;
    int nn = (c4 & 255) << 2;
    const float* src = (sec == 0) ? wq : (sec == 1 ? wk : wv);
    float4 v = *(const float4*)(src + lk * DMODEL + nn);
    *(float4*)(wqkv + lk * QKV_LD + (size_t)c4 * 4) = v;
}
__global__ void repack_bqkv_kernel(const float* __restrict__ bq, const float* __restrict__ bk,
                                   const float* __restrict__ bv, float* __restrict__ bqkv) {
    int idx = blockIdx.x * 256 + threadIdx.x;
    int l = idx / QKV_LD, n = idx % QKV_LD;
    float v = (n < 1024) ? bq[l * DMODEL + n]
            : (n < 2048) ? bk[l * DMODEL + n - 1024]
                         : bv[l * DMODEL + n - 2048];
    bqkv[idx] = v;
}

// ---------------- TF32 GEMM, cp.async 3-stage, BK=32, 2 CTAs/SM ------------
#define STAGES 3
#define A_STR 36
#define B_STR 136
#define A_WORDS (128 * A_STR)          // 4608
#define B_WORDS (32 * B_STR)           // 4352
#define STG_WORDS (A_WORDS + B_WORDS)  // 8960
#define GEMM_SMEM (STAGES * STG_WORDS * 4)  // 107520 B
#define TRUNC_COMP 1.0009765625f       // 1 + 2^-10

template<int EPI>  // 0 none, 1 +bias, 2 +bias+gelu
__global__ void __launch_bounds__(256, 2)
gemm_tf32_v5(const float* __restrict__ A, const float* __restrict__ W,
             const float* __restrict__ bias, float* __restrict__ C,
             int M, int N, int K) {
    extern __shared__ unsigned gsm[];
    const uint32_t sb = smem_u32(gsm);

    const int tid  = threadIdx.x;
    const int ln   = tid & 31;
    const int wid  = tid >> 5;
    const int warpM = wid >> 2;
    const int warpN = wid & 3;
    const int bm = blockIdx.x, bn = blockIdx.y;
    const int g = ln >> 2, tc = ln & 3;

    // lean addressing: two base pointers + int offsets (saves regs vs 8 ptrs)
    const float* Abase = A + (size_t)(bm * 128) * K;
    const float* Wbase = W + (size_t)(bn * 128);
    uint32_t aDst[4], bDst[4];
    int aOffG[4], bOffG[4];
#pragma unroll
    for (int j = 0; j < 4; j++) {
        int c = j * 256 + tid;                 // 0..1023
        int m = c >> 3, q = c & 7;
        aDst[j] = (uint32_t)((m * A_STR + q * 4) * 4);
        aOffG[j] = m * K + q * 4;
        int k = c >> 5, n4 = (c & 31) << 2;
        bDst[j] = (uint32_t)((A_WORDS + k * B_STR + n4) * 4);
        bOffG[j] = k * N + n4;
    }

    const int NS = K >> 5;

#pragma unroll
    for (int p = 0; p < STAGES - 1; p++) {
        uint32_t base = sb + (uint32_t)(p * STG_WORDS * 4);
        const int k0 = p * 32;
#pragma unroll
        for (int j = 0; j < 4; j++) {
            CP_ASYNC16(base + aDst[j], Abase + aOffG[j] + k0);
            CP_ASYNC16(base + bDst[j], Wbase + bOffG[j] + (size_t)k0 * N);
        }
        CP_COMMIT();
    }

    float acc[4][4][4];
#pragma unroll
    for (int mt = 0; mt < 4; mt++)
#pragma unroll
        for (int nt = 0; nt < 4; nt++)
#pragma unroll
            for (int r = 0; r < 4; r++) acc[mt][nt][r] = 0.f;

    for (int s = 0; s < NS; s++) {
        CP_WAIT(STAGES - 2);
        __syncthreads();

        {
            const int sn = s + STAGES - 1;
            if (sn < NS) {
                uint32_t base = sb + (uint32_t)((sn % STAGES) * STG_WORDS * 4);
                const int k0 = sn * 32;
#pragma unroll
                for (int j = 0; j < 4; j++) {
                    CP_ASYNC16(base + aDst[j], Abase + aOffG[j] + k0);
                    CP_ASYNC16(base + bDst[j], Wbase + bOffG[j] + (size_t)k0 * N);
                }
            }
            CP_COMMIT();
        }

        const unsigned* Ab = gsm + (s % STAGES) * STG_WORDS;
        const unsigned* Bb = Ab + A_WORDS;
#pragma unroll
        for (int kstep = 0; kstep < 4; kstep++) {
            const int kc = kstep * 8;
            uint4 af[4];
            uint2 bf[4];
#pragma unroll
            for (int mt = 0; mt < 4; mt++) {
                int r0 = (warpM * 64 + mt * 16 + g) * A_STR;
                af[mt].x = Ab[r0 + kc + tc];
                af[mt].y = Ab[r0 + 8 * A_STR + kc + tc];
                af[mt].z = Ab[r0 + kc + tc + 4];
                af[mt].w = Ab[r0 + 8 * A_STR + kc + tc + 4];
            }
#pragma unroll
            for (int nt = 0; nt < 4; nt++) {
                int nb = warpN * 32 + nt * 8 + g;
                bf[nt].x = Bb[(kc + tc) * B_STR + nb];
                bf[nt].y = Bb[(kc + tc + 4) * B_STR + nb];
            }
#pragma unroll
            for (int mt = 0; mt < 4; mt++)
#pragma unroll
                for (int nt = 0; nt < 4; nt++) {
                    asm volatile(
                        "mma.sync.aligned.m16n8k8.row.col.f32.tf32.tf32.f32 "
                        "{%0,%1,%2,%3}, {%4,%5,%6,%7}, {%8,%9}, {%0,%1,%2,%3};"
                        : "+f"(acc[mt][nt][0]), "+f"(acc[mt][nt][1]),
                          "+f"(acc[mt][nt][2]), "+f"(acc[mt][nt][3])
                        : "r"(af[mt].x), "r"(af[mt].y), "r"(af[mt].z), "r"(af[mt].w),
                          "r"(bf[nt].x), "r"(bf[nt].y));
                }
        }
    }

#pragma unroll
    for (int mt = 0; mt < 4; mt++) {
        int row0 = bm * 128 + warpM * 64 + mt * 16 + g;
#pragma unroll
        for (int nt = 0; nt < 4; nt++) {
            int col = bn * 128 + warpN * 32 + nt * 8 + tc * 2;
            float b0 = 0.f, b1 = 0.f;
            if (EPI >= 1) { float2 bb = *(const float2*)(bias + col); b0 = bb.x; b1 = bb.y; }
            float v0 = acc[mt][nt][0] * TRUNC_COMP + b0;
            float v1 = acc[mt][nt][1] * TRUNC_COMP + b1;
            float v2 = acc[mt][nt][2] * TRUNC_COMP + b0;
            float v3 = acc[mt][nt][3] * TRUNC_COMP + b1;
            if (EPI == 2) {
                v0 = 0.5f * v0 * (1.f + erff(v0 * 0.70710678118654752f));
                v1 = 0.5f * v1 * (1.f + erff(v1 * 0.70710678118654752f));
                v2 = 0.5f * v2 * (1.f + erff(v2 * 0.70710678118654752f));
                v3 = 0.5f * v3 * (1.f + erff(v3 * 0.70710678118654752f));
            }
            *(float2*)(C + (size_t)row0 * N + col)       = make_float2(v0, v1);
            *(float2*)(C + (size_t)(row0 + 8) * N + col) = make_float2(v2, v3);
        }
    }
}

// ---------------- Tensor-core flash attention (unchanged) ------------------
#define KS_STR 68
#define VS_STR 72
#define PS_STR 68
#define ATT_SMEM ((64*KS_STR + 64*VS_STR + 4*32*PS_STR) * 4)

__global__ void __launch_bounds__(128)
attn_tc_kernel(const float* __restrict__ Q, const float* __restrict__ K,
               const float* __restrict__ Vv, float* __restrict__ O, int ld) {
    extern __shared__ unsigned att_sm[];
    unsigned* Ks = att_sm;
    unsigned* Vs = Ks + 64 * KS_STR;
    unsigned* Ps = Vs + 64 * VS_STR;

    const int tid = threadIdx.x;
    const int w = tid >> 5, ln = tid & 31;
    const int g = ln >> 2, tc = ln & 3;
    const int q0 = blockIdx.x * 128;
    const int h = blockIdx.y, b = blockIdx.z;
    const int rowb = b * SEQ;
    const int colb = h * HDIM;
    unsigned* Pw = Ps + w * (32 * PS_STR);

    unsigned qa[2][8][4];
#pragma unroll
    for (int mt = 0; mt < 2; mt++) {
        const float* qb = Q + (size_t)(rowb + q0 + w * 32 + mt * 16) * ld + colb;
#pragma unroll
        for (int ks = 0; ks < 8; ks++) {
            qa[mt][ks][0] = f2tf(qb[(size_t)g       * ld + ks * 8 + tc]     * 0.125f);
            qa[mt][ks][1] = f2tf(qb[(size_t)(g + 8) * ld + ks * 8 + tc]     * 0.125f);
            qa[mt][ks][2] = f2tf(qb[(size_t)g       * ld + ks * 8 + tc + 4] * 0.125f);
            qa[mt][ks][3] = f2tf(qb[(size_t)(g + 8) * ld + ks * 8 + tc + 4] * 0.125f);
        }
    }

    float oc[2][8][4];
#pragma unroll
    for (int mt = 0; mt < 2; mt++)
#pragma unroll
        for (int nt = 0; nt < 8; nt++)
#pragma unroll
            for (int r = 0; r < 4; r++) oc[mt][nt][r] = 0.f;
    float mrow[2][2] = {{-1e30f, -1e30f}, {-1e30f, -1e30f}};
    float lrow[2][2] = {{0.f, 0.f}, {0.f, 0.f}};

    for (int kt = 0; kt < SEQ / 64; kt++) {
        __syncthreads();
#pragma unroll
        for (int i = 0; i < 8; i++) {
            int idx = tid + i * 128;
            int r = idx >> 4, c4 = (idx & 15) << 2;
            const float* kp = K  + (size_t)(rowb + kt * 64 + r) * ld + colb + c4;
            const float* vp = Vv + (size_t)(rowb + kt * 64 + r) * ld + colb + c4;
            float4 kv = *(const float4*)kp;
            float4 vv = *(const float4*)vp;
            *(uint4*)&Ks[r * KS_STR + c4] =
                make_uint4(f2tf(kv.x), f2tf(kv.y), f2tf(kv.z), f2tf(kv.w));
            *(uint4*)&Vs[r * VS_STR + c4] =
                make_uint4(f2tf(vv.x), f2tf(vv.y), f2tf(vv.z), f2tf(vv.w));
        }
        __syncthreads();

        float s[2][8][4];
#pragma unroll
        for (int mt = 0; mt < 2; mt++)
#pragma unroll
            for (int nt = 0; nt < 8; nt++)
#pragma unroll
                for (int r = 0; r < 4; r++) s[mt][nt][r] = 0.f;
#pragma unroll
        for (int ks = 0; ks < 8; ks++) {
#pragma unroll
            for (int nt = 0; nt < 8; nt++) {
                unsigned b0 = Ks[(nt * 8 + g) * KS_STR + ks * 8 + tc];
                unsigned b1 = Ks[(nt * 8 + g) * KS_STR + ks * 8 + tc + 4];
                MMA4(s[0][nt], qa[0][ks], b0, b1);
                MMA4(s[1][nt], qa[1][ks], b0, b1);
            }
        }

        float rmax[2][2];
#pragma unroll
        for (int mt = 0; mt < 2; mt++) {
            rmax[mt][0] = -1e30f; rmax[mt][1] = -1e30f;
#pragma unroll
            for (int nt = 0; nt < 8; nt++) {
                rmax[mt][0] = fmaxf(rmax[mt][0], fmaxf(s[mt][nt][0], s[mt][nt][1]));
                rmax[mt][1] = fmaxf(rmax[mt][1], fmaxf(s[mt][nt][2], s[mt][nt][3]));
            }
        }
#pragma unroll
        for (int mt = 0; mt < 2; mt++)
#pragma unroll
            for (int hf = 0; hf < 2; hf++) {
                float v = rmax[mt][hf];
                v = fmaxf(v, __shfl_xor_sync(0xFFFFFFFFu, v, 1));
                v = fmaxf(v, __shfl_xor_sync(0xFFFFFFFFu, v, 2));
                rmax[mt][hf] = v;
            }
        float corr[2][2], rsum[2][2];
#pragma unroll
        for (int mt = 0; mt < 2; mt++)
#pragma unroll
            for (int hf = 0; hf < 2; hf++) {
                float mn = fmaxf(mrow[mt][hf], rmax[mt][hf]);
                corr[mt][hf] = __expf(mrow[mt][hf] - mn);
                mrow[mt][hf] = mn;
                rsum[mt][hf] = 0.f;
            }
#pragma unroll
        for (int mt = 0; mt < 2; mt++) {
#pragma unroll
            for (int nt = 0; nt < 8; nt++) {
                float p0 = __expf(s[mt][nt][0] - mrow[mt][0]);
                float p1 = __expf(s[mt][nt][1] - mrow[mt][0]);
                float p2 = __expf(s[mt][nt][2] - mrow[mt][1]);
                float p3 = __expf(s[mt][nt][3] - mrow[mt][1]);
                rsum[mt][0] += p0 + p1;
                rsum[mt][1] += p2 + p3;
                *(uint2*)&Pw[(mt * 16 + g)     * PS_STR + nt * 8 + 2 * tc] =
                    make_uint2(f2tf(p0), f2tf(p1));
                *(uint2*)&Pw[(mt * 16 + g + 8) * PS_STR + nt * 8 + 2 * tc] =
                    make_uint2(f2tf(p2), f2tf(p3));
            }
        }
        __syncwarp();
#pragma unroll
        for (int mt = 0; mt < 2; mt++)
#pragma unroll
            for (int hf = 0; hf < 2; hf++) {
                float v = rsum[mt][hf];
                v += __shfl_xor_sync(0xFFFFFFFFu, v, 1);
                v += __shfl_xor_sync(0xFFFFFFFFu, v, 2);
                lrow[mt][hf] = lrow[mt][hf] * corr[mt][hf] + v;
            }
#pragma unroll
        for (int mt = 0; mt < 2; mt++)
#pragma unroll
            for (int nt = 0; nt < 8; nt++) {
                oc[mt][nt][0] *= corr[mt][0];
                oc[mt][nt][1] *= corr[mt][0];
                oc[mt][nt][2] *= corr[mt][1];
                oc[mt][nt][3] *= corr[mt][1];
            }

#pragma unroll
        for (int ks = 0; ks < 8; ks++) {
            unsigned pa[2][4];
#pragma unroll
            for (int mt = 0; mt < 2; mt++) {
                pa[mt][0] = Pw[(mt * 16 + g)     * PS_STR + ks * 8 + tc];
                pa[mt][1] = Pw[(mt * 16 + g + 8) * PS_STR + ks * 8 + tc];
                pa[mt][2] = Pw[(mt * 16 + g)     * PS_STR + ks * 8 + tc + 4];
                pa[mt][3] = Pw[(mt * 16 + g + 8) * PS_STR + ks * 8 + tc + 4];
            }
#pragma unroll
            for (int nt = 0; nt < 8; nt++) {
                unsigned b0 = Vs[(ks * 8 + tc)     * VS_STR + nt * 8 + g];
                unsigned b1 = Vs[(ks * 8 + tc + 4) * VS_STR + nt * 8 + g];
                MMA4(oc[0][nt], pa[0], b0, b1);
                MMA4(oc[1][nt], pa[1], b0, b1);
            }
        }
    }

#pragma unroll
    for (int mt = 0; mt < 2; mt++) {
        float inv0 = 1.f / lrow[mt][0];
        float inv1 = 1.f / lrow[mt][1];
        int row = rowb + q0 + w * 32 + mt * 16 + g;
#pragma unroll
        for (int nt = 0; nt < 8; nt++) {
            int col = colb + nt * 8 + 2 * tc;
            *(float2*)(O + (size_t)row * DMODEL + col) =
                make_float2(oc[mt][nt][0] * inv0, oc[mt][nt][1] * inv0);
            *(float2*)(O + (size_t)(row + 8) * DMODEL + col) =
                make_float2(oc[mt][nt][2] * inv1, oc[mt][nt][3] * inv1);
        }
    }
}

// ---------------- residual add + LayerNorm ---------------------------------
template<int HAS_RES>
__global__ void __launch_bounds__(256)
add_ln_kernel(const float* __restrict__ x, const float* __restrict__ res,
              const float* __restrict__ g, const float* __restrict__ b,
              float* __restrict__ out) {
    int row = blockIdx.x, tid = threadIdx.x;
    __shared__ float sh[16];
    __shared__ float stats[2];

    float4 v = *(const float4*)(x + (size_t)row * DMODEL + tid * 4);
    if (HAS_RES) {
        float4 r = *(const float4*)(res + (size_t)row * DMODEL + tid * 4);
        v.x += r.x; v.y += r.y; v.z += r.z; v.w += r.w;
    }
    float s  = v.x + v.y + v.z + v.w;
    float s2 = v.x*v.x + v.y*v.y + v.z*v.z + v.w*v.w;
#pragma unroll
    for (int o = 16; o > 0; o >>= 1) {
        s  += __shfl_down_sync(0xFFFFFFFFu, s,  o);
        s2 += __shfl_down_sync(0xFFFFFFFFu, s2, o);
    }
    int wid = tid >> 5, lane = tid & 31;
    if (lane == 0) { sh[wid] = s; sh[wid + 8] = s2; }
    __syncthreads();
    if (tid == 0) {
        float ts = 0.f, ts2 = 0.f;
#pragma unroll
        for (int i = 0; i < 8; i++) { ts += sh[i]; ts2 += sh[i + 8]; }
        float mean = ts * (1.f / DMODEL);
        float var  = ts2 * (1.f / DMODEL) - mean * mean;
        stats[0] = mean;
        stats[1] = rsqrtf(var + 1e-5f);
    }
    __syncthreads();
    float mean = stats[0], rstd = stats[1];
    float4 gv = *(const float4*)(g + tid * 4);
    float4 bv = *(const float4*)(b + tid * 4);
    float4 o;
    o.x = (v.x - mean) * rstd * gv.x + bv.x;
    o.y = (v.y - mean) * rstd * gv.y + bv.y;
    o.z = (v.z - mean) * rstd * gv.z + bv.z;
    o.w = (v.w - mean) * rstd * gv.w + bv.w;
    *(float4*)(out + (size_t)row * DMODEL + tid * 4) = o;
}

// ---------------- host orchestration ---------------------------------------
extern "C" void kernel_launch(void* const* d_in, const int* in_sizes, int n_in,
                              void* d_out, int out_size) {
    const int*   ids     = (const int*)  d_in[0];
    const float* emb     = (const float*)d_in[1];
    const float* pe      = (const float*)d_in[2];
    const float* wq      = (const float*)d_in[3];
    const float* bq      = (const float*)d_in[4];
    const float* wk      = (const float*)d_in[5];
    const float* bk      = (const float*)d_in[6];
    const float* wv      = (const float*)d_in[7];
    const float* bvv     = (const float*)d_in[8];
    const float* wo      = (const float*)d_in[9];
    const float* bo      = (const float*)d_in[10];
    const float* ln1_g   = (const float*)d_in[11];
    const float* ln1_b   = (const float*)d_in[12];
    const float* w1      = (const float*)d_in[13];
    const float* b1      = (const float*)d_in[14];
    const float* w2      = (const float*)d_in[15];
    const float* b2      = (const float*)d_in[16];
    const float* ln2_g   = (const float*)d_in[17];
    const float* ln2_b   = (const float*)d_in[18];
    const float* lnf_g   = (const float*)d_in[19];
    const float* lnf_b   = (const float*)d_in[20];
    const float* lm_head = (const float*)d_in[21];
    float* out = (float*)d_out;

    float *h, *qkv, *ctx, *tmp, *ffn, *wqkv, *bqkv;
    cudaGetSymbolAddress((void**)&h,    g_h);
    cudaGetSymbolAddress((void**)&qkv,  g_qkv);
    cudaGetSymbolAddress((void**)&ctx,  g_ctx);
    cudaGetSymbolAddress((void**)&tmp,  g_tmp);
    cudaGetSymbolAddress((void**)&ffn,  g_ffn);
    cudaGetSymbolAddress((void**)&wqkv, g_wqkv);
    cudaGetSymbolAddress((void**)&bqkv, g_bqkv);

    cudaFuncSetAttribute(attn_tc_kernel, cudaFuncAttributeMaxDynamicSharedMemorySize, ATT_SMEM);
    cudaFuncSetAttribute(gemm_tf32_v5<0>, cudaFuncAttributeMaxDynamicSharedMemorySize, GEMM_SMEM);
    cudaFuncSetAttribute(gemm_tf32_v5<1>, cudaFuncAttributeMaxDynamicSharedMemorySize, GEMM_SMEM);
    cudaFuncSetAttribute(gemm_tf32_v5<2>, cudaFuncAttributeMaxDynamicSharedMemorySize, GEMM_SMEM);

    embed_kernel<<<NTOK, 256>>>(ids, emb, pe, h);
    repack_wqkv_kernel<<<(LYR * DMODEL * QKV_LD / 4) / 256, 256>>>(wq, wk, wv, wqkv);
    repack_bqkv_kernel<<<(LYR * QKV_LD) / 256, 256>>>(bq, bk, bvv, bqkv);

    dim3 gQKV(NTOK / 128, QKV_LD / 128);  // (32, 24)
    dim3 gD(NTOK / 128, DMODEL / 128);    // (32, 8)
    dim3 gF(NTOK / 128, FDIM / 128);      // (32, 32)
    dim3 gV(NTOK / 128, VOCAB / 128);     // (32, 250)
    dim3 gAttn(SEQ / 128, NHEAD, BATCH);  // (16, 16, 2)

    for (int i = 0; i < LYR; i++) {
        const size_t oDD = (size_t)i * DMODEL * DMODEL;
        const size_t oD  = (size_t)i * DMODEL;
        const size_t oDF = (size_t)i * DMODEL * FDIM;
        const size_t oF  = (size_t)i * FDIM;

        gemm_tf32_v5<1><<<gQKV, 256, GEMM_SMEM>>>(h, wqkv + (size_t)i * DMODEL * QKV_LD,
                                                  bqkv + (size_t)i * QKV_LD, qkv,
                                                  NTOK, QKV_LD, DMODEL);

        attn_tc_kernel<<<gAttn, 128, ATT_SMEM>>>(qkv, qkv + 1024, qkv + 2048, ctx, QKV_LD);

        gemm_tf32_v5<1><<<gD, 256, GEMM_SMEM>>>(ctx, wo + oDD, bo + oD, tmp, NTOK, DMODEL, DMODEL);
        add_ln_kernel<1><<<NTOK, 256>>>(tmp, h, ln1_g + oD, ln1_b + oD, h);

        gemm_tf32_v5<2><<<gF, 256, GEMM_SMEM>>>(h, w1 + oDF, b1 + oF, ffn, NTOK, FDIM, DMODEL);
        gemm_tf32_v5<1><<<gD, 256, GEMM_SMEM>>>(ffn, w2 + oDF, b2 + oD, tmp, NTOK, DMODEL, FDIM);
        add_ln_kernel<1><<<NTOK, 256>>>(tmp, h, ln2_g + oD, ln2_b + oD, h);
    }

    add_ln_kernel<0><<<NTOK, 256>>>(h, nullptr, lnf_g, lnf_b, h);

    gemm_tf32_v5<0><<<gV, 256, GEMM_SMEM>>>(h, lm_head, nullptr, out, NTOK, VOCAB, DMODEL);
}

// round 15
// speedup vs baseline: 5.6260x; 1.3557x over previous
#include <cuda_runtime.h>
#include <cuda_fp16.h>
#include <math.h>
#include <stdint.h>

#define LYR 4
#define DMODEL 1024
#define NHEAD 16
#define HDIM 64
#define FDIM 4096
#define VOCAB 32000
#define BATCH 2
#define SEQ 2048
#define NTOK (BATCH*SEQ)   // 4096
#define QKV_LD 3072

// ---------------- scratch -----------------------------------------------
__device__ float  g_h[NTOK * DMODEL];
__device__ __half g_h16[NTOK * DMODEL];
__device__ float  g_qkv[NTOK * QKV_LD];
__device__ __half g_ctx16[NTOK * DMODEL];
__device__ float  g_tmp[NTOK * DMODEL];
__device__ __half g_ffn16[NTOK * FDIM];
__device__ float  g_bqkv[LYR * QKV_LD];
__device__ __half g_wqkv16[(size_t)LYR * DMODEL * QKV_LD];   // [l][n(3072)][k(1024)]
__device__ __half g_wo16[(size_t)LYR * DMODEL * DMODEL];     // [l][n][k]
__device__ __half g_w116[(size_t)LYR * DMODEL * FDIM];       // [l][n(4096)][k(1024)]
__device__ __half g_w216[(size_t)LYR * DMODEL * FDIM];       // [l][n(1024)][k(4096)]
__device__ __half g_lm16[(size_t)VOCAB * DMODEL];            // [n(32000)][k(1024)]

__device__ __forceinline__ unsigned f2tf(float x) {
    unsigned u; asm("cvt.rna.tf32.f32 %0, %1;" : "=r"(u) : "f"(x)); return u;
}
__device__ __forceinline__ uint32_t smem_u32(const void* p) {
    uint32_t a;
    asm("{ .reg .u64 t; cvta.to.shared.u64 t, %1; cvt.u32.u64 %0, t; }" : "=r"(a) : "l"(p));
    return a;
}

#define CP_ASYNC16(dst, src) \
    asm volatile("cp.async.cg.shared.global [%0], [%1], 16;" :: "r"(dst), "l"(src))
#define CP_COMMIT() asm volatile("cp.async.commit_group;" ::: "memory")
#define CP_WAIT(n)  asm volatile("cp.async.wait_group %0;" :: "n"(n) : "memory")

#define MMA4(d, a, b0, b1) \
    asm volatile("mma.sync.aligned.m16n8k8.row.col.f32.tf32.tf32.f32 " \
        "{%0,%1,%2,%3}, {%4,%5,%6,%7}, {%8,%9}, {%0,%1,%2,%3};" \
        : "+f"((d)[0]), "+f"((d)[1]), "+f"((d)[2]), "+f"((d)[3]) \
        : "r"((a)[0]), "r"((a)[1]), "r"((a)[2]), "r"((a)[3]), "r"(b0), "r"(b1))

#define MMA_F16(d, a, b0, b1) \
    asm volatile("mma.sync.aligned.m16n8k16.row.col.f32.f16.f16.f32 " \
        "{%0,%1,%2,%3}, {%4,%5,%6,%7}, {%8,%9}, {%0,%1,%2,%3};" \
        : "+f"((d)[0]), "+f"((d)[1]), "+f"((d)[2]), "+f"((d)[3]) \
        : "r"((a).x), "r"((a).y), "r"((a).z), "r"((a).w), "r"(b0), "r"(b1))

// ---------------- embed: h = 2*tok + pe (fp32 + fp16 copy) ------------------
__global__ void embed_kernel(const int* __restrict__ ids, const float* __restrict__ emb,
                             const float* __restrict__ pe, float* __restrict__ h,
                             __half* __restrict__ h16) {
    int n = blockIdx.x;
    int s = n & (SEQ - 1);
    int id = ids[n];
    int c = threadIdx.x * 4;
    const float4 e = *(const float4*)(emb + (size_t)id * DMODEL + c);
    const float4 p = *(const float4*)(pe + (size_t)s * DMODEL + c);
    float4 o;
    o.x = 2.f * e.x + p.x; o.y = 2.f * e.y + p.y;
    o.z = 2.f * e.z + p.z; o.w = 2.f * e.w + p.w;
    *(float4*)(h + (size_t)n * DMODEL + c) = o;
    __half2* hp = (__half2*)(h16 + (size_t)n * DMODEL + c);
    hp[0] = __floats2half2_rn(o.x, o.y);
    hp[1] = __floats2half2_rn(o.z, o.w);
}

// ---------------- transpose + fp32->fp16: dst[n][k] = src[k][n] -------------
__global__ void transpose_f16_kernel(const float* __restrict__ src, __half* __restrict__ dst,
                                     int K, int N) {
    __shared__ float t[32][33];
    int n0 = blockIdx.x * 32, k0 = blockIdx.y * 32;
#pragma unroll
    for (int i = threadIdx.y; i < 32; i += 8)
        t[i][threadIdx.x] = src[(size_t)(k0 + i) * N + n0 + threadIdx.x];
    __syncthreads();
#pragma unroll
    for (int i = threadIdx.y; i < 32; i += 8)
        dst[(size_t)(n0 + i) * K + k0 + threadIdx.x] = __float2half_rn(t[threadIdx.x][i]);
}

__global__ void repack_bqkv_kernel(const float* __restrict__ bq, const float* __restrict__ bk,
                                   const float* __restrict__ bv, float* __restrict__ bqkv) {
    int idx = blockIdx.x * 256 + threadIdx.x;
    int l = idx / QKV_LD, n = idx % QKV_LD;
    float v = (n < 1024) ? bq[l * DMODEL + n]
            : (n < 2048) ? bk[l * DMODEL + n - 1024]
                         : bv[l * DMODEL + n - 2048];
    bqkv[idx] = v;
}

// ---------------- FP16 GEMM, cp.async 4-stage, BK=32, 2 CTAs/SM -------------
// C[M,N] = A[M,K] @ W[N,K]^T (+bias)(+gelu). A fp16 K-major, W fp16 N-major
// ([n][k]). BM=BN=128, 256 thr = 8 warps (2Mx4N), warp tile 64x32,
// mma m16n8k16 fp16 -> fp32 acc. Smem rows stride 40 halfs (20 words):
// fragment banks (20g+tc) all-distinct; STS.128 phases conflict-free.
#define STAGES 4
#define STRW 20                          // words per 32-half row (incl. pad)
#define A_WORDS (128 * STRW)             // 2560
#define B_WORDS (128 * STRW)             // 2560
#define STG_WORDS (A_WORDS + B_WORDS)    // 5120
#define GEMM_SMEM (STAGES * STG_WORDS * 4)  // 81920 B

template<int EPI, int OUT16>  // EPI: 0 none, 1 +bias, 2 +bias+gelu; OUT16: write fp16 instead of fp32
__global__ void __launch_bounds__(256, 2)
gemm_f16(const __half* __restrict__ A, const __half* __restrict__ W,
         const float* __restrict__ bias, float* __restrict__ C,
         __half* __restrict__ C16, int M, int N, int K) {
    extern __shared__ unsigned gsm[];
    const uint32_t sb = smem_u32(gsm);

    const int tid  = threadIdx.x;
    const int ln   = tid & 31;
    const int wid  = tid >> 5;
    const int warpM = wid >> 2;
    const int warpN = wid & 3;
    const int bm = blockIdx.x, bn = blockIdx.y;
    const int g = ln >> 2, tc = ln & 3;

    // producer: per stage, each thread copies 2 A-chunks + 2 B-chunks (16B = 8 halfs)
    const __half* Abase = A + (size_t)(bm * 128) * K;
    const __half* Wbase = W + (size_t)(bn * 128) * K;
    uint32_t aDst[2], bDst[2];
    int aOffG[2], bOffG[2];
#pragma unroll
    for (int j = 0; j < 2; j++) {
        int c = j * 256 + tid;                 // 0..511
        int r = c >> 2, q = c & 3;             // row 0..127, k-chunk 0..3
        aDst[j] = (uint32_t)((r * STRW + q * 4) * 4);
        aOffG[j] = r * K + q * 8;
        bDst[j] = (uint32_t)((A_WORDS + r * STRW + q * 4) * 4);
        bOffG[j] = r * K + q * 8;
    }

    const int NS = K >> 5;

#pragma unroll
    for (int p = 0; p < STAGES - 1; p++) {
        uint32_t base = sb + (uint32_t)(p * STG_WORDS * 4);
        const int k0 = p * 32;
#pragma unroll
        for (int j = 0; j < 2; j++) {
            CP_ASYNC16(base + aDst[j], Abase + aOffG[j] + k0);
            CP_ASYNC16(base + bDst[j], Wbase + bOffG[j] + k0);
        }
        CP_COMMIT();
    }

    float acc[4][4][4];
#pragma unroll
    for (int mt = 0; mt < 4; mt++)
#pragma unroll
        for (int nt = 0; nt < 4; nt++)
#pragma unroll
            for (int r = 0; r < 4; r++) acc[mt][nt][r] = 0.f;

    for (int s = 0; s < NS; s++) {
        CP_WAIT(STAGES - 2);
        __syncthreads();

        {
            const int sn = s + STAGES - 1;
            if (sn < NS) {
                uint32_t base = sb + (uint32_t)((sn % STAGES) * STG_WORDS * 4);
                const int k0 = sn * 32;
#pragma unroll
                for (int j = 0; j < 2; j++) {
                    CP_ASYNC16(base + aDst[j], Abase + aOffG[j] + k0);
                    CP_ASYNC16(base + bDst[j], Wbase + bOffG[j] + k0);
                }
            }
            CP_COMMIT();
        }

        const unsigned* Ab = gsm + (s % STAGES) * STG_WORDS;
        const unsigned* Bb = Ab + A_WORDS;
#pragma unroll
        for (int kstep = 0; kstep < 2; kstep++) {      // two k16 chunks
            const int kc = kstep * 8;                  // word offset in row
            uint4 af[4];
            uint2 bf[4];
#pragma unroll
            for (int mt = 0; mt < 4; mt++) {
                int r0 = (warpM * 64 + mt * 16 + g) * STRW;
                af[mt].x = Ab[r0 + kc + tc];                 // [g][2tc]
                af[mt].y = Ab[r0 + 8 * STRW + kc + tc];      // [g+8][2tc]
                af[mt].z = Ab[r0 + kc + tc + 4];             // [g][2tc+8]
                af[mt].w = Ab[r0 + 8 * STRW + kc + tc + 4];  // [g+8][2tc+8]
            }
#pragma unroll
            for (int nt = 0; nt < 4; nt++) {
                int nb = (warpN * 32 + nt * 8 + g) * STRW;
                bf[nt].x = Bb[nb + kc + tc];                 // [n=g][2tc]
                bf[nt].y = Bb[nb + kc + tc + 4];             // [n=g][2tc+8]
            }
#pragma unroll
            for (int mt = 0; mt < 4; mt++)
#pragma unroll
                for (int nt = 0; nt < 4; nt++)
                    MMA_F16(acc[mt][nt], af[mt], bf[nt].x, bf[nt].y);
        }
    }

    // epilogue
#pragma unroll
    for (int mt = 0; mt < 4; mt++) {
        int row0 = bm * 128 + warpM * 64 + mt * 16 + g;
#pragma unroll
        for (int nt = 0; nt < 4; nt++) {
            int col = bn * 128 + warpN * 32 + nt * 8 + tc * 2;
            float b0 = 0.f, b1 = 0.f;
            if (EPI >= 1) { float2 bb = *(const float2*)(bias + col); b0 = bb.x; b1 = bb.y; }
            float v0 = acc[mt][nt][0] + b0;
            float v1 = acc[mt][nt][1] + b1;
            float v2 = acc[mt][nt][2] + b0;
            float v3 = acc[mt][nt][3] + b1;
            if (EPI == 2) {
                v0 = 0.5f * v0 * (1.f + erff(v0 * 0.70710678118654752f));
                v1 = 0.5f * v1 * (1.f + erff(v1 * 0.70710678118654752f));
                v2 = 0.5f * v2 * (1.f + erff(v2 * 0.70710678118654752f));
                v3 = 0.5f * v3 * (1.f + erff(v3 * 0.70710678118654752f));
            }
            if (OUT16) {
                *(__half2*)(C16 + (size_t)row0 * N + col)       = __floats2half2_rn(v0, v1);
                *(__half2*)(C16 + (size_t)(row0 + 8) * N + col) = __floats2half2_rn(v2, v3);
            } else {
                *(float2*)(C + (size_t)row0 * N + col)       = make_float2(v0, v1);
                *(float2*)(C + (size_t)(row0 + 8) * N + col) = make_float2(v2, v3);
            }
        }
    }
}

// ---------------- Tensor-core flash attention (tf32; fp16 ctx out) ----------
#define KS_STR 68
#define VS_STR 72
#define PS_STR 68
#define ATT_SMEM ((64*KS_STR + 64*VS_STR + 4*32*PS_STR) * 4)

__global__ void __launch_bounds__(128)
attn_tc_kernel(const float* __restrict__ Q, const float* __restrict__ K,
               const float* __restrict__ Vv, __half* __restrict__ O, int ld) {
    extern __shared__ unsigned att_sm[];
    unsigned* Ks = att_sm;
    unsigned* Vs = Ks + 64 * KS_STR;
    unsigned* Ps = Vs + 64 * VS_STR;

    const int tid = threadIdx.x;
    const int w = tid >> 5, ln = tid & 31;
    const int g = ln >> 2, tc = ln & 3;
    const int q0 = blockIdx.x * 128;
    const int h = blockIdx.y, b = blockIdx.z;
    const int rowb = b * SEQ;
    const int colb = h * HDIM;
    unsigned* Pw = Ps + w * (32 * PS_STR);

    unsigned qa[2][8][4];
#pragma unroll
    for (int mt = 0; mt < 2; mt++) {
        const float* qb = Q + (size_t)(rowb + q0 + w * 32 + mt * 16) * ld + colb;
#pragma unroll
        for (int ks = 0; ks < 8; ks++) {
            qa[mt][ks][0] = f2tf(qb[(size_t)g       * ld + ks * 8 + tc]     * 0.125f);
            qa[mt][ks][1] = f2tf(qb[(size_t)(g + 8) * ld + ks * 8 + tc]     * 0.125f);
            qa[mt][ks][2] = f2tf(qb[(size_t)g       * ld + ks * 8 + tc + 4] * 0.125f);
            qa[mt][ks][3] = f2tf(qb[(size_t)(g + 8) * ld + ks * 8 + tc + 4] * 0.125f);
        }
    }

    float oc[2][8][4];
#pragma unroll
    for (int mt = 0; mt < 2; mt++)
#pragma unroll
        for (int nt = 0; nt < 8; nt++)
#pragma unroll
            for (int r = 0; r < 4; r++) oc[mt][nt][r] = 0.f;
    float mrow[2][2] = {{-1e30f, -1e30f}, {-1e30f, -1e30f}};
    float lrow[2][2] = {{0.f, 0.f}, {0.f, 0.f}};

    for (int kt = 0; kt < SEQ / 64; kt++) {
        __syncthreads();
#pragma unroll
        for (int i = 0; i < 8; i++) {
            int idx = tid + i * 128;
            int r = idx >> 4, c4 = (idx & 15) << 2;
            const float* kp = K  + (size_t)(rowb + kt * 64 + r) * ld + colb + c4;
            const float* vp = Vv + (size_t)(rowb + kt * 64 + r) * ld + colb + c4;
            float4 kv = *(const float4*)kp;
            float4 vv = *(const float4*)vp;
            *(uint4*)&Ks[r * KS_STR + c4] =
                make_uint4(f2tf(kv.x), f2tf(kv.y), f2tf(kv.z), f2tf(kv.w));
            *(uint4*)&Vs[r * VS_STR + c4] =
                make_uint4(f2tf(vv.x), f2tf(vv.y), f2tf(vv.z), f2tf(vv.w));
        }
        __syncthreads();

        float s[2][8][4];
#pragma unroll
        for (int mt = 0; mt < 2; mt++)
#pragma unroll
            for (int nt = 0; nt < 8; nt++)
#pragma unroll
                for (int r = 0; r < 4; r++) s[mt][nt][r] = 0.f;
#pragma unroll
        for (int ks = 0; ks < 8; ks++) {
#pragma unroll
            for (int nt = 0; nt < 8; nt++) {
                unsigned b0 = Ks[(nt * 8 + g) * KS_STR + ks * 8 + tc];
                unsigned b1 = Ks[(nt * 8 + g) * KS_STR + ks * 8 + tc + 4];
                MMA4(s[0][nt], qa[0][ks], b0, b1);
                MMA4(s[1][nt], qa[1][ks], b0, b1);
            }
        }

        float rmax[2][2];
#pragma unroll
        for (int mt = 0; mt < 2; mt++) {
            rmax[mt][0] = -1e30f; rmax[mt][1] = -1e30f;
#pragma unroll
            for (int nt = 0; nt < 8; nt++) {
                rmax[mt][0] = fmaxf(rmax[mt][0], fmaxf(s[mt][nt][0], s[mt][nt][1]));
                rmax[mt][1] = fmaxf(rmax[mt][1], fmaxf(s[mt][nt][2], s[mt][nt][3]));
            }
        }
#pragma unroll
        for (int mt = 0; mt < 2; mt++)
#pragma unroll
            for (int hf = 0; hf < 2; hf++) {
                float v = rmax[mt][hf];
                v = fmaxf(v, __shfl_xor_sync(0xFFFFFFFFu, v, 1));
                v = fmaxf(v, __shfl_xor_sync(0xFFFFFFFFu, v, 2));
                rmax[mt][hf] = v;
            }
        float corr[2][2], rsum[2][2];
#pragma unroll
        for (int mt = 0; mt < 2; mt++)
#pragma unroll
            for (int hf = 0; hf < 2; hf++) {
                float mn = fmaxf(mrow[mt][hf], rmax[mt][hf]);
                corr[mt][hf] = __expf(mrow[mt][hf] - mn);
                mrow[mt][hf] = mn;
                rsum[mt][hf] = 0.f;
            }
#pragma unroll
        for (int mt = 0; mt < 2; mt++) {
#pragma unroll
            for (int nt = 0; nt < 8; nt++) {
                float p0 = __expf(s[mt][nt][0] - mrow[mt][0]);
                float p1 = __expf(s[mt][nt][1] - mrow[mt][0]);
                float p2 = __expf(s[mt][nt][2] - mrow[mt][1]);
                float p3 = __expf(s[mt][nt][3] - mrow[mt][1]);
                rsum[mt][0] += p0 + p1;
                rsum[mt][1] += p2 + p3;
                *(uint2*)&Pw[(mt * 16 + g)     * PS_STR + nt * 8 + 2 * tc] =
                    make_uint2(f2tf(p0), f2tf(p1));
                *(uint2*)&Pw[(mt * 16 + g + 8) * PS_STR + nt * 8 + 2 * tc] =
                    make_uint2(f2tf(p2), f2tf(p3));
            }
        }
        __syncwarp();
#pragma unroll
        for (int mt = 0; mt < 2; mt++)
#pragma unroll
            for (int hf = 0; hf < 2; hf++) {
                float v = rsum[mt][hf];
                v += __shfl_xor_sync(0xFFFFFFFFu, v, 1);
                v += __shfl_xor_sync(0xFFFFFFFFu, v, 2);
                lrow[mt][hf] = lrow[mt][hf] * corr[mt][hf] + v;
            }
#pragma unroll
        for (int mt = 0; mt < 2; mt++)
#pragma unroll
            for (int nt = 0; nt < 8; nt++) {
                oc[mt][nt][0] *= corr[mt][0];
                oc[mt][nt][1] *= corr[mt][0];
                oc[mt][nt][2] *= corr[mt][1];
                oc[mt][nt][3] *= corr[mt][1];
            }

#pragma unroll
        for (int ks = 0; ks < 8; ks++) {
            unsigned pa[2][4];
#pragma unroll
            for (int mt = 0; mt < 2; mt++) {
                pa[mt][0] = Pw[(mt * 16 + g)     * PS_STR + ks * 8 + tc];
                pa[mt][1] = Pw[(mt * 16 + g + 8) * PS_STR + ks * 8 + tc];
                pa[mt][2] = Pw[(mt * 16 + g)     * PS_STR + ks * 8 + tc + 4];
                pa[mt][3] = Pw[(mt * 16 + g + 8) * PS_STR + ks * 8 + tc + 4];
            }
#pragma unroll
            for (int nt = 0; nt < 8; nt++) {
                unsigned b0 = Vs[(ks * 8 + tc)     * VS_STR + nt * 8 + g];
                unsigned b1 = Vs[(ks * 8 + tc + 4) * VS_STR + nt * 8 + g];
                MMA4(oc[0][nt], pa[0], b0, b1);
                MMA4(oc[1][nt], pa[1], b0, b1);
            }
        }
    }

#pragma unroll
    for (int mt = 0; mt < 2; mt++) {
        float inv0 = 1.f / lrow[mt][0];
        float inv1 = 1.f / lrow[mt][1];
        int row = rowb + q0 + w * 32 + mt * 16 + g;
#pragma unroll
        for (int nt = 0; nt < 8; nt++) {
            int col = colb + nt * 8 + 2 * tc;
            *(__half2*)(O + (size_t)row * DMODEL + col) =
                __floats2half2_rn(oc[mt][nt][0] * inv0, oc[mt][nt][1] * inv0);
            *(__half2*)(O + (size_t)(row + 8) * DMODEL + col) =
                __floats2half2_rn(oc[mt][nt][2] * inv1, oc[mt][nt][3] * inv1);
        }
    }
}

// ---------------- residual add + LayerNorm (fp32 + fp16 copy) ---------------
template<int HAS_RES>
__global__ void __launch_bounds__(256)
add_ln_kernel(const float* __restrict__ x, const float* __restrict__ res,
              const float* __restrict__ g, const float* __restrict__ b,
              float* __restrict__ out, __half* __restrict__ out16) {
    int row = blockIdx.x, tid = threadIdx.x;
    __shared__ float sh[16];
    __shared__ float stats[2];

    float4 v = *(const float4*)(x + (size_t)row * DMODEL + tid * 4);
    if (HAS_RES) {
        float4 r = *(const float4*)(res + (size_t)row * DMODEL + tid * 4);
        v.x += r.x; v.y += r.y; v.z += r.z; v.w += r.w;
    }
    float s  = v.x + v.y + v.z + v.w;
    float s2 = v.x*v.x + v.y*v.y + v.z*v.z + v.w*v.w;
#pragma unroll
    for (int o = 16; o > 0; o >>= 1) {
        s  += __shfl_down_sync(0xFFFFFFFFu, s,  o);
        s2 += __shfl_down_sync(0xFFFFFFFFu, s2, o);
    }
    int wid = tid >> 5, lane = tid & 31;
    if (lane == 0) { sh[wid] = s; sh[wid + 8] = s2; }
    __syncthreads();
    if (tid == 0) {
        float ts = 0.f, ts2 = 0.f;
#pragma unroll
        for (int i = 0; i < 8; i++) { ts += sh[i]; ts2 += sh[i + 8]; }
        float mean = ts * (1.f / DMODEL);
        float var  = ts2 * (1.f / DMODEL) - mean * mean;
        stats[0] = mean;
        stats[1] = rsqrtf(var + 1e-5f);
    }
    __syncthreads();
    float mean = stats[0], rstd = stats[1];
    float4 gv = *(const float4*)(g + tid * 4);
    float4 bv = *(const float4*)(b + tid * 4);
    float4 o;
    o.x = (v.x - mean) * rstd * gv.x + bv.x;
    o.y = (v.y - mean) * rstd * gv.y + bv.y;
    o.z = (v.z - mean) * rstd * gv.z + bv.z;
    o.w = (v.w - mean) * rstd * gv.w + bv.w;
    *(float4*)(out + (size_t)row * DMODEL + tid * 4) = o;
    __half2* hp = (__half2*)(out16 + (size_t)row * DMODEL + tid * 4);
    hp[0] = __floats2half2_rn(o.x, o.y);
    hp[1] = __floats2half2_rn(o.z, o.w);
}

// ---------------- host orchestration ---------------------------------------
extern "C" void kernel_launch(void* const* d_in, const int* in_sizes, int n_in,
                              void* d_out, int out_size) {
    const int*   ids     = (const int*)  d_in[0];
    const float* emb     = (const float*)d_in[1];
    const float* pe      = (const float*)d_in[2];
    const float* wq      = (const float*)d_in[3];
    const float* bq      = (const float*)d_in[4];
    const float* wk      = (const float*)d_in[5];
    const float* bk      = (const float*)d_in[6];
    const float* wv      = (const float*)d_in[7];
    const float* bvv     = (const float*)d_in[8];
    const float* wo      = (const float*)d_in[9];
    const float* bo      = (const float*)d_in[10];
    const float* ln1_g   = (const float*)d_in[11];
    const float* ln1_b   = (const float*)d_in[12];
    const float* w1      = (const float*)d_in[13];
    const float* b1      = (const float*)d_in[14];
    const float* w2      = (const float*)d_in[15];
    const float* b2      = (const float*)d_in[16];
    const float* ln2_g   = (const float*)d_in[17];
    const float* ln2_b   = (const float*)d_in[18];
    const float* lnf_g   = (const float*)d_in[19];
    const float* lnf_b   = (const float*)d_in[20];
    const float* lm_head = (const float*)d_in[21];
    float* out = (float*)d_out;

    float *h, *qkv, *tmp, *bqkv;
    __half *h16, *ctx16, *ffn16, *wqkv16, *wo16, *w116, *w216, *lm16;
    cudaGetSymbolAddress((void**)&h,      g_h);
    cudaGetSymbolAddress((void**)&h16,    g_h16);
    cudaGetSymbolAddress((void**)&qkv,    g_qkv);
    cudaGetSymbolAddress((void**)&ctx16,  g_ctx16);
    cudaGetSymbolAddress((void**)&tmp,    g_tmp);
    cudaGetSymbolAddress((void**)&ffn16,  g_ffn16);
    cudaGetSymbolAddress((void**)&bqkv,   g_bqkv);
    cudaGetSymbolAddress((void**)&wqkv16, g_wqkv16);
    cudaGetSymbolAddress((void**)&wo16,   g_wo16);
    cudaGetSymbolAddress((void**)&w116,   g_w116);
    cudaGetSymbolAddress((void**)&w216,   g_w216);
    cudaGetSymbolAddress((void**)&lm16,   g_lm16);

    cudaFuncSetAttribute(attn_tc_kernel, cudaFuncAttributeMaxDynamicSharedMemorySize, ATT_SMEM);
    cudaFuncSetAttribute(gemm_f16<0,0>, cudaFuncAttributeMaxDynamicSharedMemorySize, GEMM_SMEM);
    cudaFuncSetAttribute(gemm_f16<1,0>, cudaFuncAttributeMaxDynamicSharedMemorySize, GEMM_SMEM);
    cudaFuncSetAttribute(gemm_f16<2,1>, cudaFuncAttributeMaxDynamicSharedMemorySize, GEMM_SMEM);

    embed_kernel<<<NTOK, 256>>>(ids, emb, pe, h, h16);
    repack_bqkv_kernel<<<(LYR * QKV_LD) / 256, 256>>>(bq, bk, bvv, bqkv);

    // weight transposes -> fp16 [n][k]
    dim3 tthr(32, 8);
    for (int l = 0; l < LYR; l++) {
        const size_t oDD = (size_t)l * DMODEL * DMODEL;
        const size_t oDF = (size_t)l * DMODEL * FDIM;
        transpose_f16_kernel<<<dim3(32, 32), tthr>>>(wq + oDD,
            wqkv16 + ((size_t)l * QKV_LD + 0) * DMODEL, DMODEL, DMODEL);
        transpose_f16_kernel<<<dim3(32, 32), tthr>>>(wk + oDD,
            wqkv16 + ((size_t)l * QKV_LD + 1024) * DMODEL, DMODEL, DMODEL);
        transpose_f16_kernel<<<dim3(32, 32), tthr>>>(wv + oDD,
            wqkv16 + ((size_t)l * QKV_LD + 2048) * DMODEL, DMODEL, DMODEL);
        transpose_f16_kernel<<<dim3(32, 32), tthr>>>(wo + oDD,
            wo16 + oDD, DMODEL, DMODEL);
        transpose_f16_kernel<<<dim3(FDIM / 32, 32), tthr>>>(w1 + oDF,
            w116 + oDF, DMODEL, FDIM);
        transpose_f16_kernel<<<dim3(32, FDIM / 32), tthr>>>(w2 + oDF,
            w216 + oDF, FDIM, DMODEL);
    }
    transpose_f16_kernel<<<dim3(VOCAB / 32, 32), tthr>>>(lm_head, lm16, DMODEL, VOCAB);

    dim3 gQKV(NTOK / 128, QKV_LD / 128);  // (32, 24)
    dim3 gD(NTOK / 128, DMODEL / 128);    // (32, 8)
    dim3 gF(NTOK / 128, FDIM / 128);      // (32, 32)
    dim3 gV(NTOK / 128, VOCAB / 128);     // (32, 250)
    dim3 gAttn(SEQ / 128, NHEAD, BATCH);  // (16, 16, 2)

    for (int i = 0; i < LYR; i++) {
        const size_t oD  = (size_t)i * DMODEL;
        const size_t oF  = (size_t)i * FDIM;

        gemm_f16<1,0><<<gQKV, 256, GEMM_SMEM>>>(h16, wqkv16 + (size_t)i * QKV_LD * DMODEL,
                                                bqkv + (size_t)i * QKV_LD, qkv, nullptr,
                                                NTOK, QKV_LD, DMODEL);

        attn_tc_kernel<<<gAttn, 128, ATT_SMEM>>>(qkv, qkv + 1024, qkv + 2048, ctx16, QKV_LD);

        gemm_f16<1,0><<<gD, 256, GEMM_SMEM>>>(ctx16, wo16 + (size_t)i * DMODEL * DMODEL,
                                              bo + oD, tmp, nullptr, NTOK, DMODEL, DMODEL);
        add_ln_kernel<1><<<NTOK, 256>>>(tmp, h, ln1_g + oD, ln1_b + oD, h, h16);

        gemm_f16<2,1><<<gF, 256, GEMM_SMEM>>>(h16, w116 + (size_t)i * DMODEL * FDIM,
                                              b1 + oF, nullptr, ffn16, NTOK, FDIM, DMODEL);
        gemm_f16<1,0><<<gD, 256, GEMM_SMEM>>>(ffn16, w216 + (size_t)i * DMODEL * FDIM,
                                              b2 + oD, tmp, nullptr, NTOK, DMODEL, FDIM);
        add_ln_kernel<1><<<NTOK, 256>>>(tmp, h, ln2_g + oD, ln2_b + oD, h, h16);
    }

    add_ln_kernel<0><<<NTOK, 256>>>(h, nullptr, lnf_g, lnf_b, h, h16);

    gemm_f16<0,0><<<gV, 256, GEMM_SMEM>>>(h16, lm16, nullptr, out, nullptr,
                                          NTOK, VOCAB, DMODEL);
}

// round 16
// speedup vs baseline: 6.5356x; 1.1617x over previous
#include <cuda_runtime.h>
#include <cuda_fp16.h>
#include <math.h>
#include <stdint.h>

#define LYR 4
#define DMODEL 1024
#define NHEAD 16
#define HDIM 64
#define FDIM 4096
#define VOCAB 32000
#define BATCH 2
#define SEQ 2048
#define NTOK (BATCH*SEQ)   // 4096
#define QKV_LD 3072

// ---------------- scratch -----------------------------------------------
__device__ float  g_h[NTOK * DMODEL];
__device__ __half g_h16[NTOK * DMODEL];
__device__ __half g_qkv16[NTOK * QKV_LD];
__device__ __half g_ctx16[NTOK * DMODEL];
__device__ float  g_tmp[NTOK * DMODEL];
__device__ __half g_ffn16[NTOK * FDIM];
__device__ float  g_bqkv[LYR * QKV_LD];
__device__ __half g_wqkv16[(size_t)LYR * DMODEL * QKV_LD];   // [l][n(3072)][k(1024)]
__device__ __half g_wo16[(size_t)LYR * DMODEL * DMODEL];     // [l][n][k]
__device__ __half g_w116[(size_t)LYR * DMODEL * FDIM];       // [l][n(4096)][k(1024)]
__device__ __half g_w216[(size_t)LYR * DMODEL * FDIM];       // [l][n(1024)][k(4096)]
__device__ __half g_lm16[(size_t)VOCAB * DMODEL];            // [n(32000)][k(1024)]

__device__ __forceinline__ uint32_t smem_u32(const void* p) {
    uint32_t a;
    asm("{ .reg .u64 t; cvta.to.shared.u64 t, %1; cvt.u32.u64 %0, t; }" : "=r"(a) : "l"(p));
    return a;
}

#define CP_ASYNC16(dst, src) \
    asm volatile("cp.async.cg.shared.global [%0], [%1], 16;" :: "r"(dst), "l"(src))
#define CP_COMMIT() asm volatile("cp.async.commit_group;" ::: "memory")
#define CP_WAIT(n)  asm volatile("cp.async.wait_group %0;" :: "n"(n) : "memory")

#define MMA_F16(d, a, b0, b1) \
    asm volatile("mma.sync.aligned.m16n8k16.row.col.f32.f16.f16.f32 " \
        "{%0,%1,%2,%3}, {%4,%5,%6,%7}, {%8,%9}, {%0,%1,%2,%3};" \
        : "+f"((d)[0]), "+f"((d)[1]), "+f"((d)[2]), "+f"((d)[3]) \
        : "r"((a).x), "r"((a).y), "r"((a).z), "r"((a).w), "r"(b0), "r"(b1))

#define LDSM_X4_TRANS(r0, r1, r2, r3, addr) \
    asm volatile("ldmatrix.sync.aligned.m8n8.x4.trans.shared.b16 {%0,%1,%2,%3}, [%4];" \
        : "=r"(r0), "=r"(r1), "=r"(r2), "=r"(r3) : "r"(addr))

// ---------------- embed: h = 2*tok + pe (fp32 + fp16 copy) ------------------
__global__ void embed_kernel(const int* __restrict__ ids, const float* __restrict__ emb,
                             const float* __restrict__ pe, float* __restrict__ h,
                             __half* __restrict__ h16) {
    int n = blockIdx.x;
    int s = n & (SEQ - 1);
    int id = ids[n];
    int c = threadIdx.x * 4;
    const float4 e = *(const float4*)(emb + (size_t)id * DMODEL + c);
    const float4 p = *(const float4*)(pe + (size_t)s * DMODEL + c);
    float4 o;
    o.x = 2.f * e.x + p.x; o.y = 2.f * e.y + p.y;
    o.z = 2.f * e.z + p.z; o.w = 2.f * e.w + p.w;
    *(float4*)(h + (size_t)n * DMODEL + c) = o;
    __half2* hp = (__half2*)(h16 + (size_t)n * DMODEL + c);
    hp[0] = __floats2half2_rn(o.x, o.y);
    hp[1] = __floats2half2_rn(o.z, o.w);
}

// ---------------- transpose + fp32->fp16: dst[n][k] = src[k][n] -------------
__global__ void transpose_f16_kernel(const float* __restrict__ src, __half* __restrict__ dst,
                                     int K, int N) {
    __shared__ float t[32][33];
    int n0 = blockIdx.x * 32, k0 = blockIdx.y * 32;
#pragma unroll
    for (int i = threadIdx.y; i < 32; i += 8)
        t[i][threadIdx.x] = src[(size_t)(k0 + i) * N + n0 + threadIdx.x];
    __syncthreads();
#pragma unroll
    for (int i = threadIdx.y; i < 32; i += 8)
        dst[(size_t)(n0 + i) * K + k0 + threadIdx.x] = __float2half_rn(t[threadIdx.x][i]);
}

__global__ void repack_bqkv_kernel(const float* __restrict__ bq, const float* __restrict__ bk,
                                   const float* __restrict__ bv, float* __restrict__ bqkv) {
    int idx = blockIdx.x * 256 + threadIdx.x;
    int l = idx / QKV_LD, n = idx % QKV_LD;
    float v = (n < 1024) ? bq[l * DMODEL + n]
            : (n < 2048) ? bk[l * DMODEL + n - 1024]
                         : bv[l * DMODEL + n - 2048];
    bqkv[idx] = v;
}

// ---------------- FP16 GEMM, cp.async 4-stage, BK=32, 2 CTAs/SM -------------
#define STAGES 4
#define STRW 20
#define A_WORDS (128 * STRW)
#define B_WORDS (128 * STRW)
#define STG_WORDS (A_WORDS + B_WORDS)
#define GEMM_SMEM (STAGES * STG_WORDS * 4)  // 81920 B

template<int EPI, int OUT16>
__global__ void __launch_bounds__(256, 2)
gemm_f16(const __half* __restrict__ A, const __half* __restrict__ W,
         const float* __restrict__ bias, float* __restrict__ C,
         __half* __restrict__ C16, int M, int N, int K) {
    extern __shared__ unsigned gsm[];
    const uint32_t sb = smem_u32(gsm);

    const int tid  = threadIdx.x;
    const int ln   = tid & 31;
    const int wid  = tid >> 5;
    const int warpM = wid >> 2;
    const int warpN = wid & 3;
    const int bm = blockIdx.x, bn = blockIdx.y;
    const int g = ln >> 2, tc = ln & 3;

    const __half* Abase = A + (size_t)(bm * 128) * K;
    const __half* Wbase = W + (size_t)(bn * 128) * K;
    uint32_t aDst[2], bDst[2];
    int aOffG[2], bOffG[2];
#pragma unroll
    for (int j = 0; j < 2; j++) {
        int c = j * 256 + tid;
        int r = c >> 2, q = c & 3;
        aDst[j] = (uint32_t)((r * STRW + q * 4) * 4);
        aOffG[j] = r * K + q * 8;
        bDst[j] = (uint32_t)((A_WORDS + r * STRW + q * 4) * 4);
        bOffG[j] = r * K + q * 8;
    }

    const int NS = K >> 5;

#pragma unroll
    for (int p = 0; p < STAGES - 1; p++) {
        uint32_t base = sb + (uint32_t)(p * STG_WORDS * 4);
        const int k0 = p * 32;
#pragma unroll
        for (int j = 0; j < 2; j++) {
            CP_ASYNC16(base + aDst[j], Abase + aOffG[j] + k0);
            CP_ASYNC16(base + bDst[j], Wbase + bOffG[j] + k0);
        }
        CP_COMMIT();
    }

    float acc[4][4][4];
#pragma unroll
    for (int mt = 0; mt < 4; mt++)
#pragma unroll
        for (int nt = 0; nt < 4; nt++)
#pragma unroll
            for (int r = 0; r < 4; r++) acc[mt][nt][r] = 0.f;

    for (int s = 0; s < NS; s++) {
        CP_WAIT(STAGES - 2);
        __syncthreads();

        {
            const int sn = s + STAGES - 1;
            if (sn < NS) {
                uint32_t base = sb + (uint32_t)((sn % STAGES) * STG_WORDS * 4);
                const int k0 = sn * 32;
#pragma unroll
                for (int j = 0; j < 2; j++) {
                    CP_ASYNC16(base + aDst[j], Abase + aOffG[j] + k0);
                    CP_ASYNC16(base + bDst[j], Wbase + bOffG[j] + k0);
                }
            }
            CP_COMMIT();
        }

        const unsigned* Ab = gsm + (s % STAGES) * STG_WORDS;
        const unsigned* Bb = Ab + A_WORDS;
#pragma unroll
        for (int kstep = 0; kstep < 2; kstep++) {
            const int kc = kstep * 8;
            uint4 af[4];
            uint2 bf[4];
#pragma unroll
            for (int mt = 0; mt < 4; mt++) {
                int r0 = (warpM * 64 + mt * 16 + g) * STRW;
                af[mt].x = Ab[r0 + kc + tc];
                af[mt].y = Ab[r0 + 8 * STRW + kc + tc];
                af[mt].z = Ab[r0 + kc + tc + 4];
                af[mt].w = Ab[r0 + 8 * STRW + kc + tc + 4];
            }
#pragma unroll
            for (int nt = 0; nt < 4; nt++) {
                int nb = (warpN * 32 + nt * 8 + g) * STRW;
                bf[nt].x = Bb[nb + kc + tc];
                bf[nt].y = Bb[nb + kc + tc + 4];
            }
#pragma unroll
            for (int mt = 0; mt < 4; mt++)
#pragma unroll
                for (int nt = 0; nt < 4; nt++)
                    MMA_F16(acc[mt][nt], af[mt], bf[nt].x, bf[nt].y);
        }
    }

#pragma unroll
    for (int mt = 0; mt < 4; mt++) {
        int row0 = bm * 128 + warpM * 64 + mt * 16 + g;
#pragma unroll
        for (int nt = 0; nt < 4; nt++) {
            int col = bn * 128 + warpN * 32 + nt * 8 + tc * 2;
            float b0 = 0.f, b1 = 0.f;
            if (EPI >= 1) { float2 bb = *(const float2*)(bias + col); b0 = bb.x; b1 = bb.y; }
            float v0 = acc[mt][nt][0] + b0;
            float v1 = acc[mt][nt][1] + b1;
            float v2 = acc[mt][nt][2] + b0;
            float v3 = acc[mt][nt][3] + b1;
            if (EPI == 2) {
                v0 = 0.5f * v0 * (1.f + erff(v0 * 0.70710678118654752f));
                v1 = 0.5f * v1 * (1.f + erff(v1 * 0.70710678118654752f));
                v2 = 0.5f * v2 * (1.f + erff(v2 * 0.70710678118654752f));
                v3 = 0.5f * v3 * (1.f + erff(v3 * 0.70710678118654752f));
            }
            if (OUT16) {
                *(__half2*)(C16 + (size_t)row0 * N + col)       = __floats2half2_rn(v0, v1);
                *(__half2*)(C16 + (size_t)(row0 + 8) * N + col) = __floats2half2_rn(v2, v3);
            } else {
                *(float2*)(C + (size_t)row0 * N + col)       = make_float2(v0, v1);
                *(float2*)(C + (size_t)(row0 + 8) * N + col) = make_float2(v2, v3);
            }
        }
    }
}

// ---------------- FP16 tensor-core flash attention --------------------------
// CTA = 128 q rows, 4 warps x 32 rows (2 m16 tiles). K-tile 64.
// Q,K,V,P fp16; S and ctx accumulate fp32 (m16n8k16). V^T fragments via
// ldmatrix.x4.trans on the [j][d]-stored V tile. Smem rows: 72 halfs
// (36 words) -> fragment banks (4g+tc) all-distinct; ldmatrix rows
// conflict-free (banks 4j..4j+3).
#define AST 72                                     // halfs per smem row
#define ATT_SMEM ((64*AST + 64*AST + 4*32*AST) * 2)  // 36864 B

__global__ void __launch_bounds__(128)
attn_f16_kernel(const __half* __restrict__ Q, const __half* __restrict__ K,
                const __half* __restrict__ Vv, __half* __restrict__ O, int ld) {
    extern __shared__ __half asm16[];
    __half* Ks = asm16;
    __half* Vs = Ks + 64 * AST;
    __half* Pall = Vs + 64 * AST;

    const int tid = threadIdx.x;
    const int w = tid >> 5, ln = tid & 31;
    const int g = ln >> 2, tc = ln & 3;
    const int q0 = blockIdx.x * 128;
    const int h = blockIdx.y, b = blockIdx.z;
    const int rowb = b * SEQ;
    const int colb = h * HDIM;
    __half* Pw = Pall + w * 32 * AST;
    const uint32_t vsb = smem_u32(Vs);
    // ldmatrix per-thread address components (constant across kt/ks/np)
    const uint32_t lm_row = (uint32_t)(ln & 15);
    const uint32_t lm_dof = (uint32_t)((ln & 16) ? 8 : 0);

    // Q fragments from global fp16 (raw; scale applied to S after mma)
    uint4 qa[2][4];
#pragma unroll
    for (int mt = 0; mt < 2; mt++) {
        const __half* qb = Q + (size_t)(rowb + q0 + w * 32 + mt * 16) * ld + colb;
#pragma unroll
        for (int ks = 0; ks < 4; ks++) {
            qa[mt][ks].x = *(const unsigned*)(qb + (size_t)g       * ld + ks * 16 + 2 * tc);
            qa[mt][ks].y = *(const unsigned*)(qb + (size_t)(g + 8) * ld + ks * 16 + 2 * tc);
            qa[mt][ks].z = *(const unsigned*)(qb + (size_t)g       * ld + ks * 16 + 2 * tc + 8);
            qa[mt][ks].w = *(const unsigned*)(qb + (size_t)(g + 8) * ld + ks * 16 + 2 * tc + 8);
        }
    }

    float oc[2][8][4];
#pragma unroll
    for (int mt = 0; mt < 2; mt++)
#pragma unroll
        for (int nt = 0; nt < 8; nt++)
#pragma unroll
            for (int r = 0; r < 4; r++) oc[mt][nt][r] = 0.f;
    float mrow[2][2] = {{-1e30f, -1e30f}, {-1e30f, -1e30f}};
    float lrow[2][2] = {{0.f, 0.f}, {0.f, 0.f}};

    for (int kt = 0; kt < SEQ / 64; kt++) {
        __syncthreads();
        // stage K,V tiles: 64 rows x 64 halfs (128B) each, [j][d]
#pragma unroll
        for (int i = 0; i < 4; i++) {
            int idx = tid + i * 128;          // 0..511
            int r = idx >> 3, q = (idx & 7) * 8;
            const __half* kp = K  + (size_t)(rowb + kt * 64 + r) * ld + colb + q;
            const __half* vp = Vv + (size_t)(rowb + kt * 64 + r) * ld + colb + q;
            *(uint4*)(Ks + r * AST + q) = *(const uint4*)kp;
            *(uint4*)(Vs + r * AST + q) = *(const uint4*)vp;
        }
        __syncthreads();

        // ---- S = Q @ K^T (raw), then scale
        float s[2][8][4];
#pragma unroll
        for (int mt = 0; mt < 2; mt++)
#pragma unroll
            for (int nt = 0; nt < 8; nt++)
#pragma unroll
                for (int r = 0; r < 4; r++) s[mt][nt][r] = 0.f;
#pragma unroll
        for (int ks = 0; ks < 4; ks++) {
#pragma unroll
            for (int nt = 0; nt < 8; nt++) {
                unsigned b0 = *(const unsigned*)(Ks + (nt * 8 + g) * AST + ks * 16 + 2 * tc);
                unsigned b1 = *(const unsigned*)(Ks + (nt * 8 + g) * AST + ks * 16 + 2 * tc + 8);
                MMA_F16(s[0][nt], qa[0][ks], b0, b1);
                MMA_F16(s[1][nt], qa[1][ks], b0, b1);
            }
        }
#pragma unroll
        for (int mt = 0; mt < 2; mt++)
#pragma unroll
            for (int nt = 0; nt < 8; nt++)
#pragma unroll
                for (int r = 0; r < 4; r++) s[mt][nt][r] *= 0.125f;

        // ---- online softmax
        float rmax[2][2];
#pragma unroll
        for (int mt = 0; mt < 2; mt++) {
            rmax[mt][0] = -1e30f; rmax[mt][1] = -1e30f;
#pragma unroll
            for (int nt = 0; nt < 8; nt++) {
                rmax[mt][0] = fmaxf(rmax[mt][0], fmaxf(s[mt][nt][0], s[mt][nt][1]));
                rmax[mt][1] = fmaxf(rmax[mt][1], fmaxf(s[mt][nt][2], s[mt][nt][3]));
            }
        }
#pragma unroll
        for (int mt = 0; mt < 2; mt++)
#pragma unroll
            for (int hf = 0; hf < 2; hf++) {
                float v = rmax[mt][hf];
                v = fmaxf(v, __shfl_xor_sync(0xFFFFFFFFu, v, 1));
                v = fmaxf(v, __shfl_xor_sync(0xFFFFFFFFu, v, 2));
                rmax[mt][hf] = v;
            }
        float corr[2][2], rsum[2][2];
#pragma unroll
        for (int mt = 0; mt < 2; mt++)
#pragma unroll
            for (int hf = 0; hf < 2; hf++) {
                float mn = fmaxf(mrow[mt][hf], rmax[mt][hf]);
                corr[mt][hf] = __expf(mrow[mt][hf] - mn);
                mrow[mt][hf] = mn;
                rsum[mt][hf] = 0.f;
            }
        // p = exp(s - m) -> fp16 P tile in per-warp smem
#pragma unroll
        for (int mt = 0; mt < 2; mt++) {
#pragma unroll
            for (int nt = 0; nt < 8; nt++) {
                float p0 = __expf(s[mt][nt][0] - mrow[mt][0]);
                float p1 = __expf(s[mt][nt][1] - mrow[mt][0]);
                float p2 = __expf(s[mt][nt][2] - mrow[mt][1]);
                float p3 = __expf(s[mt][nt][3] - mrow[mt][1]);
                rsum[mt][0] += p0 + p1;
                rsum[mt][1] += p2 + p3;
                *(__half2*)(Pw + (mt * 16 + g)     * AST + nt * 8 + 2 * tc) =
                    __floats2half2_rn(p0, p1);
                *(__half2*)(Pw + (mt * 16 + g + 8) * AST + nt * 8 + 2 * tc) =
                    __floats2half2_rn(p2, p3);
            }
        }
        __syncwarp();
#pragma unroll
        for (int mt = 0; mt < 2; mt++)
#pragma unroll
            for (int hf = 0; hf < 2; hf++) {
                float v = rsum[mt][hf];
                v += __shfl_xor_sync(0xFFFFFFFFu, v, 1);
                v += __shfl_xor_sync(0xFFFFFFFFu, v, 2);
                lrow[mt][hf] = lrow[mt][hf] * corr[mt][hf] + v;
            }
#pragma unroll
        for (int mt = 0; mt < 2; mt++)
#pragma unroll
            for (int nt = 0; nt < 8; nt++) {
                oc[mt][nt][0] *= corr[mt][0];
                oc[mt][nt][1] *= corr[mt][0];
                oc[mt][nt][2] *= corr[mt][1];
                oc[mt][nt][3] *= corr[mt][1];
            }

        // ---- ctx += P @ V (V^T frags via ldmatrix.trans)
#pragma unroll
        for (int ks = 0; ks < 4; ks++) {        // j-chunk of 16
            uint4 pa[2];
#pragma unroll
            for (int mt = 0; mt < 2; mt++) {
                pa[mt].x = *(const unsigned*)(Pw + (mt * 16 + g)     * AST + ks * 16 + 2 * tc);
                pa[mt].y = *(const unsigned*)(Pw + (mt * 16 + g + 8) * AST + ks * 16 + 2 * tc);
                pa[mt].z = *(const unsigned*)(Pw + (mt * 16 + g)     * AST + ks * 16 + 2 * tc + 8);
                pa[mt].w = *(const unsigned*)(Pw + (mt * 16 + g + 8) * AST + ks * 16 + 2 * tc + 8);
            }
#pragma unroll
            for (int np = 0; np < 4; np++) {    // pair of d8-tiles
                unsigned r0, r1, r2, r3;
                uint32_t addr = vsb + (((ks * 16 + lm_row) * AST) + np * 16 + lm_dof) * 2;
                LDSM_X4_TRANS(r0, r1, r2, r3, addr);
                MMA_F16(oc[0][np * 2],     pa[0], r0, r1);
                MMA_F16(oc[0][np * 2 + 1], pa[0], r2, r3);
                MMA_F16(oc[1][np * 2],     pa[1], r0, r1);
                MMA_F16(oc[1][np * 2 + 1], pa[1], r2, r3);
            }
        }
    }

    // ---- write ctx (fp16)
#pragma unroll
    for (int mt = 0; mt < 2; mt++) {
        float inv0 = 1.f / lrow[mt][0];
        float inv1 = 1.f / lrow[mt][1];
        int row = rowb + q0 + w * 32 + mt * 16 + g;
#pragma unroll
        for (int nt = 0; nt < 8; nt++) {
            int col = colb + nt * 8 + 2 * tc;
            *(__half2*)(O + (size_t)row * DMODEL + col) =
                __floats2half2_rn(oc[mt][nt][0] * inv0, oc[mt][nt][1] * inv0);
            *(__half2*)(O + (size_t)(row + 8) * DMODEL + col) =
                __floats2half2_rn(oc[mt][nt][2] * inv1, oc[mt][nt][3] * inv1);
        }
    }
}

// ---------------- residual add + LayerNorm (fp32 + fp16 copy) ---------------
template<int HAS_RES>
__global__ void __launch_bounds__(256)
add_ln_kernel(const float* __restrict__ x, const float* __restrict__ res,
              const float* __restrict__ g, const float* __restrict__ b,
              float* __restrict__ out, __half* __restrict__ out16) {
    int row = blockIdx.x, tid = threadIdx.x;
    __shared__ float sh[16];
    __shared__ float stats[2];

    float4 v = *(const float4*)(x + (size_t)row * DMODEL + tid * 4);
    if (HAS_RES) {
        float4 r = *(const float4*)(res + (size_t)row * DMODEL + tid * 4);
        v.x += r.x; v.y += r.y; v.z += r.z; v.w += r.w;
    }
    float s  = v.x + v.y + v.z + v.w;
    float s2 = v.x*v.x + v.y*v.y + v.z*v.z + v.w*v.w;
#pragma unroll
    for (int o = 16; o > 0; o >>= 1) {
        s  += __shfl_down_sync(0xFFFFFFFFu, s,  o);
        s2 += __shfl_down_sync(0xFFFFFFFFu, s2, o);
    }
    int wid = tid >> 5, lane = tid & 31;
    if (lane == 0) { sh[wid] = s; sh[wid + 8] = s2; }
    __syncthreads();
    if (tid == 0) {
        float ts = 0.f, ts2 = 0.f;
#pragma unroll
        for (int i = 0; i < 8; i++) { ts += sh[i]; ts2 += sh[i + 8]; }
        float mean = ts * (1.f / DMODEL);
        float var  = ts2 * (1.f / DMODEL) - mean * mean;
        stats[0] = mean;
        stats[1] = rsqrtf(var + 1e-5f);
    }
    __syncthreads();
    float mean = stats[0], rstd = stats[1];
    float4 gv = *(const float4*)(g + tid * 4);
    float4 bv = *(const float4*)(b + tid * 4);
    float4 o;
    o.x = (v.x - mean) * rstd * gv.x + bv.x;
    o.y = (v.y - mean) * rstd * gv.y + bv.y;
    o.z = (v.z - mean) * rstd * gv.z + bv.z;
    o.w = (v.w - mean) * rstd * gv.w + bv.w;
    *(float4*)(out + (size_t)row * DMODEL + tid * 4) = o;
    __half2* hp = (__half2*)(out16 + (size_t)row * DMODEL + tid * 4);
    hp[0] = __floats2half2_rn(o.x, o.y);
    hp[1] = __floats2half2_rn(o.z, o.w);
}

// ---------------- host orchestration ---------------------------------------
extern "C" void kernel_launch(void* const* d_in, const int* in_sizes, int n_in,
                              void* d_out, int out_size) {
    const int*   ids     = (const int*)  d_in[0];
    const float* emb     = (const float*)d_in[1];
    const float* pe      = (const float*)d_in[2];
    const float* wq      = (const float*)d_in[3];
    const float* bq      = (const float*)d_in[4];
    const float* wk      = (const float*)d_in[5];
    const float* bk      = (const float*)d_in[6];
    const float* wv      = (const float*)d_in[7];
    const float* bvv     = (const float*)d_in[8];
    const float* wo      = (const float*)d_in[9];
    const float* bo      = (const float*)d_in[10];
    const float* ln1_g   = (const float*)d_in[11];
    const float* ln1_b   = (const float*)d_in[12];
    const float* w1      = (const float*)d_in[13];
    const float* b1      = (const float*)d_in[14];
    const float* w2      = (const float*)d_in[15];
    const float* b2      = (const float*)d_in[16];
    const float* ln2_g   = (const float*)d_in[17];
    const float* ln2_b   = (const float*)d_in[18];
    const float* lnf_g   = (const float*)d_in[19];
    const float* lnf_b   = (const float*)d_in[20];
    const float* lm_head = (const float*)d_in[21];
    float* out = (float*)d_out;

    float *h, *tmp, *bqkv;
    __half *h16, *qkv16, *ctx16, *ffn16, *wqkv16, *wo16, *w116, *w216, *lm16;
    cudaGetSymbolAddress((void**)&h,      g_h);
    cudaGetSymbolAddress((void**)&h16,    g_h16);
    cudaGetSymbolAddress((void**)&qkv16,  g_qkv16);
    cudaGetSymbolAddress((void**)&ctx16,  g_ctx16);
    cudaGetSymbolAddress((void**)&tmp,    g_tmp);
    cudaGetSymbolAddress((void**)&ffn16,  g_ffn16);
    cudaGetSymbolAddress((void**)&bqkv,   g_bqkv);
    cudaGetSymbolAddress((void**)&wqkv16, g_wqkv16);
    cudaGetSymbolAddress((void**)&wo16,   g_wo16);
    cudaGetSymbolAddress((void**)&w116,   g_w116);
    cudaGetSymbolAddress((void**)&w216,   g_w216);
    cudaGetSymbolAddress((void**)&lm16,   g_lm16);

    cudaFuncSetAttribute(attn_f16_kernel, cudaFuncAttributeMaxDynamicSharedMemorySize, ATT_SMEM);
    cudaFuncSetAttribute(gemm_f16<0,0>, cudaFuncAttributeMaxDynamicSharedMemorySize, GEMM_SMEM);
    cudaFuncSetAttribute(gemm_f16<1,0>, cudaFuncAttributeMaxDynamicSharedMemorySize, GEMM_SMEM);
    cudaFuncSetAttribute(gemm_f16<1,1>, cudaFuncAttributeMaxDynamicSharedMemorySize, GEMM_SMEM);
    cudaFuncSetAttribute(gemm_f16<2,1>, cudaFuncAttributeMaxDynamicSharedMemorySize, GEMM_SMEM);

    embed_kernel<<<NTOK, 256>>>(ids, emb, pe, h, h16);
    repack_bqkv_kernel<<<(LYR * QKV_LD) / 256, 256>>>(bq, bk, bvv, bqkv);

    dim3 tthr(32, 8);
    for (int l = 0; l < LYR; l++) {
        const size_t oDD = (size_t)l * DMODEL * DMODEL;
        const size_t oDF = (size_t)l * DMODEL * FDIM;
        transpose_f16_kernel<<<dim3(32, 32), tthr>>>(wq + oDD,
            wqkv16 + ((size_t)l * QKV_LD + 0) * DMODEL, DMODEL, DMODEL);
        transpose_f16_kernel<<<dim3(32, 32), tthr>>>(wk + oDD,
            wqkv16 + ((size_t)l * QKV_LD + 1024) * DMODEL, DMODEL, DMODEL);
        transpose_f16_kernel<<<dim3(32, 32), tthr>>>(wv + oDD,
            wqkv16 + ((size_t)l * QKV_LD + 2048) * DMODEL, DMODEL, DMODEL);
        transpose_f16_kernel<<<dim3(32, 32), tthr>>>(wo + oDD,
            wo16 + oDD, DMODEL, DMODEL);
        transpose_f16_kernel<<<dim3(FDIM / 32, 32), tthr>>>(w1 + oDF,
            w116 + oDF, DMODEL, FDIM);
        transpose_f16_kernel<<<dim3(32, FDIM / 32), tthr>>>(w2 + oDF,
            w216 + oDF, FDIM, DMODEL);
    }
    transpose_f16_kernel<<<dim3(VOCAB / 32, 32), tthr>>>(lm_head, lm16, DMODEL, VOCAB);

    dim3 gQKV(NTOK / 128, QKV_LD / 128);  // (32, 24)
    dim3 gD(NTOK / 128, DMODEL / 128);    // (32, 8)
    dim3 gF(NTOK / 128, FDIM / 128);      // (32, 32)
    dim3 gV(NTOK / 128, VOCAB / 128);     // (32, 250)
    dim3 gAttn(SEQ / 128, NHEAD, BATCH);  // (16, 16, 2)

    for (int i = 0; i < LYR; i++) {
        const size_t oD  = (size_t)i * DMODEL;
        const size_t oF  = (size_t)i * FDIM;

        gemm_f16<1,1><<<gQKV, 256, GEMM_SMEM>>>(h16, wqkv16 + (size_t)i * QKV_LD * DMODEL,
                                                bqkv + (size_t)i * QKV_LD, nullptr, qkv16,
                                                NTOK, QKV_LD, DMODEL);

        attn_f16_kernel<<<gAttn, 128, ATT_SMEM>>>(qkv16, qkv16 + 1024, qkv16 + 2048,
                                                  ctx16, QKV_LD);

        gemm_f16<1,0><<<gD, 256, GEMM_SMEM>>>(ctx16, wo16 + (size_t)i * DMODEL * DMODEL,
                                              bo + oD, tmp, nullptr, NTOK, DMODEL, DMODEL);
        add_ln_kernel<1><<<NTOK, 256>>>(tmp, h, ln1_g + oD, ln1_b + oD, h, h16);

        gemm_f16<2,1><<<gF, 256, GEMM_SMEM>>>(h16, w116 + (size_t)i * DMODEL * FDIM,
                                              b1 + oF, nullptr, ffn16, NTOK, FDIM, DMODEL);
        gemm_f16<1,0><<<gD, 256, GEMM_SMEM>>>(ffn16, w216 + (size_t)i * DMODEL * FDIM,
                                              b2 + oD, tmp, nullptr, NTOK, DMODEL, FDIM);
        add_ln_kernel<1><<<NTOK, 256>>>(tmp, h, ln2_g + oD, ln2_b + oD, h, h16);
    }

    add_ln_kernel<0><<<NTOK, 256>>>(h, nullptr, lnf_g, lnf_b, h, h16);

    gemm_f16<0,0><<<gV, 256, GEMM_SMEM>>>(h16, lm16, nullptr, out, nullptr,
                                          NTOK, VOCAB, DMODEL);
}

// round 17
// speedup vs baseline: 6.9338x; 1.0609x over previous
#include <cuda_runtime.h>
#include <cuda_fp16.h>
#include <math.h>
#include <stdint.h>

#define LYR 4
#define DMODEL 1024
#define NHEAD 16
#define HDIM 64
#define FDIM 4096
#define VOCAB 32000
#define BATCH 2
#define SEQ 2048
#define NTOK (BATCH*SEQ)   // 4096
#define QKV_LD 3072

// ---------------- scratch -----------------------------------------------
__device__ float  g_h[NTOK * DMODEL];
__device__ __half g_h16[NTOK * DMODEL];
__device__ __half g_qkv16[NTOK * QKV_LD];
__device__ __half g_ctx16[NTOK * DMODEL];
__device__ float  g_tmp[NTOK * DMODEL];
__device__ __half g_ffn16[NTOK * FDIM];
__device__ float  g_bqkv[LYR * QKV_LD];
__device__ __half g_wqkv16[(size_t)LYR * DMODEL * QKV_LD];
__device__ __half g_wo16[(size_t)LYR * DMODEL * DMODEL];
__device__ __half g_w116[(size_t)LYR * DMODEL * FDIM];
__device__ __half g_w216[(size_t)LYR * DMODEL * FDIM];
__device__ __half g_lm16[(size_t)VOCAB * DMODEL];

__device__ __forceinline__ uint32_t smem_u32(const void* p) {
    uint32_t a;
    asm("{ .reg .u64 t; cvta.to.shared.u64 t, %1; cvt.u32.u64 %0, t; }" : "=r"(a) : "l"(p));
    return a;
}

#define CP_ASYNC16(dst, src) \
    asm volatile("cp.async.cg.shared.global [%0], [%1], 16;" :: "r"(dst), "l"(src))
#define CP_COMMIT() asm volatile("cp.async.commit_group;" ::: "memory")
#define CP_WAIT(n)  asm volatile("cp.async.wait_group %0;" :: "n"(n) : "memory")

#define MMA_F16(d, a, b0, b1) \
    asm volatile("mma.sync.aligned.m16n8k16.row.col.f32.f16.f16.f32 " \
        "{%0,%1,%2,%3}, {%4,%5,%6,%7}, {%8,%9}, {%0,%1,%2,%3};" \
        : "+f"((d)[0]), "+f"((d)[1]), "+f"((d)[2]), "+f"((d)[3]) \
        : "r"((a).x), "r"((a).y), "r"((a).z), "r"((a).w), "r"(b0), "r"(b1))

#define LDSM_X4(r0, r1, r2, r3, addr) \
    asm volatile("ldmatrix.sync.aligned.m8n8.x4.shared.b16 {%0,%1,%2,%3}, [%4];" \
        : "=r"(r0), "=r"(r1), "=r"(r2), "=r"(r3) : "r"(addr))

#define LDSM_X4_TRANS(r0, r1, r2, r3, addr) \
    asm volatile("ldmatrix.sync.aligned.m8n8.x4.trans.shared.b16 {%0,%1,%2,%3}, [%4];" \
        : "=r"(r0), "=r"(r1), "=r"(r2), "=r"(r3) : "r"(addr))

// ---------------- embed ---------------------------------------------------
__global__ void embed_kernel(const int* __restrict__ ids, const float* __restrict__ emb,
                             const float* __restrict__ pe, float* __restrict__ h,
                             __half* __restrict__ h16) {
    int n = blockIdx.x;
    int s = n & (SEQ - 1);
    int id = ids[n];
    int c = threadIdx.x * 4;
    const float4 e = *(const float4*)(emb + (size_t)id * DMODEL + c);
    const float4 p = *(const float4*)(pe + (size_t)s * DMODEL + c);
    float4 o;
    o.x = 2.f * e.x + p.x; o.y = 2.f * e.y + p.y;
    o.z = 2.f * e.z + p.z; o.w = 2.f * e.w + p.w;
    *(float4*)(h + (size_t)n * DMODEL + c) = o;
    __half2* hp = (__half2*)(h16 + (size_t)n * DMODEL + c);
    hp[0] = __floats2half2_rn(o.x, o.y);
    hp[1] = __floats2half2_rn(o.z, o.w);
}

// ---------------- transpose + fp32->fp16 ------------------------------------
__global__ void transpose_f16_kernel(const float* __restrict__ src, __half* __restrict__ dst,
                                     int K, int N) {
    __shared__ float t[32][33];
    int n0 = blockIdx.x * 32, k0 = blockIdx.y * 32;
#pragma unroll
    for (int i = threadIdx.y; i < 32; i += 8)
        t[i][threadIdx.x] = src[(size_t)(k0 + i) * N + n0 + threadIdx.x];
    __syncthreads();
#pragma unroll
    for (int i = threadIdx.y; i < 32; i += 8)
        dst[(size_t)(n0 + i) * K + k0 + threadIdx.x] = __float2half_rn(t[threadIdx.x][i]);
}

__global__ void repack_bqkv_kernel(const float* __restrict__ bq, const float* __restrict__ bk,
                                   const float* __restrict__ bv, float* __restrict__ bqkv) {
    int idx = blockIdx.x * 256 + threadIdx.x;
    int l = idx / QKV_LD, n = idx % QKV_LD;
    float v = (n < 1024) ? bq[l * DMODEL + n]
            : (n < 2048) ? bk[l * DMODEL + n - 1024]
                         : bv[l * DMODEL + n - 2048];
    bqkv[idx] = v;
}

// ---------------- FP16 GEMM: BK=64, 3-stage cp.async, ldmatrix --------------
// C[M,N] = A[M,K] @ W[N,K]^T (+bias)(+gelu). 128x128 CTA tile, 8 warps (2Mx4N),
// warp 64x32, mma m16n8k16. Smem rows: 64 halfs + pad = 72 halfs (144 B);
// ldmatrix rows r*36 words -> banks 4r..4r+3, all-32-distinct.
#define STAGES 3
#define STRH 72                              // halfs per row
#define A_HALFS (128 * STRH)                 // 9216
#define STG_HALFS (2 * A_HALFS)              // 18432
#define STG_BYTES (STG_HALFS * 2)            // 36864
#define GEMM_SMEM (STAGES * STG_BYTES)       // 110592 B

template<int EPI, int OUT16>
__global__ void __launch_bounds__(256, 2)
gemm_f16(const __half* __restrict__ A, const __half* __restrict__ W,
         const float* __restrict__ bias, float* __restrict__ C,
         __half* __restrict__ C16, int M, int N, int K) {
    extern __shared__ __half gsm[];
    const uint32_t sb = smem_u32(gsm);

    const int tid  = threadIdx.x;
    const int ln   = tid & 31;
    const int wid  = tid >> 5;
    const int warpM = wid >> 2;
    const int warpN = wid & 3;
    const int bm = blockIdx.x, bn = blockIdx.y;
    const int g = ln >> 2, tc = ln & 3;

    // producer: 4 A + 4 B cp.async per thread per stage
    const __half* Abase = A + (size_t)(bm * 128) * K;
    const __half* Wbase = W + (size_t)(bn * 128) * K;
    uint32_t aDst[4], bDst[4];
    int offG[4];
#pragma unroll
    for (int j = 0; j < 4; j++) {
        int c = j * 256 + tid;                 // 0..1023
        int r = c >> 3, q = c & 7;
        aDst[j] = (uint32_t)((r * STRH + q * 8) * 2);
        bDst[j] = (uint32_t)((A_HALFS + r * STRH + q * 8) * 2);
        offG[j] = r * K + q * 8;
    }

    // ldmatrix addresses (byte offsets within stage)
    const int lrow = ln & 15;
    const int lkh  = (ln >> 4) * 8;            // k-half offset in halfs
    uint32_t aLm[4], bLm[2];
#pragma unroll
    for (int mt = 0; mt < 4; mt++)
        aLm[mt] = (uint32_t)(((warpM * 64 + mt * 16 + lrow) * STRH + lkh) * 2);
#pragma unroll
    for (int bt = 0; bt < 2; bt++)
        bLm[bt] = (uint32_t)((A_HALFS + (warpN * 32 + bt * 16 + lrow) * STRH + lkh) * 2);

    const int NS = K >> 6;

#pragma unroll
    for (int p = 0; p < STAGES - 1; p++) {
        uint32_t base = sb + (uint32_t)(p * STG_BYTES);
        const int k0 = p * 64;
#pragma unroll
        for (int j = 0; j < 4; j++) {
            CP_ASYNC16(base + aDst[j], Abase + offG[j] + k0);
            CP_ASYNC16(base + bDst[j], Wbase + offG[j] + k0);
        }
        CP_COMMIT();
    }

    float acc[4][4][4];
#pragma unroll
    for (int mt = 0; mt < 4; mt++)
#pragma unroll
        for (int nt = 0; nt < 4; nt++)
#pragma unroll
            for (int r = 0; r < 4; r++) acc[mt][nt][r] = 0.f;

    for (int s = 0; s < NS; s++) {
        CP_WAIT(STAGES - 2);
        __syncthreads();

        {
            const int sn = s + STAGES - 1;
            if (sn < NS) {
                uint32_t base = sb + (uint32_t)((sn % STAGES) * STG_BYTES);
                const int k0 = sn * 64;
#pragma unroll
                for (int j = 0; j < 4; j++) {
                    CP_ASYNC16(base + aDst[j], Abase + offG[j] + k0);
                    CP_ASYNC16(base + bDst[j], Wbase + offG[j] + k0);
                }
            }
            CP_COMMIT();
        }

        const uint32_t stb = sb + (uint32_t)((s % STAGES) * STG_BYTES);
#pragma unroll
        for (int ks = 0; ks < 4; ks++) {
            const uint32_t ko = (uint32_t)(ks * 32);   // 16 halfs
            uint4 af[4];
#pragma unroll
            for (int mt = 0; mt < 4; mt++)
                LDSM_X4(af[mt].x, af[mt].y, af[mt].z, af[mt].w, stb + aLm[mt] + ko);
#pragma unroll
            for (int bt = 0; bt < 2; bt++) {
                unsigned r0, r1, r2, r3;
                LDSM_X4(r0, r1, r2, r3, stb + bLm[bt] + ko);
#pragma unroll
                for (int mt = 0; mt < 4; mt++) {
                    MMA_F16(acc[mt][bt * 2],     af[mt], r0, r2);
                    MMA_F16(acc[mt][bt * 2 + 1], af[mt], r1, r3);
                }
            }
        }
    }

    // epilogue
#pragma unroll
    for (int mt = 0; mt < 4; mt++) {
        int row0 = bm * 128 + warpM * 64 + mt * 16 + g;
#pragma unroll
        for (int nt = 0; nt < 4; nt++) {
            int col = bn * 128 + warpN * 32 + nt * 8 + tc * 2;
            float b0 = 0.f, b1 = 0.f;
            if (EPI >= 1) { float2 bb = *(const float2*)(bias + col); b0 = bb.x; b1 = bb.y; }
            float v0 = acc[mt][nt][0] + b0;
            float v1 = acc[mt][nt][1] + b1;
            float v2 = acc[mt][nt][2] + b0;
            float v3 = acc[mt][nt][3] + b1;
            if (EPI == 2) {
                v0 = 0.5f * v0 * (1.f + erff(v0 * 0.70710678118654752f));
                v1 = 0.5f * v1 * (1.f + erff(v1 * 0.70710678118654752f));
                v2 = 0.5f * v2 * (1.f + erff(v2 * 0.70710678118654752f));
                v3 = 0.5f * v3 * (1.f + erff(v3 * 0.70710678118654752f));
            }
            if (OUT16) {
                *(__half2*)(C16 + (size_t)row0 * N + col)       = __floats2half2_rn(v0, v1);
                *(__half2*)(C16 + (size_t)(row0 + 8) * N + col) = __floats2half2_rn(v2, v3);
            } else {
                *(float2*)(C + (size_t)row0 * N + col)       = make_float2(v0, v1);
                *(float2*)(C + (size_t)(row0 + 8) * N + col) = make_float2(v2, v3);
            }
        }
    }
}

// ---------------- FP16 tensor-core flash attention (unchanged) --------------
#define AST 72
#define ATT_SMEM ((64*AST + 64*AST + 4*32*AST) * 2)

__global__ void __launch_bounds__(128)
attn_f16_kernel(const __half* __restrict__ Q, const __half* __restrict__ K,
                const __half* __restrict__ Vv, __half* __restrict__ O, int ld) {
    extern __shared__ __half asm16[];
    __half* Ks = asm16;
    __half* Vs = Ks + 64 * AST;
    __half* Pall = Vs + 64 * AST;

    const int tid = threadIdx.x;
    const int w = tid >> 5, ln = tid & 31;
    const int g = ln >> 2, tc = ln & 3;
    const int q0 = blockIdx.x * 128;
    const int h = blockIdx.y, b = blockIdx.z;
    const int rowb = b * SEQ;
    const int colb = h * HDIM;
    __half* Pw = Pall + w * 32 * AST;
    const uint32_t vsb = smem_u32(Vs);
    const uint32_t lm_row = (uint32_t)(ln & 15);
    const uint32_t lm_dof = (uint32_t)((ln & 16) ? 8 : 0);

    uint4 qa[2][4];
#pragma unroll
    for (int mt = 0; mt < 2; mt++) {
        const __half* qb = Q + (size_t)(rowb + q0 + w * 32 + mt * 16) * ld + colb;
#pragma unroll
        for (int ks = 0; ks < 4; ks++) {
            qa[mt][ks].x = *(const unsigned*)(qb + (size_t)g       * ld + ks * 16 + 2 * tc);
            qa[mt][ks].y = *(const unsigned*)(qb + (size_t)(g + 8) * ld + ks * 16 + 2 * tc);
            qa[mt][ks].z = *(const unsigned*)(qb + (size_t)g       * ld + ks * 16 + 2 * tc + 8);
            qa[mt][ks].w = *(const unsigned*)(qb + (size_t)(g + 8) * ld + ks * 16 + 2 * tc + 8);
        }
    }

    float oc[2][8][4];
#pragma unroll
    for (int mt = 0; mt < 2; mt++)
#pragma unroll
        for (int nt = 0; nt < 8; nt++)
#pragma unroll
            for (int r = 0; r < 4; r++) oc[mt][nt][r] = 0.f;
    float mrow[2][2] = {{-1e30f, -1e30f}, {-1e30f, -1e30f}};
    float lrow[2][2] = {{0.f, 0.f}, {0.f, 0.f}};

    for (int kt = 0; kt < SEQ / 64; kt++) {
        __syncthreads();
#pragma unroll
        for (int i = 0; i < 4; i++) {
            int idx = tid + i * 128;
            int r = idx >> 3, q = (idx & 7) * 8;
            const __half* kp = K  + (size_t)(rowb + kt * 64 + r) * ld + colb + q;
            const __half* vp = Vv + (size_t)(rowb + kt * 64 + r) * ld + colb + q;
            *(uint4*)(Ks + r * AST + q) = *(const uint4*)kp;
            *(uint4*)(Vs + r * AST + q) = *(const uint4*)vp;
        }
        __syncthreads();

        float s[2][8][4];
#pragma unroll
        for (int mt = 0; mt < 2; mt++)
#pragma unroll
            for (int nt = 0; nt < 8; nt++)
#pragma unroll
                for (int r = 0; r < 4; r++) s[mt][nt][r] = 0.f;
#pragma unroll
        for (int ks = 0; ks < 4; ks++) {
#pragma unroll
            for (int nt = 0; nt < 8; nt++) {
                unsigned b0 = *(const unsigned*)(Ks + (nt * 8 + g) * AST + ks * 16 + 2 * tc);
                unsigned b1 = *(const unsigned*)(Ks + (nt * 8 + g) * AST + ks * 16 + 2 * tc + 8);
                MMA_F16(s[0][nt], qa[0][ks], b0, b1);
                MMA_F16(s[1][nt], qa[1][ks], b0, b1);
            }
        }
#pragma unroll
        for (int mt = 0; mt < 2; mt++)
#pragma unroll
            for (int nt = 0; nt < 8; nt++)
#pragma unroll
                for (int r = 0; r < 4; r++) s[mt][nt][r] *= 0.125f;

        float rmax[2][2];
#pragma unroll
        for (int mt = 0; mt < 2; mt++) {
            rmax[mt][0] = -1e30f; rmax[mt][1] = -1e30f;
#pragma unroll
            for (int nt = 0; nt < 8; nt++) {
                rmax[mt][0] = fmaxf(rmax[mt][0], fmaxf(s[mt][nt][0], s[mt][nt][1]));
                rmax[mt][1] = fmaxf(rmax[mt][1], fmaxf(s[mt][nt][2], s[mt][nt][3]));
            }
        }
#pragma unroll
        for (int mt = 0; mt < 2; mt++)
#pragma unroll
            for (int hf = 0; hf < 2; hf++) {
                float v = rmax[mt][hf];
                v = fmaxf(v, __shfl_xor_sync(0xFFFFFFFFu, v, 1));
                v = fmaxf(v, __shfl_xor_sync(0xFFFFFFFFu, v, 2));
                rmax[mt][hf] = v;
            }
        float corr[2][2], rsum[2][2];
#pragma unroll
        for (int mt = 0; mt < 2; mt++)
#pragma unroll
            for (int hf = 0; hf < 2; hf++) {
                float mn = fmaxf(mrow[mt][hf], rmax[mt][hf]);
                corr[mt][hf] = __expf(mrow[mt][hf] - mn);
                mrow[mt][hf] = mn;
                rsum[mt][hf] = 0.f;
            }
#pragma unroll
        for (int mt = 0; mt < 2; mt++) {
#pragma unroll
            for (int nt = 0; nt < 8; nt++) {
                float p0 = __expf(s[mt][nt][0] - mrow[mt][0]);
                float p1 = __expf(s[mt][nt][1] - mrow[mt][0]);
                float p2 = __expf(s[mt][nt][2] - mrow[mt][1]);
                float p3 = __expf(s[mt][nt][3] - mrow[mt][1]);
                rsum[mt][0] += p0 + p1;
                rsum[mt][1] += p2 + p3;
                *(__half2*)(Pw + (mt * 16 + g)     * AST + nt * 8 + 2 * tc) =
                    __floats2half2_rn(p0, p1);
                *(__half2*)(Pw + (mt * 16 + g + 8) * AST + nt * 8 + 2 * tc) =
                    __floats2half2_rn(p2, p3);
            }
        }
        __syncwarp();
#pragma unroll
        for (int mt = 0; mt < 2; mt++)
#pragma unroll
            for (int hf = 0; hf < 2; hf++) {
                float v = rsum[mt][hf];
                v += __shfl_xor_sync(0xFFFFFFFFu, v, 1);
                v += __shfl_xor_sync(0xFFFFFFFFu, v, 2);
                lrow[mt][hf] = lrow[mt][hf] * corr[mt][hf] + v;
            }
#pragma unroll
        for (int mt = 0; mt < 2; mt++)
#pragma unroll
            for (int nt = 0; nt < 8; nt++) {
                oc[mt][nt][0] *= corr[mt][0];
                oc[mt][nt][1] *= corr[mt][0];
                oc[mt][nt][2] *= corr[mt][1];
                oc[mt][nt][3] *= corr[mt][1];
            }

#pragma unroll
        for (int ks = 0; ks < 4; ks++) {
            uint4 pa[2];
#pragma unroll
            for (int mt = 0; mt < 2; mt++) {
                pa[mt].x = *(const unsigned*)(Pw + (mt * 16 + g)     * AST + ks * 16 + 2 * tc);
                pa[mt].y = *(const unsigned*)(Pw + (mt * 16 + g + 8) * AST + ks * 16 + 2 * tc);
                pa[mt].z = *(const unsigned*)(Pw + (mt * 16 + g)     * AST + ks * 16 + 2 * tc + 8);
                pa[mt].w = *(const unsigned*)(Pw + (mt * 16 + g + 8) * AST + ks * 16 + 2 * tc + 8);
            }
#pragma unroll
            for (int np = 0; np < 4; np++) {
                unsigned r0, r1, r2, r3;
                uint32_t addr = vsb + (((ks * 16 + lm_row) * AST) + np * 16 + lm_dof) * 2;
                LDSM_X4_TRANS(r0, r1, r2, r3, addr);
                MMA_F16(oc[0][np * 2],     pa[0], r0, r1);
                MMA_F16(oc[0][np * 2 + 1], pa[0], r2, r3);
                MMA_F16(oc[1][np * 2],     pa[1], r0, r1);
                MMA_F16(oc[1][np * 2 + 1], pa[1], r2, r3);
            }
        }
    }

#pragma unroll
    for (int mt = 0; mt < 2; mt++) {
        float inv0 = 1.f / lrow[mt][0];
        float inv1 = 1.f / lrow[mt][1];
        int row = rowb + q0 + w * 32 + mt * 16 + g;
#pragma unroll
        for (int nt = 0; nt < 8; nt++) {
            int col = colb + nt * 8 + 2 * tc;
            *(__half2*)(O + (size_t)row * DMODEL + col) =
                __floats2half2_rn(oc[mt][nt][0] * inv0, oc[mt][nt][1] * inv0);
            *(__half2*)(O + (size_t)(row + 8) * DMODEL + col) =
                __floats2half2_rn(oc[mt][nt][2] * inv1, oc[mt][nt][3] * inv1);
        }
    }
}

// ---------------- residual add + LayerNorm ----------------------------------
template<int HAS_RES>
__global__ void __launch_bounds__(256)
add_ln_kernel(const float* __restrict__ x, const float* __restrict__ res,
              const float* __restrict__ g, const float* __restrict__ b,
              float* __restrict__ out, __half* __restrict__ out16) {
    int row = blockIdx.x, tid = threadIdx.x;
    __shared__ float sh[16];
    __shared__ float stats[2];

    float4 v = *(const float4*)(x + (size_t)row * DMODEL + tid * 4);
    if (HAS_RES) {
        float4 r = *(const float4*)(res + (size_t)row * DMODEL + tid * 4);
        v.x += r.x; v.y += r.y; v.z += r.z; v.w += r.w;
    }
    float s  = v.x + v.y + v.z + v.w;
    float s2 = v.x*v.x + v.y*v.y + v.z*v.z + v.w*v.w;
#pragma unroll
    for (int o = 16; o > 0; o >>= 1) {
        s  += __shfl_down_sync(0xFFFFFFFFu, s,  o);
        s2 += __shfl_down_sync(0xFFFFFFFFu, s2, o);
    }
    int wid = tid >> 5, lane = tid & 31;
    if (lane == 0) { sh[wid] = s; sh[wid + 8] = s2; }
    __syncthreads();
    if (tid == 0) {
        float ts = 0.f, ts2 = 0.f;
#pragma unroll
        for (int i = 0; i < 8; i++) { ts += sh[i]; ts2 += sh[i + 8]; }
        float mean = ts * (1.f / DMODEL);
        float var  = ts2 * (1.f / DMODEL) - mean * mean;
        stats[0] = mean;
        stats[1] = rsqrtf(var + 1e-5f);
    }
    __syncthreads();
    float mean = stats[0], rstd = stats[1];
    float4 gv = *(const float4*)(g + tid * 4);
    float4 bv = *(const float4*)(b + tid * 4);
    float4 o;
    o.x = (v.x - mean) * rstd * gv.x + bv.x;
    o.y = (v.y - mean) * rstd * gv.y + bv.y;
    o.z = (v.z - mean) * rstd * gv.z + bv.z;
    o.w = (v.w - mean) * rstd * gv.w + bv.w;
    *(float4*)(out + (size_t)row * DMODEL + tid * 4) = o;
    __half2* hp = (__half2*)(out16 + (size_t)row * DMODEL + tid * 4);
    hp[0] = __floats2half2_rn(o.x, o.y);
    hp[1] = __floats2half2_rn(o.z, o.w);
}

// ---------------- host orchestration ---------------------------------------
extern "C" void kernel_launch(void* const* d_in, const int* in_sizes, int n_in,
                              void* d_out, int out_size) {
    const int*   ids     = (const int*)  d_in[0];
    const float* emb     = (const float*)d_in[1];
    const float* pe      = (const float*)d_in[2];
    const float* wq      = (const float*)d_in[3];
    const float* bq      = (const float*)d_in[4];
    const float* wk      = (const float*)d_in[5];
    const float* bk      = (const float*)d_in[6];
    const float* wv      = (const float*)d_in[7];
    const float* bvv     = (const float*)d_in[8];
    const float* wo      = (const float*)d_in[9];
    const float* bo      = (const float*)d_in[10];
    const float* ln1_g   = (const float*)d_in[11];
    const float* ln1_b   = (const float*)d_in[12];
    const float* w1      = (const float*)d_in[13];
    const float* b1      = (const float*)d_in[14];
    const float* w2      = (const float*)d_in[15];
    const float* b2      = (const float*)d_in[16];
    const float* ln2_g   = (const float*)d_in[17];
    const float* ln2_b   = (const float*)d_in[18];
    const float* lnf_g   = (const float*)d_in[19];
    const float* lnf_b   = (const float*)d_in[20];
    const float* lm_head = (const float*)d_in[21];
    float* out = (float*)d_out;

    float *h, *tmp, *bqkv;
    __half *h16, *qkv16, *ctx16, *ffn16, *wqkv16, *wo16, *w116, *w216, *lm16;
    cudaGetSymbolAddress((void**)&h,      g_h);
    cudaGetSymbolAddress((void**)&h16,    g_h16);
    cudaGetSymbolAddress((void**)&qkv16,  g_qkv16);
    cudaGetSymbolAddress((void**)&ctx16,  g_ctx16);
    cudaGetSymbolAddress((void**)&tmp,    g_tmp);
    cudaGetSymbolAddress((void**)&ffn16,  g_ffn16);
    cudaGetSymbolAddress((void**)&bqkv,   g_bqkv);
    cudaGetSymbolAddress((void**)&wqkv16, g_wqkv16);
    cudaGetSymbolAddress((void**)&wo16,   g_wo16);
    cudaGetSymbolAddress((void**)&w116,   g_w116);
    cudaGetSymbolAddress((void**)&w216,   g_w216);
    cudaGetSymbolAddress((void**)&lm16,   g_lm16);

    cudaFuncSetAttribute(attn_f16_kernel, cudaFuncAttributeMaxDynamicSharedMemorySize, ATT_SMEM);
    cudaFuncSetAttribute(gemm_f16<0,0>, cudaFuncAttributeMaxDynamicSharedMemorySize, GEMM_SMEM);
    cudaFuncSetAttribute(gemm_f16<1,0>, cudaFuncAttributeMaxDynamicSharedMemorySize, GEMM_SMEM);
    cudaFuncSetAttribute(gemm_f16<1,1>, cudaFuncAttributeMaxDynamicSharedMemorySize, GEMM_SMEM);
    cudaFuncSetAttribute(gemm_f16<2,1>, cudaFuncAttributeMaxDynamicSharedMemorySize, GEMM_SMEM);

    embed_kernel<<<NTOK, 256>>>(ids, emb, pe, h, h16);
    repack_bqkv_kernel<<<(LYR * QKV_LD) / 256, 256>>>(bq, bk, bvv, bqkv);

    dim3 tthr(32, 8);
    for (int l = 0; l < LYR; l++) {
        const size_t oDD = (size_t)l * DMODEL * DMODEL;
        const size_t oDF = (size_t)l * DMODEL * FDIM;
        transpose_f16_kernel<<<dim3(32, 32), tthr>>>(wq + oDD,
            wqkv16 + ((size_t)l * QKV_LD + 0) * DMODEL, DMODEL, DMODEL);
        transpose_f16_kernel<<<dim3(32, 32), tthr>>>(wk + oDD,
            wqkv16 + ((size_t)l * QKV_LD + 1024) * DMODEL, DMODEL, DMODEL);
        transpose_f16_kernel<<<dim3(32, 32), tthr>>>(wv + oDD,
            wqkv16 + ((size_t)l * QKV_LD + 2048) * DMODEL, DMODEL, DMODEL);
        transpose_f16_kernel<<<dim3(32, 32), tthr>>>(wo + oDD,
            wo16 + oDD, DMODEL, DMODEL);
        transpose_f16_kernel<<<dim3(FDIM / 32, 32), tthr>>>(w1 + oDF,
            w116 + oDF, DMODEL, FDIM);
        transpose_f16_kernel<<<dim3(32, FDIM / 32), tthr>>>(w2 + oDF,
            w216 + oDF, FDIM, DMODEL);
    }
    transpose_f16_kernel<<<dim3(VOCAB / 32, 32), tthr>>>(lm_head, lm16, DMODEL, VOCAB);

    dim3 gQKV(NTOK / 128, QKV_LD / 128);
    dim3 gD(NTOK / 128, DMODEL / 128);
    dim3 gF(NTOK / 128, FDIM / 128);
    dim3 gV(NTOK / 128, VOCAB / 128);
    dim3 gAttn(SEQ / 128, NHEAD, BATCH);

    for (int i = 0; i < LYR; i++) {
        const size_t oD  = (size_t)i * DMODEL;
        const size_t oF  = (size_t)i * FDIM;

        gemm_f16<1,1><<<gQKV, 256, GEMM_SMEM>>>(h16, wqkv16 + (size_t)i * QKV_LD * DMODEL,
                                                bqkv + (size_t)i * QKV_LD, nullptr, qkv16,
                                                NTOK, QKV_LD, DMODEL);

        attn_f16_kernel<<<gAttn, 128, ATT_SMEM>>>(qkv16, qkv16 + 1024, qkv16 + 2048,
                                                  ctx16, QKV_LD);

        gemm_f16<1,0><<<gD, 256, GEMM_SMEM>>>(ctx16, wo16 + (size_t)i * DMODEL * DMODEL,
                                              bo + oD, tmp, nullptr, NTOK, DMODEL, DMODEL);
        add_ln_kernel<1><<<NTOK, 256>>>(tmp, h, ln1_g + oD, ln1_b + oD, h, h16);

        gemm_f16<2,1><<<gF, 256, GEMM_SMEM>>>(h16, w116 + (size_t)i * DMODEL * FDIM,
                                              b1 + oF, nullptr, ffn16, NTOK, FDIM, DMODEL);
        gemm_f16<1,0><<<gD, 256, GEMM_SMEM>>>(ffn16, w216 + (size_t)i * DMODEL * FDIM,
                                              b2 + oD, tmp, nullptr, NTOK, DMODEL, FDIM);
        add_ln_kernel<1><<<NTOK, 256>>>(tmp, h, ln2_g + oD, ln2_b + oD, h, h16);
    }

    add_ln_kernel<0><<<NTOK, 256>>>(h, nullptr, lnf_g, lnf_b, h, h16);

    gemm_f16<0,0><<<gV, 256, GEMM_SMEM>>>(h16, lm16, nullptr, out, nullptr,
                                          NTOK, VOCAB, DMODEL);
}